// round 6
// baseline (speedup 1.0000x reference)
#include <cuda_runtime.h>
#include <cstdint>

#define NN 50000
#define EE 800000
#define DIN 128
#define NH 4
#define CH 64
#define HC 256
#define NG 512
#define EPSBN 1e-5f
#define SLOPE 0.2f

// ---------------- scratch ----------------
__device__ float g_feat[(size_t)NN * HC];
__device__ float g_res [(size_t)NN * HC];
__device__ float g_act [(size_t)NN * HC];
__device__ float g_es[NN * NH];
__device__ float g_ed[NN * NH];
__device__ int   g_rowptr[NN + 1];
__device__ int   g_cursor[NN];
__device__ int   g_srcsorted[EE];
__device__ int   g_blocksums[256];
__device__ int   g_blockoff[256];
__device__ float g_bnacc[2 * HC];
__device__ float g_bnA[HC];
__device__ float g_bnB[HC];
__device__ float g_pooled[NG * HC];
// split bf16 buffers (hi/lo packed as bf16x2 words, 2 k per word)
__device__ uint32_t g_xh[(size_t)NN * DIN / 2], g_xl[(size_t)NN * DIN / 2];
__device__ uint32_t g_a2h[(size_t)NN * HC / 2], g_a2l[(size_t)NN * HC / 2];
__device__ uint32_t g_w1h[HC * DIN / 2], g_w1l[HC * DIN / 2];
__device__ uint32_t g_r1h[HC * DIN / 2], g_r1l[HC * DIN / 2];
__device__ uint32_t g_w2h[HC * HC / 2],  g_w2l[HC * HC / 2];
__device__ uint32_t g_r2h[HC * HC / 2],  g_r2l[HC * HC / 2];

// float2 -> (hi bf16x2, lo bf16x2); lo = residual after bf16 rounding.
__device__ __forceinline__ void f2_split(float2 v, uint32_t& h, uint32_t& l) {
    asm("cvt.rn.bf16x2.f32 %0, %1, %2;" : "=r"(h) : "f"(v.y), "f"(v.x));
    float hx = __uint_as_float(h << 16);
    float hy = __uint_as_float(h & 0xFFFF0000u);
    asm("cvt.rn.bf16x2.f32 %0, %1, %2;" : "=r"(l) : "f"(v.y - hy), "f"(v.x - hx));
}

// ---------------- tiny utility kernels ----------------
__global__ void zero_float_kernel(float* p, int n) {
    int i = blockIdx.x * blockDim.x + threadIdx.x;
    if (i < n) p[i] = 0.0f;
}
__global__ void zero_int_kernel(int* p, int n) {
    int i = blockIdx.x * blockDim.x + threadIdx.x;
    if (i < n) p[i] = 0;
}
__global__ void copy_int_kernel(int* dst, const int* src, int n) {
    int i = blockIdx.x * blockDim.x + threadIdx.x;
    if (i < n) dst[i] = src[i];
}

// ---------------- split / transpose prep kernels ----------------
// split a fp32 array (n float4 chunks) into hi/lo bf16x2 word arrays
__global__ void split_f4_kernel(const float* __restrict__ src,
                                uint32_t* __restrict__ dh, uint32_t* __restrict__ dl,
                                int n4) {
    int i = blockIdx.x * blockDim.x + threadIdx.x;
    if (i >= n4) return;
    float4 v = ((const float4*)src)[i];
    uint32_t h0, l0, h1, l1;
    f2_split(make_float2(v.x, v.y), h0, l0);
    f2_split(make_float2(v.z, v.w), h1, l1);
    dh[2 * i] = h0; dh[2 * i + 1] = h1;
    dl[2 * i] = l0; dl[2 * i + 1] = l1;
}

// W[K][256] -> Wt hi/lo [256][K/2 words] (transposed, k-pairs packed)
__global__ void wsplit_kernel(const float* __restrict__ W,
                              uint32_t* __restrict__ th, uint32_t* __restrict__ tl,
                              int Kd) {
    int idx = blockIdx.x * blockDim.x + threadIdx.x;
    int kw = Kd >> 1;
    if (idx >= HC * kw) return;
    int n = idx / kw, kp = idx % kw;
    float a = W[(size_t)(2 * kp) * HC + n];
    float b = W[(size_t)(2 * kp + 1) * HC + n];
    uint32_t h, l;
    f2_split(make_float2(a, b), h, l);
    th[idx] = h; tl[idx] = l;
}

// BN+ReLU applied to act, output as split bf16 (layer-2 GEMM input)
__global__ __launch_bounds__(256) void bn_apply_split_kernel(const float* __restrict__ x,
                                                             uint32_t* __restrict__ dh,
                                                             uint32_t* __restrict__ dl) {
    int i = blockIdx.x * blockDim.x + threadIdx.x;
    if (i >= NN * HC / 4) return;
    float4 v = ((const float4*)x)[i];
    int c = (i * 4) & 255;
    v.x = fmaxf(v.x * g_bnA[c + 0] + g_bnB[c + 0], 0.f);
    v.y = fmaxf(v.y * g_bnA[c + 1] + g_bnB[c + 1], 0.f);
    v.z = fmaxf(v.z * g_bnA[c + 2] + g_bnB[c + 2], 0.f);
    v.w = fmaxf(v.w * g_bnA[c + 3] + g_bnB[c + 3], 0.f);
    uint32_t h0, l0, h1, l1;
    f2_split(make_float2(v.x, v.y), h0, l0);
    f2_split(make_float2(v.z, v.w), h1, l1);
    dh[2 * i] = h0; dh[2 * i + 1] = h1;
    dl[2 * i] = l0; dl[2 * i + 1] = l1;
}

// ---------------- CSR build ----------------
__global__ void count_deg_kernel(const int* __restrict__ ei) {
    int e = blockIdx.x * blockDim.x + threadIdx.x;
    if (e >= EE) return;
    atomicAdd(&g_cursor[ei[EE + e]], 1);   // dst
}

__global__ void scan_block_kernel(const int* __restrict__ in, int* __restrict__ out,
                                  int* __restrict__ blocksums, int n) {
    __shared__ int sh[256];
    int tid = threadIdx.x;
    int i = blockIdx.x * 256 + tid;
    int v = (i < n) ? in[i] : 0;
    sh[tid] = v;
    __syncthreads();
    for (int off = 1; off < 256; off <<= 1) {
        int t = (tid >= off) ? sh[tid - off] : 0;
        __syncthreads();
        sh[tid] += t;
        __syncthreads();
    }
    if (i < n) out[i] = sh[tid] - v;
    if (tid == 255 && blocksums) blocksums[blockIdx.x] = sh[255];
}

__global__ void scan_add_kernel(int* __restrict__ rowptr, const int* __restrict__ blockoff, int n) {
    int i = blockIdx.x * 256 + threadIdx.x;
    if (i < n) rowptr[i] += blockoff[blockIdx.x];
    if (blockIdx.x == 0 && threadIdx.x == 0) rowptr[n] = EE;
}

__global__ void fill_csr_kernel(const int* __restrict__ ei) {
    int e = blockIdx.x * blockDim.x + threadIdx.x;
    if (e >= EE) return;
    int s = ei[e];
    int d = ei[EE + e];
    int pos = atomicAdd(&g_cursor[d], 1);
    g_srcsorted[pos] = s;
}

// ============================================================================
// Tensor-core dual GEMM, pre-split bf16 operands (3-product error compensation)
// A: hi/lo bf16x2 word arrays [Nr][K/2]; B: transposed hi/lo [256][K/2].
// Block tile 128x64 (col tile == one head), 8 warps (4m x 2n), warp 32x32,
// k-tile 16 (= 8 words), mma.m16n8k16.bf16. Fragments are single LDS.32 words.
// smem row stride 12 words -> fragment loads hit all 32 banks exactly once.
// z==0 branch computes es/ed (attention dots) in the epilogue.
// ============================================================================
#define AST 12   // words per A/B smem row (8 data + 4 pad)

__device__ __forceinline__ void mma_bf16(float* d, const uint32_t* a,
                                         uint32_t b0, uint32_t b1) {
    asm volatile(
        "mma.sync.aligned.m16n8k16.row.col.f32.bf16.bf16.f32 "
        "{%0,%1,%2,%3}, {%4,%5,%6,%7}, {%8,%9}, {%0,%1,%2,%3};\n"
        : "+f"(d[0]), "+f"(d[1]), "+f"(d[2]), "+f"(d[3])
        : "r"(a[0]), "r"(a[1]), "r"(a[2]), "r"(a[3]), "r"(b0), "r"(b1));
}

__device__ __forceinline__ void cp_async16u(uint32_t* smem_ptr, const uint32_t* gptr, bool pred) {
    uint32_t sa = (uint32_t)__cvta_generic_to_shared(smem_ptr);
    int bytes = pred ? 16 : 0;
    asm volatile("cp.async.ca.shared.global [%0], [%1], 16, %2;\n"
                 :: "r"(sa), "l"(gptr), "r"(bytes));
}

__global__ __launch_bounds__(256) void gemm2tcs_kernel(
    const uint32_t* __restrict__ Ah, const uint32_t* __restrict__ Al,
    const uint32_t* __restrict__ Bh0, const uint32_t* __restrict__ Bl0,
    const uint32_t* __restrict__ Bh1, const uint32_t* __restrict__ Bl1,
    const float* __restrict__ bias1,
    const float* __restrict__ asrc, const float* __restrict__ adst,
    float* __restrict__ C0, float* __restrict__ C1,
    float* __restrict__ es, float* __restrict__ ed,
    int Nr, int K)
{
    __shared__ uint32_t sAh[2][128 * AST], sAl[2][128 * AST];
    __shared__ uint32_t sBh[2][64 * AST],  sBl[2][64 * AST];
    __shared__ float sEs[128], sEd[128];

    const uint32_t* Bh = blockIdx.z ? Bh1 : Bh0;
    const uint32_t* Bl = blockIdx.z ? Bl1 : Bl0;
    float*          Cc = blockIdx.z ? C1 : C0;
    const bool    hasb = blockIdx.z != 0;

    const int Kw = K >> 1;
    const int tid  = threadIdx.x;
    const int lane = tid & 31;
    const int wid  = tid >> 5;
    const int warp_m = wid & 3;
    const int warp_n = wid >> 2;
    const int row0 = blockIdx.y * 128;
    const int col0 = blockIdx.x * 64;

    const int grp = lane >> 2;
    const int tig = lane & 3;

    if (tid < 128) { sEs[tid] = 0.f; sEd[tid] = 0.f; }

    float acc[2][4][4];
#pragma unroll
    for (int mt = 0; mt < 2; mt++)
#pragma unroll
        for (int nt = 0; nt < 4; nt++)
#pragma unroll
            for (int i = 0; i < 4; i++) acc[mt][nt][i] = 0.f;

    const int a_row  = tid >> 1;       // 0..127
    const int a_wof  = (tid & 1) * 4;  // word offset 0 or 4
    const int b_row  = (tid & 127) >> 1;
    const int b_wof  = (tid & 1) * 4;
    const bool do_bh = tid < 128;

    const int T = K / 16;

    auto load_tile = [&](int it, int buf) {
        int gr = row0 + a_row;
        const uint32_t* gah = &Ah[(size_t)gr * Kw + it * 8 + a_wof];
        const uint32_t* gal = &Al[(size_t)gr * Kw + it * 8 + a_wof];
        bool p = gr < Nr;
        cp_async16u(&sAh[buf][a_row * AST + a_wof], gah, p);
        cp_async16u(&sAl[buf][a_row * AST + a_wof], gal, p);
        if (do_bh)
            cp_async16u(&sBh[buf][b_row * AST + b_wof],
                        &Bh[(size_t)(col0 + b_row) * Kw + it * 8 + b_wof], true);
        else
            cp_async16u(&sBl[buf][b_row * AST + b_wof],
                        &Bl[(size_t)(col0 + b_row) * Kw + it * 8 + b_wof], true);
        asm volatile("cp.async.commit_group;\n");
    };

    load_tile(0, 0);
    load_tile(1, 1);

    for (int it = 0; it < T; it++) {
        if (it < T - 1) asm volatile("cp.async.wait_group 1;\n");
        else            asm volatile("cp.async.wait_group 0;\n");
        __syncthreads();
        const uint32_t* ah_s = sAh[it & 1];
        const uint32_t* al_s = sAl[it & 1];
        const uint32_t* bh_s = sBh[it & 1];
        const uint32_t* bl_s = sBl[it & 1];

        uint32_t ah[2][4], al[2][4];
#pragma unroll
        for (int mt = 0; mt < 2; mt++) {
            int b0 = (warp_m * 32 + mt * 16 + grp) * AST + tig;
            ah[mt][0] = ah_s[b0];
            ah[mt][1] = ah_s[b0 + 8 * AST];
            ah[mt][2] = ah_s[b0 + 4];
            ah[mt][3] = ah_s[b0 + 8 * AST + 4];
            al[mt][0] = al_s[b0];
            al[mt][1] = al_s[b0 + 8 * AST];
            al[mt][2] = al_s[b0 + 4];
            al[mt][3] = al_s[b0 + 8 * AST + 4];
        }
#pragma unroll
        for (int nt = 0; nt < 4; nt++) {
            int nb = (warp_n * 32 + nt * 8 + grp) * AST + tig;
            uint32_t bh0 = bh_s[nb], bh1v = bh_s[nb + 4];
            uint32_t bl0 = bl_s[nb], bl1v = bl_s[nb + 4];
#pragma unroll
            for (int mt = 0; mt < 2; mt++) {
                mma_bf16(acc[mt][nt], al[mt], bh0, bh1v);   // Al*Bh
                mma_bf16(acc[mt][nt], ah[mt], bl0, bl1v);   // Ah*Bl
                mma_bf16(acc[mt][nt], ah[mt], bh0, bh1v);   // Ah*Bh
            }
        }
        __syncthreads();
        if (it + 2 < T) load_tile(it + 2, it & 1);
    }

    // ---- C write ----
#pragma unroll
    for (int mt = 0; mt < 2; mt++) {
        int r = row0 + warp_m * 32 + mt * 16 + grp;
#pragma unroll
        for (int nt = 0; nt < 4; nt++) {
            int c = col0 + warp_n * 32 + nt * 8 + 2 * tig;
            float bx = 0.f, by = 0.f;
            if (hasb) { bx = bias1[c]; by = bias1[c + 1]; }
            if (r < Nr)
                *(float2*)&Cc[(size_t)r * HC + c] =
                    make_float2(acc[mt][nt][0] + bx, acc[mt][nt][1] + by);
            if (r + 8 < Nr)
                *(float2*)&Cc[(size_t)(r + 8) * HC + c] =
                    make_float2(acc[mt][nt][2] + bx, acc[mt][nt][3] + by);
        }
    }

    // ---- fused attention dots (feat branch only) ----
    if (blockIdx.z == 0) {
        const int head = blockIdx.x;
        float pes[2][2] = {{0.f, 0.f}, {0.f, 0.f}};
        float ped[2][2] = {{0.f, 0.f}, {0.f, 0.f}};
#pragma unroll
        for (int mt = 0; mt < 2; mt++)
#pragma unroll
            for (int nt = 0; nt < 4; nt++) {
                int cl = warp_n * 32 + nt * 8 + 2 * tig;
                float a0 = asrc[head * CH + cl], a1 = asrc[head * CH + cl + 1];
                float d0 = adst[head * CH + cl], d1 = adst[head * CH + cl + 1];
                pes[mt][0] += acc[mt][nt][0] * a0 + acc[mt][nt][1] * a1;
                pes[mt][1] += acc[mt][nt][2] * a0 + acc[mt][nt][3] * a1;
                ped[mt][0] += acc[mt][nt][0] * d0 + acc[mt][nt][1] * d1;
                ped[mt][1] += acc[mt][nt][2] * d0 + acc[mt][nt][3] * d1;
            }
#pragma unroll
        for (int o = 1; o <= 2; o <<= 1) {
#pragma unroll
            for (int mt = 0; mt < 2; mt++)
#pragma unroll
                for (int hh = 0; hh < 2; hh++) {
                    pes[mt][hh] += __shfl_xor_sync(0xffffffffu, pes[mt][hh], o);
                    ped[mt][hh] += __shfl_xor_sync(0xffffffffu, ped[mt][hh], o);
                }
        }
        if (tig == 0) {
#pragma unroll
            for (int mt = 0; mt < 2; mt++)
#pragma unroll
                for (int hh = 0; hh < 2; hh++) {
                    int lr = warp_m * 32 + mt * 16 + hh * 8 + grp;
                    atomicAdd(&sEs[lr], pes[mt][hh]);
                    atomicAdd(&sEd[lr], ped[mt][hh]);
                }
        }
        __syncthreads();
        if (tid < 128) {
            int node = row0 + tid;
            if (node < Nr) {
                es[node * NH + head] = sEs[tid];
                ed[node * NH + head] = sEd[tid];
            }
        }
    }
}

// ---------------- GAT softmax + aggregate: warp per (node, head) ----------------
__global__ __launch_bounds__(256) void agg_kernel(
    const float* __restrict__ feat, const float* __restrict__ es,
    const float* __restrict__ ed, const float* __restrict__ bias,
    const float* __restrict__ res, float* __restrict__ out)
{
    int gw = (blockIdx.x * blockDim.x + threadIdx.x) >> 5;
    int lane = threadIdx.x & 31;
    if (gw >= NN * NH) return;
    int node = gw >> 2, head = gw & 3;
    int s0 = g_rowptr[node], s1 = g_rowptr[node + 1];
    int ch = head * CH + 2 * lane;
    float accx = 0.f, accy = 0.f;

    if (s1 > s0) {
        float edv = ed[node * NH + head];
        float m = -INFINITY, den = 0.f;
        for (int k = s0 + lane; k < s1; k += 32) {
            int s = g_srcsorted[k];
            float e = es[s * NH + head] + edv;
            e = (e >= 0.f) ? e : SLOPE * e;
            if (e > m) { den = den * __expf(m - e) + 1.f; m = e; }
            else den += __expf(e - m);
        }
#pragma unroll
        for (int o = 16; o; o >>= 1) {
            float mo  = __shfl_xor_sync(0xffffffffu, m, o);
            float dno = __shfl_xor_sync(0xffffffffu, den, o);
            float nm = fmaxf(m, mo);
            float f1 = (m == nm) ? 1.f : __expf(m - nm);
            float f2 = (mo == nm) ? 1.f : __expf(mo - nm);
            den = den * f1 + dno * f2;
            m = nm;
        }
        float inv = 1.f / (den + 1e-16f);
        for (int k = s0; k < s1; k++) {
            int s = g_srcsorted[k];
            float e = es[s * NH + head] + edv;
            e = (e >= 0.f) ? e : SLOPE * e;
            float w = __expf(e - m) * inv;
            float2 v = *(const float2*)&feat[(size_t)s * HC + ch];
            accx += w * v.x;
            accy += w * v.y;
        }
    }
    float2 bv = *(const float2*)&bias[ch];
    float2 rv = *(const float2*)&res[(size_t)node * HC + ch];
    float2 o2;
    o2.x = accx + bv.x + rv.x;
    o2.y = accy + bv.y + rv.y;
    *(float2*)&out[(size_t)node * HC + ch] = o2;
}

// ---------------- BatchNorm ----------------
__global__ __launch_bounds__(256) void bn_stats_kernel(const float* __restrict__ x) {
    int chn = threadIdx.x;
    int r0 = blockIdx.x * 64;
    int r1 = min(r0 + 64, NN);
    float s = 0.f, q = 0.f;
    for (int r = r0; r < r1; r++) {
        float v = x[(size_t)r * HC + chn];
        s += v; q += v * v;
    }
    atomicAdd(&g_bnacc[chn], s);
    atomicAdd(&g_bnacc[chn + HC], q);
}

__global__ void bn_finalize_kernel(const float* __restrict__ gma, const float* __restrict__ beta) {
    int c = threadIdx.x;
    float mean = g_bnacc[c] / (float)NN;
    float var  = g_bnacc[c + HC] / (float)NN - mean * mean;
    float a = gma[c] * rsqrtf(var + EPSBN);
    g_bnA[c] = a;
    g_bnB[c] = beta[c] - mean * a;
}

__global__ __launch_bounds__(256) void bn_apply_kernel(float* __restrict__ x) {
    int i = blockIdx.x * blockDim.x + threadIdx.x;
    if (i >= NN * HC / 4) return;
    float4 v = ((const float4*)x)[i];
    int c = (i * 4) & 255;
    v.x = fmaxf(v.x * g_bnA[c + 0] + g_bnB[c + 0], 0.f);
    v.y = fmaxf(v.y * g_bnA[c + 1] + g_bnB[c + 1], 0.f);
    v.z = fmaxf(v.z * g_bnA[c + 2] + g_bnB[c + 2], 0.f);
    v.w = fmaxf(v.w * g_bnA[c + 3] + g_bnB[c + 3], 0.f);
    ((float4*)x)[i] = v;
}

// ---------------- pooling (atomic-free; batch is sorted) ----------------
__global__ __launch_bounds__(256) void pool_kernel(const float* __restrict__ act,
                                                   const int* __restrict__ batch) {
    __shared__ int s_lo, s_hi;
    int g = blockIdx.x;
    int t = threadIdx.x;
    if (t == 0) {
        int lo = 0, hi = NN;
        while (lo < hi) { int mid = (lo + hi) >> 1; if (batch[mid] < g) lo = mid + 1; else hi = mid; }
        s_lo = lo;
        int lo2 = lo; hi = NN;
        while (lo2 < hi) { int mid = (lo2 + hi) >> 1; if (batch[mid] < g + 1) lo2 = mid + 1; else hi = mid; }
        s_hi = lo2;
    }
    __syncthreads();
    int lo = s_lo, hi = s_hi;
    float s = 0.f;
    for (int r = lo; r < hi; r++) s += act[(size_t)r * HC + t];
    float inv = (hi > lo) ? 1.0f / (float)(hi - lo) : 0.0f;
    g_pooled[(size_t)g * HC + t] = s * inv;
}

// ---------------- graph-level MLP ----------------
__global__ __launch_bounds__(128) void mlp_kernel(
    const float* __restrict__ fc1W, const float* __restrict__ fc1b,
    const float* __restrict__ fc2W, const float* __restrict__ fc2b,
    float* __restrict__ out)
{
    __shared__ float row[HC];
    __shared__ float red[128];
    int g = blockIdx.x, t = threadIdx.x;
    row[t]       = g_pooled[(size_t)g * HC + t];
    row[t + 128] = g_pooled[(size_t)g * HC + t + 128];
    __syncthreads();
    float a = fc1b[t];
#pragma unroll 8
    for (int k = 0; k < HC; k++) a += row[k] * fc1W[k * 128 + t];
    a = fmaxf(a, 0.f);
    for (int j = 0; j < 2; j++) {
        red[t] = a * fc2W[t * 2 + j];
        __syncthreads();
        for (int off = 64; off; off >>= 1) {
            if (t < off) red[t] += red[t + off];
            __syncthreads();
        }
        if (t == 0) out[g * 2 + j] = red[0] + fc2b[j];
        __syncthreads();
    }
}

// ---------------- host side ----------------
static void* symp(const void* sym) {
    void* p = nullptr;
    cudaGetSymbolAddress(&p, sym);
    return p;
}

extern "C" void kernel_launch(void* const* d_in, const int* in_sizes, int n_in,
                              void* d_out, int out_size)
{
    const float* x        = (const float*)d_in[0];
    const int*   edge_idx = (const int*)  d_in[1];
    const int*   batch    = (const int*)  d_in[3];
    const float* W1       = (const float*)d_in[4];
    const float* asrc1    = (const float*)d_in[5];
    const float* adst1    = (const float*)d_in[6];
    const float* b1       = (const float*)d_in[7];
    const float* res1W    = (const float*)d_in[8];
    const float* res1b    = (const float*)d_in[9];
    const float* bn1g     = (const float*)d_in[10];
    const float* bn1b     = (const float*)d_in[11];
    const float* W2       = (const float*)d_in[12];
    const float* asrc2    = (const float*)d_in[13];
    const float* adst2    = (const float*)d_in[14];
    const float* b2       = (const float*)d_in[15];
    const float* res2W    = (const float*)d_in[16];
    const float* res2b    = (const float*)d_in[17];
    const float* bn2g     = (const float*)d_in[18];
    const float* bn2b     = (const float*)d_in[19];
    const float* fc1W     = (const float*)d_in[20];
    const float* fc1b     = (const float*)d_in[21];
    const float* fc2W     = (const float*)d_in[22];
    const float* fc2b     = (const float*)d_in[23];
    float* out = (float*)d_out;

    float* feat  = (float*)symp(g_feat);
    float* res   = (float*)symp(g_res);
    float* act   = (float*)symp(g_act);
    float* es    = (float*)symp(g_es);
    float* ed    = (float*)symp(g_ed);
    int*   rowp  = (int*)  symp(g_rowptr);
    int*   curs  = (int*)  symp(g_cursor);
    int*   bsum  = (int*)  symp(g_blocksums);
    int*   boff  = (int*)  symp(g_blockoff);
    float* bnacc = (float*)symp(g_bnacc);
    uint32_t* xh  = (uint32_t*)symp(g_xh),  *xl  = (uint32_t*)symp(g_xl);
    uint32_t* a2h = (uint32_t*)symp(g_a2h), *a2l = (uint32_t*)symp(g_a2l);
    uint32_t* w1h = (uint32_t*)symp(g_w1h), *w1l = (uint32_t*)symp(g_w1l);
    uint32_t* r1h = (uint32_t*)symp(g_r1h), *r1l = (uint32_t*)symp(g_r1l);
    uint32_t* w2h = (uint32_t*)symp(g_w2h), *w2l = (uint32_t*)symp(g_w2l);
    uint32_t* r2h = (uint32_t*)symp(g_r2h), *r2l = (uint32_t*)symp(g_r2l);

    const int NB = (NN + 255) / 256;
    const int EB = (EE + 255) / 256;
    const int WARPBLKS = (NN * NH * 32 + 255) / 256;
    dim3 gemm_grid(HC / 64, (NN + 127) / 128, 2);
    const int W1W = HC * DIN / 2, W2W = HC * HC / 2;

    // ---- prep: split x and layer-1 weights (gemm L1 lands at launch idx 3) ----
    split_f4_kernel<<<(NN * DIN / 4 + 255) / 256, 256>>>(x, xh, xl, NN * DIN / 4); // 0
    wsplit_kernel<<<(W1W + 255) / 256, 256>>>(W1, w1h, w1l, DIN);                  // 1
    wsplit_kernel<<<(W1W + 255) / 256, 256>>>(res1W, r1h, r1l, DIN);               // 2

    gemm2tcs_kernel<<<gemm_grid, 256>>>(xh, xl, w1h, w1l, r1h, r1l, res1b,
                                        asrc1, adst1, feat, res, es, ed,
                                        NN, DIN);                                  // 3 <- profiled

    // ---- CSR build ----
    zero_int_kernel<<<NB, 256>>>(curs, NN);
    count_deg_kernel<<<EB, 256>>>(edge_idx);
    scan_block_kernel<<<NB, 256>>>(curs, rowp, bsum, NN);
    scan_block_kernel<<<1, 256>>>(bsum, boff, nullptr, NB);
    scan_add_kernel<<<NB, 256>>>(rowp, boff, NN);
    copy_int_kernel<<<NB, 256>>>(curs, rowp, NN);
    fill_csr_kernel<<<EB, 256>>>(edge_idx);

    // ---- layer 1 rest ----
    agg_kernel<<<WARPBLKS, 256>>>(feat, es, ed, b1, res, act);
    zero_float_kernel<<<2, 256>>>(bnacc, 2 * HC);
    bn_stats_kernel<<<(NN + 63) / 64, 256>>>(act);
    bn_finalize_kernel<<<1, HC>>>(bn1g, bn1b);
    bn_apply_split_kernel<<<(NN * HC / 4 + 255) / 256, 256>>>(act, a2h, a2l);

    // ---- layer 2 ----
    wsplit_kernel<<<(W2W + 255) / 256, 256>>>(W2, w2h, w2l, HC);
    wsplit_kernel<<<(W2W + 255) / 256, 256>>>(res2W, r2h, r2l, HC);
    gemm2tcs_kernel<<<gemm_grid, 256>>>(a2h, a2l, w2h, w2l, r2h, r2l, res2b,
                                        asrc2, adst2, feat, res, es, ed,
                                        NN, HC);
    agg_kernel<<<WARPBLKS, 256>>>(feat, es, ed, b2, res, act);
    zero_float_kernel<<<2, 256>>>(bnacc, 2 * HC);
    bn_stats_kernel<<<(NN + 63) / 64, 256>>>(act);
    bn_finalize_kernel<<<1, HC>>>(bn2g, bn2b);
    bn_apply_kernel<<<(NN * HC / 4 + 255) / 256, 256>>>(act);

    // ---- pooling + MLP ----
    pool_kernel<<<NG, 256>>>(act, batch);
    mlp_kernel<<<NG, 128>>>(fc1W, fc1b, fc2W, fc2b, out);
}

// round 7
// speedup vs baseline: 1.0528x; 1.0528x over previous
#include <cuda_runtime.h>
#include <cstdint>

#define NN 50000
#define EE 800000
#define DIN 128
#define NH 4
#define CH 64
#define HC 256
#define NG 512
#define EPSBN 1e-5f
#define SLOPE 0.2f

// ---------------- scratch ----------------
__device__ float g_feat[(size_t)NN * HC];
__device__ float g_res [(size_t)NN * HC];
__device__ float g_act [(size_t)NN * HC];
__device__ float g_es[NN * NH];
__device__ float g_ed[NN * NH];
__device__ int   g_rowptr[NN + 1];
__device__ int   g_cursor[NN];
__device__ int   g_srcsorted[EE];
__device__ int   g_blocksums[256];
__device__ int   g_blockoff[256];
__device__ float g_bnacc[2 * HC];
__device__ float g_bnA[HC];
__device__ float g_bnB[HC];
__device__ float g_pooled[NG * HC];
// split bf16 buffers (hi/lo packed as bf16x2 words, 2 k per word)
__device__ uint32_t g_xh[(size_t)NN * DIN / 2], g_xl[(size_t)NN * DIN / 2];
__device__ uint32_t g_a2h[(size_t)NN * HC / 2], g_a2l[(size_t)NN * HC / 2];
__device__ uint32_t g_w1h[HC * DIN / 2], g_w1l[HC * DIN / 2];
__device__ uint32_t g_r1h[HC * DIN / 2], g_r1l[HC * DIN / 2];
__device__ uint32_t g_w2h[HC * HC / 2],  g_w2l[HC * HC / 2];
__device__ uint32_t g_r2h[HC * HC / 2],  g_r2l[HC * HC / 2];

// float2 -> (hi bf16x2, lo bf16x2); lo = residual after bf16 rounding.
__device__ __forceinline__ void f2_split(float2 v, uint32_t& h, uint32_t& l) {
    asm("cvt.rn.bf16x2.f32 %0, %1, %2;" : "=r"(h) : "f"(v.y), "f"(v.x));
    float hx = __uint_as_float(h << 16);
    float hy = __uint_as_float(h & 0xFFFF0000u);
    asm("cvt.rn.bf16x2.f32 %0, %1, %2;" : "=r"(l) : "f"(v.y - hy), "f"(v.x - hx));
}

// ---------------- tiny utility kernels ----------------
__global__ void zero_float_kernel(float* p, int n) {
    int i = blockIdx.x * blockDim.x + threadIdx.x;
    if (i < n) p[i] = 0.0f;
}
__global__ void zero_int_kernel(int* p, int n) {
    int i = blockIdx.x * blockDim.x + threadIdx.x;
    if (i < n) p[i] = 0;
}
__global__ void copy_int_kernel(int* dst, const int* src, int n) {
    int i = blockIdx.x * blockDim.x + threadIdx.x;
    if (i < n) dst[i] = src[i];
}

// ---------------- split / transpose prep kernels ----------------
__global__ void split_f4_kernel(const float* __restrict__ src,
                                uint32_t* __restrict__ dh, uint32_t* __restrict__ dl,
                                int n4) {
    int i = blockIdx.x * blockDim.x + threadIdx.x;
    if (i >= n4) return;
    float4 v = ((const float4*)src)[i];
    uint32_t h0, l0, h1, l1;
    f2_split(make_float2(v.x, v.y), h0, l0);
    f2_split(make_float2(v.z, v.w), h1, l1);
    dh[2 * i] = h0; dh[2 * i + 1] = h1;
    dl[2 * i] = l0; dl[2 * i + 1] = l1;
}

// two weights at once (blockIdx.y selects); W[K][256] -> Wt hi/lo [256][K/2]
__global__ void wsplit2_kernel(const float* __restrict__ W0, const float* __restrict__ W1,
                               uint32_t* __restrict__ th0, uint32_t* __restrict__ tl0,
                               uint32_t* __restrict__ th1, uint32_t* __restrict__ tl1,
                               int Kd) {
    const float* W = blockIdx.y ? W1 : W0;
    uint32_t* th = blockIdx.y ? th1 : th0;
    uint32_t* tl = blockIdx.y ? tl1 : tl0;
    int idx = blockIdx.x * blockDim.x + threadIdx.x;
    int kw = Kd >> 1;
    if (idx >= HC * kw) return;
    int n = idx / kw, kp = idx % kw;
    float a = W[(size_t)(2 * kp) * HC + n];
    float b = W[(size_t)(2 * kp + 1) * HC + n];
    uint32_t h, l;
    f2_split(make_float2(a, b), h, l);
    th[idx] = h; tl[idx] = l;
}

// BN+ReLU applied to act, output as split bf16 (layer-2 GEMM input)
__global__ __launch_bounds__(256) void bn_apply_split_kernel(const float* __restrict__ x,
                                                             uint32_t* __restrict__ dh,
                                                             uint32_t* __restrict__ dl) {
    int i = blockIdx.x * blockDim.x + threadIdx.x;
    if (i >= NN * HC / 4) return;
    float4 v = ((const float4*)x)[i];
    int c = (i * 4) & 255;
    v.x = fmaxf(v.x * g_bnA[c + 0] + g_bnB[c + 0], 0.f);
    v.y = fmaxf(v.y * g_bnA[c + 1] + g_bnB[c + 1], 0.f);
    v.z = fmaxf(v.z * g_bnA[c + 2] + g_bnB[c + 2], 0.f);
    v.w = fmaxf(v.w * g_bnA[c + 3] + g_bnB[c + 3], 0.f);
    uint32_t h0, l0, h1, l1;
    f2_split(make_float2(v.x, v.y), h0, l0);
    f2_split(make_float2(v.z, v.w), h1, l1);
    dh[2 * i] = h0; dh[2 * i + 1] = h1;
    dl[2 * i] = l0; dl[2 * i + 1] = l1;
}

// ---------------- CSR build ----------------
__global__ void count_deg_kernel(const int* __restrict__ ei) {
    int e = blockIdx.x * blockDim.x + threadIdx.x;
    if (e >= EE) return;
    atomicAdd(&g_cursor[ei[EE + e]], 1);   // dst
}

__global__ void scan_block_kernel(const int* __restrict__ in, int* __restrict__ out,
                                  int* __restrict__ blocksums, int n) {
    __shared__ int sh[256];
    int tid = threadIdx.x;
    int i = blockIdx.x * 256 + tid;
    int v = (i < n) ? in[i] : 0;
    sh[tid] = v;
    __syncthreads();
    for (int off = 1; off < 256; off <<= 1) {
        int t = (tid >= off) ? sh[tid - off] : 0;
        __syncthreads();
        sh[tid] += t;
        __syncthreads();
    }
    if (i < n) out[i] = sh[tid] - v;
    if (tid == 255 && blocksums) blocksums[blockIdx.x] = sh[255];
}

__global__ void scan_add_kernel(int* __restrict__ rowptr, const int* __restrict__ blockoff, int n) {
    int i = blockIdx.x * 256 + threadIdx.x;
    if (i < n) rowptr[i] += blockoff[blockIdx.x];
    if (blockIdx.x == 0 && threadIdx.x == 0) rowptr[n] = EE;
}

__global__ void fill_csr_kernel(const int* __restrict__ ei) {
    int e = blockIdx.x * blockDim.x + threadIdx.x;
    if (e >= EE) return;
    int s = ei[e];
    int d = ei[EE + e];
    int pos = atomicAdd(&g_cursor[d], 1);
    g_srcsorted[pos] = s;
}

// ============================================================================
// Tensor-core dual GEMM, pre-split bf16 + ldmatrix.x4 fragment loads.
// A: hi/lo bf16x2 words [Nr][K/2]; B: transposed hi/lo [256][K/2].
// Block tile 128x64, 8 warps (4m x 2n), warp 32x32, k-tile 16,
// mma.m16n8k16.bf16 x3 (error compensation). 8 LDSM.x4 per warp per k-tile.
// smem row pitch 12 words -> every ldmatrix 8-address phase covers 32 banks.
// z==0 branch computes es/ed (attention dots) in the epilogue.
// ============================================================================
#define AST 12   // words per A/B smem row (8 data + 4 pad)

__device__ __forceinline__ void mma_bf16(float* d, const uint32_t* a,
                                         uint32_t b0, uint32_t b1) {
    asm volatile(
        "mma.sync.aligned.m16n8k16.row.col.f32.bf16.bf16.f32 "
        "{%0,%1,%2,%3}, {%4,%5,%6,%7}, {%8,%9}, {%0,%1,%2,%3};\n"
        : "+f"(d[0]), "+f"(d[1]), "+f"(d[2]), "+f"(d[3])
        : "r"(a[0]), "r"(a[1]), "r"(a[2]), "r"(a[3]), "r"(b0), "r"(b1));
}

__device__ __forceinline__ void ldsm_x4(uint32_t& r0, uint32_t& r1,
                                        uint32_t& r2, uint32_t& r3, uint32_t saddr) {
    asm volatile("ldmatrix.sync.aligned.m8n8.x4.shared.b16 {%0,%1,%2,%3}, [%4];"
                 : "=r"(r0), "=r"(r1), "=r"(r2), "=r"(r3) : "r"(saddr));
}

__device__ __forceinline__ void cp_async16u(uint32_t* smem_ptr, const uint32_t* gptr, bool pred) {
    uint32_t sa = (uint32_t)__cvta_generic_to_shared(smem_ptr);
    int bytes = pred ? 16 : 0;
    asm volatile("cp.async.ca.shared.global [%0], [%1], 16, %2;\n"
                 :: "r"(sa), "l"(gptr), "r"(bytes));
}

__global__ __launch_bounds__(256) void gemm2tcs_kernel(
    const uint32_t* __restrict__ Ah, const uint32_t* __restrict__ Al,
    const uint32_t* __restrict__ Bh0, const uint32_t* __restrict__ Bl0,
    const uint32_t* __restrict__ Bh1, const uint32_t* __restrict__ Bl1,
    const float* __restrict__ bias1,
    const float* __restrict__ asrc, const float* __restrict__ adst,
    float* __restrict__ C0, float* __restrict__ C1,
    float* __restrict__ es, float* __restrict__ ed,
    int Nr, int K)
{
    __shared__ uint32_t sAh[2][128 * AST], sAl[2][128 * AST];
    __shared__ uint32_t sBh[2][64 * AST],  sBl[2][64 * AST];
    __shared__ float sEs[128], sEd[128];

    const uint32_t* Bh = blockIdx.z ? Bh1 : Bh0;
    const uint32_t* Bl = blockIdx.z ? Bl1 : Bl0;
    float*          Cc = blockIdx.z ? C1 : C0;
    const bool    hasb = blockIdx.z != 0;

    const int Kw = K >> 1;
    const int tid  = threadIdx.x;
    const int lane = tid & 31;
    const int wid  = tid >> 5;
    const int warp_m = wid & 3;
    const int warp_n = wid >> 2;
    const int row0 = blockIdx.y * 128;
    const int col0 = blockIdx.x * 64;

    const int grp = lane >> 2;
    const int tig = lane & 3;

    if (tid < 128) { sEs[tid] = 0.f; sEd[tid] = 0.f; }

    float acc[2][4][4];
#pragma unroll
    for (int mt = 0; mt < 2; mt++)
#pragma unroll
        for (int nt = 0; nt < 4; nt++)
#pragma unroll
            for (int i = 0; i < 4; i++) acc[mt][nt][i] = 0.f;

    const int a_row  = tid >> 1;       // 0..127
    const int a_wof  = (tid & 1) * 4;  // word offset 0 or 4
    const int b_row  = (tid & 127) >> 1;
    const int b_wof  = (tid & 1) * 4;
    const bool do_bh = tid < 128;

    const int T = K / 16;

    // ldmatrix per-lane base offsets (bytes)
    const uint32_t sAh_a = (uint32_t)__cvta_generic_to_shared(&sAh[0][0]);
    const uint32_t sAl_a = (uint32_t)__cvta_generic_to_shared(&sAl[0][0]);
    const uint32_t sBh_a = (uint32_t)__cvta_generic_to_shared(&sBh[0][0]);
    const uint32_t sBl_a = (uint32_t)__cvta_generic_to_shared(&sBl[0][0]);
    const uint32_t aoff = ((warp_m * 32 + (lane & 15)) * AST + (lane >> 4) * 4) * 4;
    const uint32_t boff = ((warp_n * 32 + (lane & 7) + ((lane >> 4) << 3)) * AST
                          + ((lane >> 3) & 1) * 4) * 4;
    const uint32_t ABUF = 128 * AST * 4;
    const uint32_t BBUF = 64 * AST * 4;
    const uint32_t MTSTEP = 16 * AST * 4;   // +16 rows

    auto load_tile = [&](int it, int buf) {
        int gr = row0 + a_row;
        const uint32_t* gah = &Ah[(size_t)gr * Kw + it * 8 + a_wof];
        const uint32_t* gal = &Al[(size_t)gr * Kw + it * 8 + a_wof];
        bool p = gr < Nr;
        cp_async16u(&sAh[buf][a_row * AST + a_wof], gah, p);
        cp_async16u(&sAl[buf][a_row * AST + a_wof], gal, p);
        if (do_bh)
            cp_async16u(&sBh[buf][b_row * AST + b_wof],
                        &Bh[(size_t)(col0 + b_row) * Kw + it * 8 + b_wof], true);
        else
            cp_async16u(&sBl[buf][b_row * AST + b_wof],
                        &Bl[(size_t)(col0 + b_row) * Kw + it * 8 + b_wof], true);
        asm volatile("cp.async.commit_group;\n");
    };

    load_tile(0, 0);
    load_tile(1, 1);

    for (int it = 0; it < T; it++) {
        if (it < T - 1) asm volatile("cp.async.wait_group 1;\n");
        else            asm volatile("cp.async.wait_group 0;\n");
        __syncthreads();
        const uint32_t bufo = (it & 1) ? 1u : 0u;
        const uint32_t abh = sAh_a + bufo * ABUF + aoff;
        const uint32_t abl = sAl_a + bufo * ABUF + aoff;
        const uint32_t bbh = sBh_a + bufo * BBUF + boff;
        const uint32_t bbl = sBl_a + bufo * BBUF + boff;

        uint32_t ah[2][4], al[2][4], bh[4][2], bl[4][2];
        ldsm_x4(ah[0][0], ah[0][1], ah[0][2], ah[0][3], abh);
        ldsm_x4(ah[1][0], ah[1][1], ah[1][2], ah[1][3], abh + MTSTEP);
        ldsm_x4(al[0][0], al[0][1], al[0][2], al[0][3], abl);
        ldsm_x4(al[1][0], al[1][1], al[1][2], al[1][3], abl + MTSTEP);
        ldsm_x4(bh[0][0], bh[0][1], bh[1][0], bh[1][1], bbh);
        ldsm_x4(bh[2][0], bh[2][1], bh[3][0], bh[3][1], bbh + MTSTEP);
        ldsm_x4(bl[0][0], bl[0][1], bl[1][0], bl[1][1], bbl);
        ldsm_x4(bl[2][0], bl[2][1], bl[3][0], bl[3][1], bbl + MTSTEP);

#pragma unroll
        for (int nt = 0; nt < 4; nt++) {
#pragma unroll
            for (int mt = 0; mt < 2; mt++) {
                mma_bf16(acc[mt][nt], al[mt], bh[nt][0], bh[nt][1]);   // Al*Bh
                mma_bf16(acc[mt][nt], ah[mt], bl[nt][0], bl[nt][1]);   // Ah*Bl
                mma_bf16(acc[mt][nt], ah[mt], bh[nt][0], bh[nt][1]);   // Ah*Bh
            }
        }
        __syncthreads();
        if (it + 2 < T) load_tile(it + 2, it & 1);
    }

    // ---- C write ----
#pragma unroll
    for (int mt = 0; mt < 2; mt++) {
        int r = row0 + warp_m * 32 + mt * 16 + grp;
#pragma unroll
        for (int nt = 0; nt < 4; nt++) {
            int c = col0 + warp_n * 32 + nt * 8 + 2 * tig;
            float bx = 0.f, by = 0.f;
            if (hasb) { bx = bias1[c]; by = bias1[c + 1]; }
            if (r < Nr)
                *(float2*)&Cc[(size_t)r * HC + c] =
                    make_float2(acc[mt][nt][0] + bx, acc[mt][nt][1] + by);
            if (r + 8 < Nr)
                *(float2*)&Cc[(size_t)(r + 8) * HC + c] =
                    make_float2(acc[mt][nt][2] + bx, acc[mt][nt][3] + by);
        }
    }

    // ---- fused attention dots (feat branch only) ----
    if (blockIdx.z == 0) {
        const int head = blockIdx.x;
        float pes[2][2] = {{0.f, 0.f}, {0.f, 0.f}};
        float ped[2][2] = {{0.f, 0.f}, {0.f, 0.f}};
#pragma unroll
        for (int mt = 0; mt < 2; mt++)
#pragma unroll
            for (int nt = 0; nt < 4; nt++) {
                int cl = warp_n * 32 + nt * 8 + 2 * tig;
                float a0 = asrc[head * CH + cl], a1 = asrc[head * CH + cl + 1];
                float d0 = adst[head * CH + cl], d1 = adst[head * CH + cl + 1];
                pes[mt][0] += acc[mt][nt][0] * a0 + acc[mt][nt][1] * a1;
                pes[mt][1] += acc[mt][nt][2] * a0 + acc[mt][nt][3] * a1;
                ped[mt][0] += acc[mt][nt][0] * d0 + acc[mt][nt][1] * d1;
                ped[mt][1] += acc[mt][nt][2] * d0 + acc[mt][nt][3] * d1;
            }
#pragma unroll
        for (int o = 1; o <= 2; o <<= 1) {
#pragma unroll
            for (int mt = 0; mt < 2; mt++)
#pragma unroll
                for (int hh = 0; hh < 2; hh++) {
                    pes[mt][hh] += __shfl_xor_sync(0xffffffffu, pes[mt][hh], o);
                    ped[mt][hh] += __shfl_xor_sync(0xffffffffu, ped[mt][hh], o);
                }
        }
        if (tig == 0) {
#pragma unroll
            for (int mt = 0; mt < 2; mt++)
#pragma unroll
                for (int hh = 0; hh < 2; hh++) {
                    int lr = warp_m * 32 + mt * 16 + hh * 8 + grp;
                    atomicAdd(&sEs[lr], pes[mt][hh]);
                    atomicAdd(&sEd[lr], ped[mt][hh]);
                }
        }
        __syncthreads();
        if (tid < 128) {
            int node = row0 + tid;
            if (node < Nr) {
                es[node * NH + head] = sEs[tid];
                ed[node * NH + head] = sEd[tid];
            }
        }
    }
}

// ---------------- GAT softmax + aggregate: warp per (node, head) ----------------
__global__ __launch_bounds__(256) void agg_kernel(
    const float* __restrict__ feat, const float* __restrict__ es,
    const float* __restrict__ ed, const float* __restrict__ bias,
    const float* __restrict__ res, float* __restrict__ out)
{
    int gw = (blockIdx.x * blockDim.x + threadIdx.x) >> 5;
    int lane = threadIdx.x & 31;
    if (gw >= NN * NH) return;
    int node = gw >> 2, head = gw & 3;
    int s0 = g_rowptr[node], s1 = g_rowptr[node + 1];
    int ch = head * CH + 2 * lane;
    float accx = 0.f, accy = 0.f;

    if (s1 > s0) {
        float edv = ed[node * NH + head];
        float m = -INFINITY, den = 0.f;
        for (int k = s0 + lane; k < s1; k += 32) {
            int s = g_srcsorted[k];
            float e = es[s * NH + head] + edv;
            e = (e >= 0.f) ? e : SLOPE * e;
            if (e > m) { den = den * __expf(m - e) + 1.f; m = e; }
            else den += __expf(e - m);
        }
#pragma unroll
        for (int o = 16; o; o >>= 1) {
            float mo  = __shfl_xor_sync(0xffffffffu, m, o);
            float dno = __shfl_xor_sync(0xffffffffu, den, o);
            float nm = fmaxf(m, mo);
            float f1 = (m == nm) ? 1.f : __expf(m - nm);
            float f2 = (mo == nm) ? 1.f : __expf(mo - nm);
            den = den * f1 + dno * f2;
            m = nm;
        }
        float inv = 1.f / (den + 1e-16f);
        for (int k = s0; k < s1; k++) {
            int s = g_srcsorted[k];
            float e = es[s * NH + head] + edv;
            e = (e >= 0.f) ? e : SLOPE * e;
            float w = __expf(e - m) * inv;
            float2 v = *(const float2*)&feat[(size_t)s * HC + ch];
            accx += w * v.x;
            accy += w * v.y;
        }
    }
    float2 bv = *(const float2*)&bias[ch];
    float2 rv = *(const float2*)&res[(size_t)node * HC + ch];
    float2 o2;
    o2.x = accx + bv.x + rv.x;
    o2.y = accy + bv.y + rv.y;
    *(float2*)&out[(size_t)node * HC + ch] = o2;
}

// ---------------- BatchNorm ----------------
__global__ __launch_bounds__(256) void bn_stats_kernel(const float* __restrict__ x) {
    int chn = threadIdx.x;
    int r0 = blockIdx.x * 64;
    int r1 = min(r0 + 64, NN);
    float s = 0.f, q = 0.f;
    for (int r = r0; r < r1; r++) {
        float v = x[(size_t)r * HC + chn];
        s += v; q += v * v;
    }
    atomicAdd(&g_bnacc[chn], s);
    atomicAdd(&g_bnacc[chn + HC], q);
}

__global__ void bn_finalize_kernel(const float* __restrict__ gma, const float* __restrict__ beta) {
    int c = threadIdx.x;
    float mean = g_bnacc[c] / (float)NN;
    float var  = g_bnacc[c + HC] / (float)NN - mean * mean;
    float a = gma[c] * rsqrtf(var + EPSBN);
    g_bnA[c] = a;
    g_bnB[c] = beta[c] - mean * a;
}

__global__ __launch_bounds__(256) void bn_apply_kernel(float* __restrict__ x) {
    int i = blockIdx.x * blockDim.x + threadIdx.x;
    if (i >= NN * HC / 4) return;
    float4 v = ((const float4*)x)[i];
    int c = (i * 4) & 255;
    v.x = fmaxf(v.x * g_bnA[c + 0] + g_bnB[c + 0], 0.f);
    v.y = fmaxf(v.y * g_bnA[c + 1] + g_bnB[c + 1], 0.f);
    v.z = fmaxf(v.z * g_bnA[c + 2] + g_bnB[c + 2], 0.f);
    v.w = fmaxf(v.w * g_bnA[c + 3] + g_bnB[c + 3], 0.f);
    ((float4*)x)[i] = v;
}

// ---------------- pooling (atomic-free; batch is sorted) ----------------
__global__ __launch_bounds__(256) void pool_kernel(const float* __restrict__ act,
                                                   const int* __restrict__ batch) {
    __shared__ int s_lo, s_hi;
    int g = blockIdx.x;
    int t = threadIdx.x;
    if (t == 0) {
        int lo = 0, hi = NN;
        while (lo < hi) { int mid = (lo + hi) >> 1; if (batch[mid] < g) lo = mid + 1; else hi = mid; }
        s_lo = lo;
        int lo2 = lo; hi = NN;
        while (lo2 < hi) { int mid = (lo2 + hi) >> 1; if (batch[mid] < g + 1) lo2 = mid + 1; else hi = mid; }
        s_hi = lo2;
    }
    __syncthreads();
    int lo = s_lo, hi = s_hi;
    float s = 0.f;
    for (int r = lo; r < hi; r++) s += act[(size_t)r * HC + t];
    float inv = (hi > lo) ? 1.0f / (float)(hi - lo) : 0.0f;
    g_pooled[(size_t)g * HC + t] = s * inv;
}

// ---------------- graph-level MLP ----------------
__global__ __launch_bounds__(128) void mlp_kernel(
    const float* __restrict__ fc1W, const float* __restrict__ fc1b,
    const float* __restrict__ fc2W, const float* __restrict__ fc2b,
    float* __restrict__ out)
{
    __shared__ float row[HC];
    __shared__ float red[128];
    int g = blockIdx.x, t = threadIdx.x;
    row[t]       = g_pooled[(size_t)g * HC + t];
    row[t + 128] = g_pooled[(size_t)g * HC + t + 128];
    __syncthreads();
    float a = fc1b[t];
#pragma unroll 8
    for (int k = 0; k < HC; k++) a += row[k] * fc1W[k * 128 + t];
    a = fmaxf(a, 0.f);
    for (int j = 0; j < 2; j++) {
        red[t] = a * fc2W[t * 2 + j];
        __syncthreads();
        for (int off = 64; off; off >>= 1) {
            if (t < off) red[t] += red[t + off];
            __syncthreads();
        }
        if (t == 0) out[g * 2 + j] = red[0] + fc2b[j];
        __syncthreads();
    }
}

// ---------------- host side ----------------
static void* symp(const void* sym) {
    void* p = nullptr;
    cudaGetSymbolAddress(&p, sym);
    return p;
}

extern "C" void kernel_launch(void* const* d_in, const int* in_sizes, int n_in,
                              void* d_out, int out_size)
{
    const float* x        = (const float*)d_in[0];
    const int*   edge_idx = (const int*)  d_in[1];
    const int*   batch    = (const int*)  d_in[3];
    const float* W1       = (const float*)d_in[4];
    const float* asrc1    = (const float*)d_in[5];
    const float* adst1    = (const float*)d_in[6];
    const float* b1       = (const float*)d_in[7];
    const float* res1W    = (const float*)d_in[8];
    const float* res1b    = (const float*)d_in[9];
    const float* bn1g     = (const float*)d_in[10];
    const float* bn1b     = (const float*)d_in[11];
    const float* W2       = (const float*)d_in[12];
    const float* asrc2    = (const float*)d_in[13];
    const float* adst2    = (const float*)d_in[14];
    const float* b2       = (const float*)d_in[15];
    const float* res2W    = (const float*)d_in[16];
    const float* res2b    = (const float*)d_in[17];
    const float* bn2g     = (const float*)d_in[18];
    const float* bn2b     = (const float*)d_in[19];
    const float* fc1W     = (const float*)d_in[20];
    const float* fc1b     = (const float*)d_in[21];
    const float* fc2W     = (const float*)d_in[22];
    const float* fc2b     = (const float*)d_in[23];
    float* out = (float*)d_out;

    float* feat  = (float*)symp(g_feat);
    float* res   = (float*)symp(g_res);
    float* act   = (float*)symp(g_act);
    float* es    = (float*)symp(g_es);
    float* ed    = (float*)symp(g_ed);
    int*   rowp  = (int*)  symp(g_rowptr);
    int*   curs  = (int*)  symp(g_cursor);
    int*   bsum  = (int*)  symp(g_blocksums);
    int*   boff  = (int*)  symp(g_blockoff);
    float* bnacc = (float*)symp(g_bnacc);
    uint32_t* xh  = (uint32_t*)symp(g_xh),  *xl  = (uint32_t*)symp(g_xl);
    uint32_t* a2h = (uint32_t*)symp(g_a2h), *a2l = (uint32_t*)symp(g_a2l);
    uint32_t* w1h = (uint32_t*)symp(g_w1h), *w1l = (uint32_t*)symp(g_w1l);
    uint32_t* r1h = (uint32_t*)symp(g_r1h), *r1l = (uint32_t*)symp(g_r1l);
    uint32_t* w2h = (uint32_t*)symp(g_w2h), *w2l = (uint32_t*)symp(g_w2l);
    uint32_t* r2h = (uint32_t*)symp(g_r2h), *r2l = (uint32_t*)symp(g_r2l);

    const int NB = (NN + 255) / 256;
    const int EB = (EE + 255) / 256;
    const int WARPBLKS = (NN * NH * 32 + 255) / 256;
    dim3 gemm_grid(HC / 64, (NN + 127) / 128, 2);
    const int W1W = HC * DIN / 2, W2W = HC * HC / 2;

    // ---- prep (gemm L1 lands at launch idx 3 for the ncu capture) ----
    split_f4_kernel<<<(NN * DIN / 4 + 255) / 256, 256>>>(x, xh, xl, NN * DIN / 4);   // 0
    wsplit2_kernel<<<dim3((W1W + 255) / 256, 2), 256>>>(W1, res1W, w1h, w1l, r1h, r1l, DIN); // 1
    zero_int_kernel<<<NB, 256>>>(curs, NN);                                          // 2

    gemm2tcs_kernel<<<gemm_grid, 256>>>(xh, xl, w1h, w1l, r1h, r1l, res1b,
                                        asrc1, adst1, feat, res, es, ed,
                                        NN, DIN);                                    // 3 <- profiled

    // ---- CSR build ----
    count_deg_kernel<<<EB, 256>>>(edge_idx);
    scan_block_kernel<<<NB, 256>>>(curs, rowp, bsum, NN);
    scan_block_kernel<<<1, 256>>>(bsum, boff, nullptr, NB);
    scan_add_kernel<<<NB, 256>>>(rowp, boff, NN);
    copy_int_kernel<<<NB, 256>>>(curs, rowp, NN);
    fill_csr_kernel<<<EB, 256>>>(edge_idx);

    // ---- layer 1 rest ----
    agg_kernel<<<WARPBLKS, 256>>>(feat, es, ed, b1, res, act);
    zero_float_kernel<<<2, 256>>>(bnacc, 2 * HC);
    bn_stats_kernel<<<(NN + 63) / 64, 256>>>(act);
    bn_finalize_kernel<<<1, HC>>>(bn1g, bn1b);
    bn_apply_split_kernel<<<(NN * HC / 4 + 255) / 256, 256>>>(act, a2h, a2l);

    // ---- layer 2 ----
    wsplit2_kernel<<<dim3((W2W + 255) / 256, 2), 256>>>(W2, res2W, w2h, w2l, r2h, r2l, HC);
    gemm2tcs_kernel<<<gemm_grid, 256>>>(a2h, a2l, w2h, w2l, r2h, r2l, res2b,
                                        asrc2, adst2, feat, res, es, ed,
                                        NN, HC);
    agg_kernel<<<WARPBLKS, 256>>>(feat, es, ed, b2, res, act);
    zero_float_kernel<<<2, 256>>>(bnacc, 2 * HC);
    bn_stats_kernel<<<(NN + 63) / 64, 256>>>(act);
    bn_finalize_kernel<<<1, HC>>>(bn2g, bn2b);
    bn_apply_kernel<<<(NN * HC / 4 + 255) / 256, 256>>>(act);

    // ---- pooling + MLP ----
    pool_kernel<<<NG, 256>>>(act, batch);
    mlp_kernel<<<NG, 128>>>(fc1W, fc1b, fc2W, fc2b, out);
}

// round 9
// speedup vs baseline: 1.2806x; 1.2164x over previous
#include <cuda_runtime.h>
#include <cstdint>

#define NN 50000
#define EE 800000
#define DIN 128
#define NH 4
#define CH 64
#define HC 256
#define NG 512
#define EPSBN 1e-5f
#define SLOPE 0.2f

// ---------------- scratch ----------------
__device__ float g_feat[(size_t)NN * HC];
__device__ float g_res [(size_t)NN * HC];
__device__ float g_act [(size_t)NN * HC];
__device__ float g_es[NN * NH];
__device__ float g_ed[NN * NH];
__device__ int   g_rowptr[NN + 1];
__device__ int   g_cursor[NN];
__device__ int   g_srcsorted[EE];
__device__ int   g_blocksums[256];
__device__ int   g_blockoff[256];
__device__ float g_bnacc[2 * HC];
__device__ float g_bnA[HC];
__device__ float g_bnB[HC];
__device__ float g_pooled[NG * HC];
// fp16 operand buffers (fp16x2 words, 2 k per word)
__device__ uint32_t g_x16[(size_t)NN * DIN / 2];
__device__ uint32_t g_a216[(size_t)NN * HC / 2];
__device__ uint32_t g_w116[HC * DIN / 2], g_r116[HC * DIN / 2];
__device__ uint32_t g_w216[HC * HC / 2],  g_r216[HC * HC / 2];

// pack float2 -> fp16x2 (x in low half, y in high half)
__device__ __forceinline__ uint32_t f2h2(float2 v) {
    uint32_t r;
    asm("cvt.rn.f16x2.f32 %0, %1, %2;" : "=r"(r) : "f"(v.y), "f"(v.x));
    return r;
}

// ---------------- tiny utility kernels ----------------
__global__ void zero_float_kernel(float* p, int n) {
    int i = blockIdx.x * blockDim.x + threadIdx.x;
    if (i < n) p[i] = 0.0f;
}
__global__ void zero_int_kernel(int* p, int n) {
    int i = blockIdx.x * blockDim.x + threadIdx.x;
    if (i < n) p[i] = 0;
}
__global__ void copy_int_kernel(int* dst, const int* src, int n) {
    int i = blockIdx.x * blockDim.x + threadIdx.x;
    if (i < n) dst[i] = src[i];
}

// ---------------- prep: fp32 -> fp16 conversions ----------------
__global__ void cvt16_f4_kernel(const float* __restrict__ src,
                                uint32_t* __restrict__ dst, int n4) {
    int i = blockIdx.x * blockDim.x + threadIdx.x;
    if (i >= n4) return;
    float4 v = ((const float4*)src)[i];
    dst[2 * i]     = f2h2(make_float2(v.x, v.y));
    dst[2 * i + 1] = f2h2(make_float2(v.z, v.w));
}

// two weights at once (blockIdx.y selects); W[K][256] -> Wt fp16 [256][K/2]
__global__ void wcvt2_kernel(const float* __restrict__ W0, const float* __restrict__ W1,
                             uint32_t* __restrict__ t0, uint32_t* __restrict__ t1,
                             int Kd) {
    const float* W = blockIdx.y ? W1 : W0;
    uint32_t* th = blockIdx.y ? t1 : t0;
    int idx = blockIdx.x * blockDim.x + threadIdx.x;
    int kw = Kd >> 1;
    if (idx >= HC * kw) return;
    int n = idx / kw, kp = idx % kw;
    float a = W[(size_t)(2 * kp) * HC + n];
    float b = W[(size_t)(2 * kp + 1) * HC + n];
    th[idx] = f2h2(make_float2(a, b));
}

// BN+ReLU applied to act, output packed fp16 (layer-2 GEMM input)
__global__ __launch_bounds__(256) void bn_apply_cvt_kernel(const float* __restrict__ x,
                                                           uint32_t* __restrict__ dh) {
    int i = blockIdx.x * blockDim.x + threadIdx.x;
    if (i >= NN * HC / 4) return;
    float4 v = ((const float4*)x)[i];
    int c = (i * 4) & 255;
    v.x = fmaxf(v.x * g_bnA[c + 0] + g_bnB[c + 0], 0.f);
    v.y = fmaxf(v.y * g_bnA[c + 1] + g_bnB[c + 1], 0.f);
    v.z = fmaxf(v.z * g_bnA[c + 2] + g_bnB[c + 2], 0.f);
    v.w = fmaxf(v.w * g_bnA[c + 3] + g_bnB[c + 3], 0.f);
    dh[2 * i]     = f2h2(make_float2(v.x, v.y));
    dh[2 * i + 1] = f2h2(make_float2(v.z, v.w));
}

// ---------------- CSR build ----------------
__global__ void count_deg_kernel(const int* __restrict__ ei) {
    int e = blockIdx.x * blockDim.x + threadIdx.x;
    if (e >= EE) return;
    atomicAdd(&g_cursor[ei[EE + e]], 1);
}

__global__ void scan_block_kernel(const int* __restrict__ in, int* __restrict__ out,
                                  int* __restrict__ blocksums, int n) {
    __shared__ int sh[256];
    int tid = threadIdx.x;
    int i = blockIdx.x * 256 + tid;
    int v = (i < n) ? in[i] : 0;
    sh[tid] = v;
    __syncthreads();
    for (int off = 1; off < 256; off <<= 1) {
        int t = (tid >= off) ? sh[tid - off] : 0;
        __syncthreads();
        sh[tid] += t;
        __syncthreads();
    }
    if (i < n) out[i] = sh[tid] - v;
    if (tid == 255 && blocksums) blocksums[blockIdx.x] = sh[255];
}

__global__ void scan_add_kernel(int* __restrict__ rowptr, const int* __restrict__ blockoff, int n) {
    int i = blockIdx.x * 256 + threadIdx.x;
    if (i < n) rowptr[i] += blockoff[blockIdx.x];
    if (blockIdx.x == 0 && threadIdx.x == 0) rowptr[n] = EE;
}

__global__ void fill_csr_kernel(const int* __restrict__ ei) {
    int e = blockIdx.x * blockDim.x + threadIdx.x;
    if (e >= EE) return;
    int s = ei[e];
    int d = ei[EE + e];
    int pos = atomicAdd(&g_cursor[d], 1);
    g_srcsorted[pos] = s;
}

// ============================================================================
// Tensor-core dual GEMM, fp16 single-product, ldmatrix.x4 fragment loads.
// A: fp16x2 words [Nr][K/2]; B: transposed fp16x2 [256][K/2].
// Block tile 128x64 (col tile == one head), 8 warps (4m x 2n), warp 32x32,
// k-tile 16, mma.m16n8k16.f16. 4 LDSM.x4 + 8 MMA per warp per k-tile.
// smem row pitch 12 words -> every ldmatrix 8-address phase covers 32 banks.
// z==0 branch computes es/ed (attention dots) in the epilogue.
// ============================================================================
#define AST 12   // words per smem row (8 data + 4 pad)

__device__ __forceinline__ void mma_f16(float* d, const uint32_t* a,
                                        uint32_t b0, uint32_t b1) {
    asm volatile(
        "mma.sync.aligned.m16n8k16.row.col.f32.f16.f16.f32 "
        "{%0,%1,%2,%3}, {%4,%5,%6,%7}, {%8,%9}, {%0,%1,%2,%3};\n"
        : "+f"(d[0]), "+f"(d[1]), "+f"(d[2]), "+f"(d[3])
        : "r"(a[0]), "r"(a[1]), "r"(a[2]), "r"(a[3]), "r"(b0), "r"(b1));
}

__device__ __forceinline__ void ldsm_x4(uint32_t& r0, uint32_t& r1,
                                        uint32_t& r2, uint32_t& r3, uint32_t saddr) {
    asm volatile("ldmatrix.sync.aligned.m8n8.x4.shared.b16 {%0,%1,%2,%3}, [%4];"
                 : "=r"(r0), "=r"(r1), "=r"(r2), "=r"(r3) : "r"(saddr));
}

__device__ __forceinline__ void cp_async16u(uint32_t* smem_ptr, const uint32_t* gptr, bool pred) {
    uint32_t sa = (uint32_t)__cvta_generic_to_shared(smem_ptr);
    int bytes = pred ? 16 : 0;
    asm volatile("cp.async.ca.shared.global [%0], [%1], 16, %2;\n"
                 :: "r"(sa), "l"(gptr), "r"(bytes));
}

__global__ __launch_bounds__(256) void gemm16_kernel(
    const uint32_t* __restrict__ A16,
    const uint32_t* __restrict__ B16W, const uint32_t* __restrict__ B16R,
    const float* __restrict__ bias1,
    const float* __restrict__ asrc, const float* __restrict__ adst,
    float* __restrict__ C0, float* __restrict__ C1,
    float* __restrict__ es, float* __restrict__ ed,
    int Nr, int K)
{
    __shared__ uint32_t sA[2][128 * AST];
    __shared__ uint32_t sB[2][64 * AST];
    __shared__ float sEs[128], sEd[128];

    const uint32_t* B = blockIdx.z ? B16R : B16W;
    float*         Cc = blockIdx.z ? C1 : C0;
    const bool   hasb = blockIdx.z != 0;

    const int Kw = K >> 1;
    const int tid  = threadIdx.x;
    const int lane = tid & 31;
    const int wid  = tid >> 5;
    const int warp_m = wid & 3;
    const int warp_n = wid >> 2;
    const int row0 = blockIdx.y * 128;
    const int col0 = blockIdx.x * 64;

    const int grp = lane >> 2;
    const int tig = lane & 3;

    if (tid < 128) { sEs[tid] = 0.f; sEd[tid] = 0.f; }

    float acc[2][4][4];
#pragma unroll
    for (int mt = 0; mt < 2; mt++)
#pragma unroll
        for (int nt = 0; nt < 4; nt++)
#pragma unroll
            for (int i = 0; i < 4; i++) acc[mt][nt][i] = 0.f;

    const int a_row = tid >> 1;        // 0..127
    const int a_wof = (tid & 1) * 4;   // word offset 0 or 4
    const int b_row = (tid & 127) >> 1;
    const int b_wof = (tid & 1) * 4;
    const bool do_b = tid < 128;

    const int T = K / 16;

    const uint32_t sA_a = (uint32_t)__cvta_generic_to_shared(&sA[0][0]);
    const uint32_t sB_a = (uint32_t)__cvta_generic_to_shared(&sB[0][0]);
    const uint32_t aoff = ((warp_m * 32 + (lane & 15)) * AST + (lane >> 4) * 4) * 4;
    const uint32_t boff = ((warp_n * 32 + (lane & 7) + ((lane >> 4) << 3)) * AST
                          + ((lane >> 3) & 1) * 4) * 4;
    const uint32_t ABUF = 128 * AST * 4;
    const uint32_t BBUF = 64 * AST * 4;
    const uint32_t MTSTEP = 16 * AST * 4;   // +16 rows

    auto load_tile = [&](int it, int buf) {
        int gr = row0 + a_row;
        cp_async16u(&sA[buf][a_row * AST + a_wof],
                    &A16[(size_t)gr * Kw + it * 8 + a_wof], gr < Nr);
        if (do_b)
            cp_async16u(&sB[buf][b_row * AST + b_wof],
                        &B[(size_t)(col0 + b_row) * Kw + it * 8 + b_wof], true);
        asm volatile("cp.async.commit_group;\n");
    };

    load_tile(0, 0);
    load_tile(1, 1);

    for (int it = 0; it < T; it++) {
        if (it < T - 1) asm volatile("cp.async.wait_group 1;\n");
        else            asm volatile("cp.async.wait_group 0;\n");
        __syncthreads();
        const uint32_t bufo = (it & 1) ? 1u : 0u;
        const uint32_t ab = sA_a + bufo * ABUF + aoff;
        const uint32_t bb = sB_a + bufo * BBUF + boff;

        uint32_t ah[2][4], bh[4][2];
        ldsm_x4(ah[0][0], ah[0][1], ah[0][2], ah[0][3], ab);
        ldsm_x4(ah[1][0], ah[1][1], ah[1][2], ah[1][3], ab + MTSTEP);
        ldsm_x4(bh[0][0], bh[0][1], bh[1][0], bh[1][1], bb);
        ldsm_x4(bh[2][0], bh[2][1], bh[3][0], bh[3][1], bb + MTSTEP);

#pragma unroll
        for (int nt = 0; nt < 4; nt++)
#pragma unroll
            for (int mt = 0; mt < 2; mt++)
                mma_f16(acc[mt][nt], ah[mt], bh[nt][0], bh[nt][1]);

        __syncthreads();
        if (it + 2 < T) load_tile(it + 2, it & 1);
    }

    // ---- C write ----
#pragma unroll
    for (int mt = 0; mt < 2; mt++) {
        int r = row0 + warp_m * 32 + mt * 16 + grp;
#pragma unroll
        for (int nt = 0; nt < 4; nt++) {
            int c = col0 + warp_n * 32 + nt * 8 + 2 * tig;
            float bx = 0.f, by = 0.f;
            if (hasb) { bx = bias1[c]; by = bias1[c + 1]; }
            if (r < Nr)
                *(float2*)&Cc[(size_t)r * HC + c] =
                    make_float2(acc[mt][nt][0] + bx, acc[mt][nt][1] + by);
            if (r + 8 < Nr)
                *(float2*)&Cc[(size_t)(r + 8) * HC + c] =
                    make_float2(acc[mt][nt][2] + bx, acc[mt][nt][3] + by);
        }
    }

    // ---- fused attention dots (feat branch only) ----
    if (blockIdx.z == 0) {
        const int head = blockIdx.x;
        float pes[2][2] = {{0.f, 0.f}, {0.f, 0.f}};
        float ped[2][2] = {{0.f, 0.f}, {0.f, 0.f}};
#pragma unroll
        for (int mt = 0; mt < 2; mt++)
#pragma unroll
            for (int nt = 0; nt < 4; nt++) {
                int cl = warp_n * 32 + nt * 8 + 2 * tig;
                float a0 = asrc[head * CH + cl], a1 = asrc[head * CH + cl + 1];
                float d0 = adst[head * CH + cl], d1 = adst[head * CH + cl + 1];
                pes[mt][0] += acc[mt][nt][0] * a0 + acc[mt][nt][1] * a1;
                pes[mt][1] += acc[mt][nt][2] * a0 + acc[mt][nt][3] * a1;
                ped[mt][0] += acc[mt][nt][0] * d0 + acc[mt][nt][1] * d1;
                ped[mt][1] += acc[mt][nt][2] * d0 + acc[mt][nt][3] * d1;
            }
#pragma unroll
        for (int o = 1; o <= 2; o <<= 1) {
#pragma unroll
            for (int mt = 0; mt < 2; mt++)
#pragma unroll
                for (int hh = 0; hh < 2; hh++) {
                    pes[mt][hh] += __shfl_xor_sync(0xffffffffu, pes[mt][hh], o);
                    ped[mt][hh] += __shfl_xor_sync(0xffffffffu, ped[mt][hh], o);
                }
        }
        if (tig == 0) {
#pragma unroll
            for (int mt = 0; mt < 2; mt++)
#pragma unroll
                for (int hh = 0; hh < 2; hh++) {
                    int lr = warp_m * 32 + mt * 16 + hh * 8 + grp;
                    atomicAdd(&sEs[lr], pes[mt][hh]);
                    atomicAdd(&sEd[lr], ped[mt][hh]);
                }
        }
        __syncthreads();
        if (tid < 128) {
            int node = row0 + tid;
            if (node < Nr) {
                es[node * NH + head] = sEs[tid];
                ed[node * NH + head] = sEd[tid];
            }
        }
    }
}

// ---------------- GAT softmax + aggregate: warp per (node, head) ----------------
__global__ __launch_bounds__(256) void agg_kernel(
    const float* __restrict__ feat, const float* __restrict__ es,
    const float* __restrict__ ed, const float* __restrict__ bias,
    const float* __restrict__ res, float* __restrict__ out)
{
    int gw = (blockIdx.x * blockDim.x + threadIdx.x) >> 5;
    int lane = threadIdx.x & 31;
    if (gw >= NN * NH) return;
    int node = gw >> 2, head = gw & 3;
    int s0 = g_rowptr[node], s1 = g_rowptr[node + 1];
    int ch = head * CH + 2 * lane;
    float accx = 0.f, accy = 0.f;

    if (s1 > s0) {
        float edv = ed[node * NH + head];
        float m = -INFINITY, den = 0.f;
        for (int k = s0 + lane; k < s1; k += 32) {
            int s = g_srcsorted[k];
            float e = es[s * NH + head] + edv;
            e = (e >= 0.f) ? e : SLOPE * e;
            if (e > m) { den = den * __expf(m - e) + 1.f; m = e; }
            else den += __expf(e - m);
        }
#pragma unroll
        for (int o = 16; o; o >>= 1) {
            float mo  = __shfl_xor_sync(0xffffffffu, m, o);
            float dno = __shfl_xor_sync(0xffffffffu, den, o);
            float nm = fmaxf(m, mo);
            float f1 = (m == nm) ? 1.f : __expf(m - nm);
            float f2 = (mo == nm) ? 1.f : __expf(mo - nm);
            den = den * f1 + dno * f2;
            m = nm;
        }
        float inv = 1.f / (den + 1e-16f);
        for (int k = s0; k < s1; k++) {
            int s = g_srcsorted[k];
            float e = es[s * NH + head] + edv;
            e = (e >= 0.f) ? e : SLOPE * e;
            float w = __expf(e - m) * inv;
            float2 v = *(const float2*)&feat[(size_t)s * HC + ch];
            accx += w * v.x;
            accy += w * v.y;
        }
    }
    float2 bv = *(const float2*)&bias[ch];
    float2 rv = *(const float2*)&res[(size_t)node * HC + ch];
    float2 o2;
    o2.x = accx + bv.x + rv.x;
    o2.y = accy + bv.y + rv.y;
    *(float2*)&out[(size_t)node * HC + ch] = o2;
}

// ---------------- BatchNorm ----------------
__global__ __launch_bounds__(256) void bn_stats_kernel(const float* __restrict__ x) {
    int chn = threadIdx.x;
    int r0 = blockIdx.x * 64;
    int r1 = min(r0 + 64, NN);
    float s = 0.f, q = 0.f;
    for (int r = r0; r < r1; r++) {
        float v = x[(size_t)r * HC + chn];
        s += v; q += v * v;
    }
    atomicAdd(&g_bnacc[chn], s);
    atomicAdd(&g_bnacc[chn + HC], q);
}

__global__ void bn_finalize_kernel(const float* __restrict__ gma, const float* __restrict__ beta) {
    int c = threadIdx.x;
    float mean = g_bnacc[c] / (float)NN;
    float var  = g_bnacc[c + HC] / (float)NN - mean * mean;
    float a = gma[c] * rsqrtf(var + EPSBN);
    g_bnA[c] = a;
    g_bnB[c] = beta[c] - mean * a;
}

__global__ __launch_bounds__(256) void bn_apply_kernel(float* __restrict__ x) {
    int i = blockIdx.x * blockDim.x + threadIdx.x;
    if (i >= NN * HC / 4) return;
    float4 v = ((const float4*)x)[i];
    int c = (i * 4) & 255;
    v.x = fmaxf(v.x * g_bnA[c + 0] + g_bnB[c + 0], 0.f);
    v.y = fmaxf(v.y * g_bnA[c + 1] + g_bnB[c + 1], 0.f);
    v.z = fmaxf(v.z * g_bnA[c + 2] + g_bnB[c + 2], 0.f);
    v.w = fmaxf(v.w * g_bnA[c + 3] + g_bnB[c + 3], 0.f);
    ((float4*)x)[i] = v;
}

// ---------------- pooling (atomic-free; batch is sorted) ----------------
__global__ __launch_bounds__(256) void pool_kernel(const float* __restrict__ act,
                                                   const int* __restrict__ batch) {
    __shared__ int s_lo, s_hi;
    int g = blockIdx.x;
    int t = threadIdx.x;
    if (t == 0) {
        int lo = 0, hi = NN;
        while (lo < hi) { int mid = (lo + hi) >> 1; if (batch[mid] < g) lo = mid + 1; else hi = mid; }
        s_lo = lo;
        int lo2 = lo; hi = NN;
        while (lo2 < hi) { int mid = (lo2 + hi) >> 1; if (batch[mid] < g + 1) lo2 = mid + 1; else hi = mid; }
        s_hi = lo2;
    }
    __syncthreads();
    int lo = s_lo, hi = s_hi;
    float s = 0.f;
    for (int r = lo; r < hi; r++) s += act[(size_t)r * HC + t];
    float inv = (hi > lo) ? 1.0f / (float)(hi - lo) : 0.0f;
    g_pooled[(size_t)g * HC + t] = s * inv;
}

// ---------------- graph-level MLP ----------------
__global__ __launch_bounds__(128) void mlp_kernel(
    const float* __restrict__ fc1W, const float* __restrict__ fc1b,
    const float* __restrict__ fc2W, const float* __restrict__ fc2b,
    float* __restrict__ out)
{
    __shared__ float row[HC];
    __shared__ float red[128];
    int g = blockIdx.x, t = threadIdx.x;
    row[t]       = g_pooled[(size_t)g * HC + t];
    row[t + 128] = g_pooled[(size_t)g * HC + t + 128];
    __syncthreads();
    float a = fc1b[t];
#pragma unroll 8
    for (int k = 0; k < HC; k++) a += row[k] * fc1W[k * 128 + t];
    a = fmaxf(a, 0.f);
    for (int j = 0; j < 2; j++) {
        red[t] = a * fc2W[t * 2 + j];
        __syncthreads();
        for (int off = 64; off; off >>= 1) {
            if (t < off) red[t] += red[t + off];
            __syncthreads();
        }
        if (t == 0) out[g * 2 + j] = red[0] + fc2b[j];
        __syncthreads();
    }
}

// ---------------- host side ----------------
static void* symp(const void* sym) {
    void* p = nullptr;
    cudaGetSymbolAddress(&p, sym);
    return p;
}

extern "C" void kernel_launch(void* const* d_in, const int* in_sizes, int n_in,
                              void* d_out, int out_size)
{
    const float* x        = (const float*)d_in[0];
    const int*   edge_idx = (const int*)  d_in[1];
    const int*   batch    = (const int*)  d_in[3];
    const float* W1       = (const float*)d_in[4];
    const float* asrc1    = (const float*)d_in[5];
    const float* adst1    = (const float*)d_in[6];
    const float* b1       = (const float*)d_in[7];
    const float* res1W    = (const float*)d_in[8];
    const float* res1b    = (const float*)d_in[9];
    const float* bn1g     = (const float*)d_in[10];
    const float* bn1b     = (const float*)d_in[11];
    const float* W2       = (const float*)d_in[12];
    const float* asrc2    = (const float*)d_in[13];
    const float* adst2    = (const float*)d_in[14];
    const float* b2       = (const float*)d_in[15];
    const float* res2W    = (const float*)d_in[16];
    const float* res2b    = (const float*)d_in[17];
    const float* bn2g     = (const float*)d_in[18];
    const float* bn2b     = (const float*)d_in[19];
    const float* fc1W     = (const float*)d_in[20];
    const float* fc1b     = (const float*)d_in[21];
    const float* fc2W     = (const float*)d_in[22];
    const float* fc2b     = (const float*)d_in[23];
    float* out = (float*)d_out;

    float* feat  = (float*)symp(g_feat);
    float* res   = (float*)symp(g_res);
    float* act   = (float*)symp(g_act);
    float* es    = (float*)symp(g_es);
    float* ed    = (float*)symp(g_ed);
    int*   rowp  = (int*)  symp(g_rowptr);
    int*   curs  = (int*)  symp(g_cursor);
    int*   bsum  = (int*)  symp(g_blocksums);
    int*   boff  = (int*)  symp(g_blockoff);
    float* bnacc = (float*)symp(g_bnacc);
    uint32_t* x16  = (uint32_t*)symp(g_x16);
    uint32_t* a216 = (uint32_t*)symp(g_a216);
    uint32_t* w116 = (uint32_t*)symp(g_w116), *r116 = (uint32_t*)symp(g_r116);
    uint32_t* w216 = (uint32_t*)symp(g_w216), *r216 = (uint32_t*)symp(g_r216);

    const int NB = (NN + 255) / 256;
    const int EB = (EE + 255) / 256;
    const int WARPBLKS = (NN * NH * 32 + 255) / 256;
    dim3 gemm_grid(HC / 64, (NN + 127) / 128, 2);
    const int W1W = HC * DIN / 2, W2W = HC * HC / 2;

    // ---- prep (gemm L1 lands at launch idx 3 for the ncu capture) ----
    cvt16_f4_kernel<<<(NN * DIN / 4 + 255) / 256, 256>>>(x, x16, NN * DIN / 4);        // 0
    wcvt2_kernel<<<dim3((W1W + 255) / 256, 2), 256>>>(W1, res1W, w116, r116, DIN);     // 1
    zero_int_kernel<<<NB, 256>>>(curs, NN);                                            // 2

    gemm16_kernel<<<gemm_grid, 256>>>(x16, w116, r116, res1b,
                                      asrc1, adst1, feat, res, es, ed,
                                      NN, DIN);                                        // 3 <- profiled

    // ---- CSR build ----
    count_deg_kernel<<<EB, 256>>>(edge_idx);
    scan_block_kernel<<<NB, 256>>>(curs, rowp, bsum, NN);
    scan_block_kernel<<<1, 256>>>(bsum, boff, nullptr, NB);
    scan_add_kernel<<<NB, 256>>>(rowp, boff, NN);
    copy_int_kernel<<<NB, 256>>>(curs, rowp, NN);
    fill_csr_kernel<<<EB, 256>>>(edge_idx);

    // ---- layer 1 rest ----
    agg_kernel<<<WARPBLKS, 256>>>(feat, es, ed, b1, res, act);
    zero_float_kernel<<<2, 256>>>(bnacc, 2 * HC);
    bn_stats_kernel<<<(NN + 63) / 64, 256>>>(act);
    bn_finalize_kernel<<<1, HC>>>(bn1g, bn1b);
    bn_apply_cvt_kernel<<<(NN * HC / 4 + 255) / 256, 256>>>(act, a216);

    // ---- layer 2 ----
    wcvt2_kernel<<<dim3((W2W + 255) / 256, 2), 256>>>(W2, res2W, w216, r216, HC);
    gemm16_kernel<<<gemm_grid, 256>>>(a216, w216, r216, res2b,
                                      asrc2, adst2, feat, res, es, ed,
                                      NN, HC);
    agg_kernel<<<WARPBLKS, 256>>>(feat, es, ed, b2, res, act);
    zero_float_kernel<<<2, 256>>>(bnacc, 2 * HC);
    bn_stats_kernel<<<(NN + 63) / 64, 256>>>(act);
    bn_finalize_kernel<<<1, HC>>>(bn2g, bn2b);
    bn_apply_kernel<<<(NN * HC / 4 + 255) / 256, 256>>>(act);

    // ---- pooling + MLP ----
    pool_kernel<<<NG, 256>>>(act, batch);
    mlp_kernel<<<NG, 128>>>(fc1W, fc1b, fc2W, fc2b, out);
}

// round 10
// speedup vs baseline: 1.8007x; 1.4061x over previous
#include <cuda_runtime.h>
#include <cuda_fp16.h>
#include <cstdint>

#define NN 50000
#define EE 800000
#define DIN 128
#define NH 4
#define CH 64
#define HC 256
#define NG 512
#define EPSBN 1e-5f
#define SLOPE 0.2f

// ---------------- scratch ----------------
__device__ uint32_t g_f16[(size_t)NN * HC / 2];   // feat in fp16x2 (gather source)
__device__ float g_res [(size_t)NN * HC];
__device__ float g_act [(size_t)NN * HC];
__device__ float g_es[NN * NH];
__device__ float g_ed[NN * NH];
__device__ int   g_rowptr[NN + 1];
__device__ int   g_cursor[NN];
__device__ int   g_srcsorted[EE];
__device__ int   g_blocksums[256];
__device__ int   g_blockoff[256];
__device__ float g_bnacc[2 * HC];
__device__ float g_bnA[HC];
__device__ float g_bnB[HC];
__device__ float g_pooled[NG * HC];
// fp16 GEMM operand buffers
__device__ uint32_t g_x16[(size_t)NN * DIN / 2];
__device__ uint32_t g_a216[(size_t)NN * HC / 2];
__device__ uint32_t g_w116[HC * DIN / 2], g_r116[HC * DIN / 2];
__device__ uint32_t g_w216[HC * HC / 2],  g_r216[HC * HC / 2];

__device__ __forceinline__ uint32_t f2h2(float2 v) {
    uint32_t r;
    asm("cvt.rn.f16x2.f32 %0, %1, %2;" : "=r"(r) : "f"(v.y), "f"(v.x));
    return r;
}

// ---------------- tiny utility kernels ----------------
__global__ void zero_float_kernel(float* p, int n) {
    int i = blockIdx.x * blockDim.x + threadIdx.x;
    if (i < n) p[i] = 0.0f;
}
__global__ void zero_int_kernel(int* p, int n) {
    int i = blockIdx.x * blockDim.x + threadIdx.x;
    if (i < n) p[i] = 0;
}
__global__ void copy_int_kernel(int* dst, const int* src, int n) {
    int i = blockIdx.x * blockDim.x + threadIdx.x;
    if (i < n) dst[i] = src[i];
}

// ---------------- prep: fp32 -> fp16 conversions ----------------
__global__ void cvt16_f4_kernel(const float* __restrict__ src,
                                uint32_t* __restrict__ dst, int n4) {
    int i = blockIdx.x * blockDim.x + threadIdx.x;
    if (i >= n4) return;
    float4 v = ((const float4*)src)[i];
    dst[2 * i]     = f2h2(make_float2(v.x, v.y));
    dst[2 * i + 1] = f2h2(make_float2(v.z, v.w));
}

__global__ void wcvt2_kernel(const float* __restrict__ W0, const float* __restrict__ W1,
                             uint32_t* __restrict__ t0, uint32_t* __restrict__ t1,
                             int Kd) {
    const float* W = blockIdx.y ? W1 : W0;
    uint32_t* th = blockIdx.y ? t1 : t0;
    int idx = blockIdx.x * blockDim.x + threadIdx.x;
    int kw = Kd >> 1;
    if (idx >= HC * kw) return;
    int n = idx / kw, kp = idx % kw;
    float a = W[(size_t)(2 * kp) * HC + n];
    float b = W[(size_t)(2 * kp + 1) * HC + n];
    th[idx] = f2h2(make_float2(a, b));
}

__global__ __launch_bounds__(256) void bn_apply_cvt_kernel(const float* __restrict__ x,
                                                           uint32_t* __restrict__ dh) {
    int i = blockIdx.x * blockDim.x + threadIdx.x;
    if (i >= NN * HC / 4) return;
    float4 v = ((const float4*)x)[i];
    int c = (i * 4) & 255;
    v.x = fmaxf(v.x * g_bnA[c + 0] + g_bnB[c + 0], 0.f);
    v.y = fmaxf(v.y * g_bnA[c + 1] + g_bnB[c + 1], 0.f);
    v.z = fmaxf(v.z * g_bnA[c + 2] + g_bnB[c + 2], 0.f);
    v.w = fmaxf(v.w * g_bnA[c + 3] + g_bnB[c + 3], 0.f);
    dh[2 * i]     = f2h2(make_float2(v.x, v.y));
    dh[2 * i + 1] = f2h2(make_float2(v.z, v.w));
}

// ---------------- CSR build ----------------
__global__ void count_deg_kernel(const int* __restrict__ ei) {
    int e = blockIdx.x * blockDim.x + threadIdx.x;
    if (e >= EE) return;
    atomicAdd(&g_cursor[ei[EE + e]], 1);
}

__global__ void scan_block_kernel(const int* __restrict__ in, int* __restrict__ out,
                                  int* __restrict__ blocksums, int n) {
    __shared__ int sh[256];
    int tid = threadIdx.x;
    int i = blockIdx.x * 256 + tid;
    int v = (i < n) ? in[i] : 0;
    sh[tid] = v;
    __syncthreads();
    for (int off = 1; off < 256; off <<= 1) {
        int t = (tid >= off) ? sh[tid - off] : 0;
        __syncthreads();
        sh[tid] += t;
        __syncthreads();
    }
    if (i < n) out[i] = sh[tid] - v;
    if (tid == 255 && blocksums) blocksums[blockIdx.x] = sh[255];
}

__global__ void scan_add_kernel(int* __restrict__ rowptr, const int* __restrict__ blockoff, int n) {
    int i = blockIdx.x * 256 + threadIdx.x;
    if (i < n) rowptr[i] += blockoff[blockIdx.x];
    if (blockIdx.x == 0 && threadIdx.x == 0) rowptr[n] = EE;
}

__global__ void fill_csr_kernel(const int* __restrict__ ei) {
    int e = blockIdx.x * blockDim.x + threadIdx.x;
    if (e >= EE) return;
    int s = ei[e];
    int d = ei[EE + e];
    int pos = atomicAdd(&g_cursor[d], 1);
    g_srcsorted[pos] = s;
}

// ============================================================================
// Tensor-core dual GEMM, fp16 single-product, ldmatrix.x4 fragment loads.
// z==0 (feat branch): writes fp16x2 words + fused attention dots.
// z==1 (residual):    writes fp32 + bias.
// ============================================================================
#define AST 12

__device__ __forceinline__ void mma_f16(float* d, const uint32_t* a,
                                        uint32_t b0, uint32_t b1) {
    asm volatile(
        "mma.sync.aligned.m16n8k16.row.col.f32.f16.f16.f32 "
        "{%0,%1,%2,%3}, {%4,%5,%6,%7}, {%8,%9}, {%0,%1,%2,%3};\n"
        : "+f"(d[0]), "+f"(d[1]), "+f"(d[2]), "+f"(d[3])
        : "r"(a[0]), "r"(a[1]), "r"(a[2]), "r"(a[3]), "r"(b0), "r"(b1));
}

__device__ __forceinline__ void ldsm_x4(uint32_t& r0, uint32_t& r1,
                                        uint32_t& r2, uint32_t& r3, uint32_t saddr) {
    asm volatile("ldmatrix.sync.aligned.m8n8.x4.shared.b16 {%0,%1,%2,%3}, [%4];"
                 : "=r"(r0), "=r"(r1), "=r"(r2), "=r"(r3) : "r"(saddr));
}

__device__ __forceinline__ void cp_async16u(uint32_t* smem_ptr, const uint32_t* gptr, bool pred) {
    uint32_t sa = (uint32_t)__cvta_generic_to_shared(smem_ptr);
    int bytes = pred ? 16 : 0;
    asm volatile("cp.async.ca.shared.global [%0], [%1], 16, %2;\n"
                 :: "r"(sa), "l"(gptr), "r"(bytes));
}

__global__ __launch_bounds__(256) void gemm16_kernel(
    const uint32_t* __restrict__ A16,
    const uint32_t* __restrict__ B16W, const uint32_t* __restrict__ B16R,
    const float* __restrict__ bias1,
    const float* __restrict__ asrc, const float* __restrict__ adst,
    uint32_t* __restrict__ Cf16, float* __restrict__ C1,
    float* __restrict__ es, float* __restrict__ ed,
    int Nr, int K)
{
    __shared__ uint32_t sA[2][128 * AST];
    __shared__ uint32_t sB[2][64 * AST];
    __shared__ float sEs[128], sEd[128];

    const uint32_t* B = blockIdx.z ? B16R : B16W;
    const bool   hasb = blockIdx.z != 0;

    const int Kw = K >> 1;
    const int tid  = threadIdx.x;
    const int lane = tid & 31;
    const int wid  = tid >> 5;
    const int warp_m = wid & 3;
    const int warp_n = wid >> 2;
    const int row0 = blockIdx.y * 128;
    const int col0 = blockIdx.x * 64;

    const int grp = lane >> 2;
    const int tig = lane & 3;

    if (tid < 128) { sEs[tid] = 0.f; sEd[tid] = 0.f; }

    float acc[2][4][4];
#pragma unroll
    for (int mt = 0; mt < 2; mt++)
#pragma unroll
        for (int nt = 0; nt < 4; nt++)
#pragma unroll
            for (int i = 0; i < 4; i++) acc[mt][nt][i] = 0.f;

    const int a_row = tid >> 1;
    const int a_wof = (tid & 1) * 4;
    const int b_row = (tid & 127) >> 1;
    const int b_wof = (tid & 1) * 4;
    const bool do_b = tid < 128;

    const int T = K / 16;

    const uint32_t sA_a = (uint32_t)__cvta_generic_to_shared(&sA[0][0]);
    const uint32_t sB_a = (uint32_t)__cvta_generic_to_shared(&sB[0][0]);
    const uint32_t aoff = ((warp_m * 32 + (lane & 15)) * AST + (lane >> 4) * 4) * 4;
    const uint32_t boff = ((warp_n * 32 + (lane & 7) + ((lane >> 4) << 3)) * AST
                          + ((lane >> 3) & 1) * 4) * 4;
    const uint32_t ABUF = 128 * AST * 4;
    const uint32_t BBUF = 64 * AST * 4;
    const uint32_t MTSTEP = 16 * AST * 4;

    auto load_tile = [&](int it, int buf) {
        int gr = row0 + a_row;
        cp_async16u(&sA[buf][a_row * AST + a_wof],
                    &A16[(size_t)gr * Kw + it * 8 + a_wof], gr < Nr);
        if (do_b)
            cp_async16u(&sB[buf][b_row * AST + b_wof],
                        &B[(size_t)(col0 + b_row) * Kw + it * 8 + b_wof], true);
        asm volatile("cp.async.commit_group;\n");
    };

    load_tile(0, 0);
    load_tile(1, 1);

    for (int it = 0; it < T; it++) {
        if (it < T - 1) asm volatile("cp.async.wait_group 1;\n");
        else            asm volatile("cp.async.wait_group 0;\n");
        __syncthreads();
        const uint32_t bufo = (it & 1) ? 1u : 0u;
        const uint32_t ab = sA_a + bufo * ABUF + aoff;
        const uint32_t bb = sB_a + bufo * BBUF + boff;

        uint32_t ah[2][4], bh[4][2];
        ldsm_x4(ah[0][0], ah[0][1], ah[0][2], ah[0][3], ab);
        ldsm_x4(ah[1][0], ah[1][1], ah[1][2], ah[1][3], ab + MTSTEP);
        ldsm_x4(bh[0][0], bh[0][1], bh[1][0], bh[1][1], bb);
        ldsm_x4(bh[2][0], bh[2][1], bh[3][0], bh[3][1], bb + MTSTEP);

#pragma unroll
        for (int nt = 0; nt < 4; nt++)
#pragma unroll
            for (int mt = 0; mt < 2; mt++)
                mma_f16(acc[mt][nt], ah[mt], bh[nt][0], bh[nt][1]);

        __syncthreads();
        if (it + 2 < T) load_tile(it + 2, it & 1);
    }

    // ---- C write ----
#pragma unroll
    for (int mt = 0; mt < 2; mt++) {
        int r = row0 + warp_m * 32 + mt * 16 + grp;
#pragma unroll
        for (int nt = 0; nt < 4; nt++) {
            int c = col0 + warp_n * 32 + nt * 8 + 2 * tig;
            if (hasb) {
                float bx = bias1[c], by = bias1[c + 1];
                if (r < Nr)
                    *(float2*)&C1[(size_t)r * HC + c] =
                        make_float2(acc[mt][nt][0] + bx, acc[mt][nt][1] + by);
                if (r + 8 < Nr)
                    *(float2*)&C1[(size_t)(r + 8) * HC + c] =
                        make_float2(acc[mt][nt][2] + bx, acc[mt][nt][3] + by);
            } else {
                if (r < Nr)
                    Cf16[(size_t)r * (HC / 2) + (c >> 1)] =
                        f2h2(make_float2(acc[mt][nt][0], acc[mt][nt][1]));
                if (r + 8 < Nr)
                    Cf16[(size_t)(r + 8) * (HC / 2) + (c >> 1)] =
                        f2h2(make_float2(acc[mt][nt][2], acc[mt][nt][3]));
            }
        }
    }

    // ---- fused attention dots (feat branch only) ----
    if (blockIdx.z == 0) {
        const int head = blockIdx.x;
        float pes[2][2] = {{0.f, 0.f}, {0.f, 0.f}};
        float ped[2][2] = {{0.f, 0.f}, {0.f, 0.f}};
#pragma unroll
        for (int mt = 0; mt < 2; mt++)
#pragma unroll
            for (int nt = 0; nt < 4; nt++) {
                int cl = warp_n * 32 + nt * 8 + 2 * tig;
                float a0 = asrc[head * CH + cl], a1 = asrc[head * CH + cl + 1];
                float d0 = adst[head * CH + cl], d1 = adst[head * CH + cl + 1];
                pes[mt][0] += acc[mt][nt][0] * a0 + acc[mt][nt][1] * a1;
                pes[mt][1] += acc[mt][nt][2] * a0 + acc[mt][nt][3] * a1;
                ped[mt][0] += acc[mt][nt][0] * d0 + acc[mt][nt][1] * d1;
                ped[mt][1] += acc[mt][nt][2] * d0 + acc[mt][nt][3] * d1;
            }
#pragma unroll
        for (int o = 1; o <= 2; o <<= 1) {
#pragma unroll
            for (int mt = 0; mt < 2; mt++)
#pragma unroll
                for (int hh = 0; hh < 2; hh++) {
                    pes[mt][hh] += __shfl_xor_sync(0xffffffffu, pes[mt][hh], o);
                    ped[mt][hh] += __shfl_xor_sync(0xffffffffu, ped[mt][hh], o);
                }
        }
        if (tig == 0) {
#pragma unroll
            for (int mt = 0; mt < 2; mt++)
#pragma unroll
                for (int hh = 0; hh < 2; hh++) {
                    int lr = warp_m * 32 + mt * 16 + hh * 8 + grp;
                    atomicAdd(&sEs[lr], pes[mt][hh]);
                    atomicAdd(&sEd[lr], ped[mt][hh]);
                }
        }
        __syncthreads();
        if (tid < 128) {
            int node = row0 + tid;
            if (node < Nr) {
                es[node * NH + head] = sEs[tid];
                ed[node * NH + head] = sEd[tid];
            }
        }
    }
}

// ============================================================================
// GAT softmax + aggregate v2: ONE warp per node, all 4 heads.
// Lane l: channels 8l..8l+7 (head = l>>3). Per edge one uint4 (16B fp16).
// Stats per head in 8-lane groups (shfl_xor 1,2,4), online softmax.
// ============================================================================
__global__ __launch_bounds__(256) void agg_kernel(
    const uint32_t* __restrict__ f16, const float* __restrict__ es,
    const float* __restrict__ ed, const float* __restrict__ bias,
    const float* __restrict__ res, float* __restrict__ out)
{
    int node = (blockIdx.x * blockDim.x + threadIdx.x) >> 5;
    int lane = threadIdx.x & 31;
    if (node >= NN) return;
    int head = lane >> 3;
    int j    = lane & 7;
    int s0 = g_rowptr[node], s1 = g_rowptr[node + 1];

    float acc[8];
#pragma unroll
    for (int i = 0; i < 8; i++) acc[i] = 0.f;

    if (s1 > s0) {
        float edv = ed[node * NH + head];
        // per-head online softmax stats (8 lanes stride the edges)
        float m = -INFINITY, den = 0.f;
        for (int k = s0 + j; k < s1; k += 8) {
            int s = g_srcsorted[k];
            float e = es[s * NH + head] + edv;
            e = (e >= 0.f) ? e : SLOPE * e;
            if (e > m) { den = den * __expf(m - e) + 1.f; m = e; }
            else den += __expf(e - m);
        }
#pragma unroll
        for (int o = 1; o <= 4; o <<= 1) {
            float mo  = __shfl_xor_sync(0xffffffffu, m, o);
            float dno = __shfl_xor_sync(0xffffffffu, den, o);
            float nm = fmaxf(m, mo);
            float f1 = (m == nm) ? 1.f : __expf(m - nm);
            float f2 = (mo == nm) ? 1.f : __expf(mo - nm);
            den = den * f1 + dno * f2;
            m = nm;
        }
        float inv = 1.f / (den + 1e-16f);

        // gather: all 32 lanes walk edges together, 2-way unrolled
        int k = s0;
        for (; k + 2 <= s1; k += 2) {
            int sa = g_srcsorted[k];
            int sb = g_srcsorted[k + 1];
            uint4 va = *(const uint4*)&f16[(size_t)sa * (HC / 2) + 4 * lane];
            uint4 vb = *(const uint4*)&f16[(size_t)sb * (HC / 2) + 4 * lane];
            float ea = es[sa * NH + head] + edv;
            float eb = es[sb * NH + head] + edv;
            ea = (ea >= 0.f) ? ea : SLOPE * ea;
            eb = (eb >= 0.f) ? eb : SLOPE * eb;
            float wa = __expf(ea - m) * inv;
            float wb = __expf(eb - m) * inv;
            float2 p;
            p = __half22float2(*(const __half2*)&va.x); acc[0] += wa * p.x; acc[1] += wa * p.y;
            p = __half22float2(*(const __half2*)&va.y); acc[2] += wa * p.x; acc[3] += wa * p.y;
            p = __half22float2(*(const __half2*)&va.z); acc[4] += wa * p.x; acc[5] += wa * p.y;
            p = __half22float2(*(const __half2*)&va.w); acc[6] += wa * p.x; acc[7] += wa * p.y;
            p = __half22float2(*(const __half2*)&vb.x); acc[0] += wb * p.x; acc[1] += wb * p.y;
            p = __half22float2(*(const __half2*)&vb.y); acc[2] += wb * p.x; acc[3] += wb * p.y;
            p = __half22float2(*(const __half2*)&vb.z); acc[4] += wb * p.x; acc[5] += wb * p.y;
            p = __half22float2(*(const __half2*)&vb.w); acc[6] += wb * p.x; acc[7] += wb * p.y;
        }
        if (k < s1) {
            int sa = g_srcsorted[k];
            uint4 va = *(const uint4*)&f16[(size_t)sa * (HC / 2) + 4 * lane];
            float ea = es[sa * NH + head] + edv;
            ea = (ea >= 0.f) ? ea : SLOPE * ea;
            float wa = __expf(ea - m) * inv;
            float2 p;
            p = __half22float2(*(const __half2*)&va.x); acc[0] += wa * p.x; acc[1] += wa * p.y;
            p = __half22float2(*(const __half2*)&va.y); acc[2] += wa * p.x; acc[3] += wa * p.y;
            p = __half22float2(*(const __half2*)&va.z); acc[4] += wa * p.x; acc[5] += wa * p.y;
            p = __half22float2(*(const __half2*)&va.w); acc[6] += wa * p.x; acc[7] += wa * p.y;
        }
    }

    int cb = 8 * lane;
    const float4* bi = (const float4*)&bias[cb];
    const float4* rv = (const float4*)&res[(size_t)node * HC + cb];
    float4 o0, o1;
    float4 b0 = bi[0], b1 = bi[1], r0 = rv[0], r1 = rv[1];
    o0.x = acc[0] + b0.x + r0.x; o0.y = acc[1] + b0.y + r0.y;
    o0.z = acc[2] + b0.z + r0.z; o0.w = acc[3] + b0.w + r0.w;
    o1.x = acc[4] + b1.x + r1.x; o1.y = acc[5] + b1.y + r1.y;
    o1.z = acc[6] + b1.z + r1.z; o1.w = acc[7] + b1.w + r1.w;
    ((float4*)&out[(size_t)node * HC + cb])[0] = o0;
    ((float4*)&out[(size_t)node * HC + cb])[1] = o1;
}

// ---------------- BatchNorm ----------------
__global__ __launch_bounds__(256) void bn_stats_kernel(const float* __restrict__ x) {
    int chn = threadIdx.x;
    int r0 = blockIdx.x * 64;
    int r1 = min(r0 + 64, NN);
    float s = 0.f, q = 0.f;
    for (int r = r0; r < r1; r++) {
        float v = x[(size_t)r * HC + chn];
        s += v; q += v * v;
    }
    atomicAdd(&g_bnacc[chn], s);
    atomicAdd(&g_bnacc[chn + HC], q);
}

__global__ void bn_finalize_kernel(const float* __restrict__ gma, const float* __restrict__ beta) {
    int c = threadIdx.x;
    float mean = g_bnacc[c] / (float)NN;
    float var  = g_bnacc[c + HC] / (float)NN - mean * mean;
    float a = gma[c] * rsqrtf(var + EPSBN);
    g_bnA[c] = a;
    g_bnB[c] = beta[c] - mean * a;
}

__global__ __launch_bounds__(256) void bn_apply_kernel(float* __restrict__ x) {
    int i = blockIdx.x * blockDim.x + threadIdx.x;
    if (i >= NN * HC / 4) return;
    float4 v = ((const float4*)x)[i];
    int c = (i * 4) & 255;
    v.x = fmaxf(v.x * g_bnA[c + 0] + g_bnB[c + 0], 0.f);
    v.y = fmaxf(v.y * g_bnA[c + 1] + g_bnB[c + 1], 0.f);
    v.z = fmaxf(v.z * g_bnA[c + 2] + g_bnB[c + 2], 0.f);
    v.w = fmaxf(v.w * g_bnA[c + 3] + g_bnB[c + 3], 0.f);
    ((float4*)x)[i] = v;
}

// ---------------- pooling (atomic-free; batch is sorted) ----------------
__global__ __launch_bounds__(256) void pool_kernel(const float* __restrict__ act,
                                                   const int* __restrict__ batch) {
    __shared__ int s_lo, s_hi;
    int g = blockIdx.x;
    int t = threadIdx.x;
    if (t == 0) {
        int lo = 0, hi = NN;
        while (lo < hi) { int mid = (lo + hi) >> 1; if (batch[mid] < g) lo = mid + 1; else hi = mid; }
        s_lo = lo;
        int lo2 = lo; hi = NN;
        while (lo2 < hi) { int mid = (lo2 + hi) >> 1; if (batch[mid] < g + 1) lo2 = mid + 1; else hi = mid; }
        s_hi = lo2;
    }
    __syncthreads();
    int lo = s_lo, hi = s_hi;
    float s = 0.f;
    for (int r = lo; r < hi; r++) s += act[(size_t)r * HC + t];
    float inv = (hi > lo) ? 1.0f / (float)(hi - lo) : 0.0f;
    g_pooled[(size_t)g * HC + t] = s * inv;
}

// ---------------- graph-level MLP ----------------
__global__ __launch_bounds__(128) void mlp_kernel(
    const float* __restrict__ fc1W, const float* __restrict__ fc1b,
    const float* __restrict__ fc2W, const float* __restrict__ fc2b,
    float* __restrict__ out)
{
    __shared__ float row[HC];
    __shared__ float red[128];
    int g = blockIdx.x, t = threadIdx.x;
    row[t]       = g_pooled[(size_t)g * HC + t];
    row[t + 128] = g_pooled[(size_t)g * HC + t + 128];
    __syncthreads();
    float a = fc1b[t];
#pragma unroll 8
    for (int k = 0; k < HC; k++) a += row[k] * fc1W[k * 128 + t];
    a = fmaxf(a, 0.f);
    for (int j = 0; j < 2; j++) {
        red[t] = a * fc2W[t * 2 + j];
        __syncthreads();
        for (int off = 64; off; off >>= 1) {
            if (t < off) red[t] += red[t + off];
            __syncthreads();
        }
        if (t == 0) out[g * 2 + j] = red[0] + fc2b[j];
        __syncthreads();
    }
}

// ---------------- host side ----------------
static void* symp(const void* sym) {
    void* p = nullptr;
    cudaGetSymbolAddress(&p, sym);
    return p;
}

extern "C" void kernel_launch(void* const* d_in, const int* in_sizes, int n_in,
                              void* d_out, int out_size)
{
    const float* x        = (const float*)d_in[0];
    const int*   edge_idx = (const int*)  d_in[1];
    const int*   batch    = (const int*)  d_in[3];
    const float* W1       = (const float*)d_in[4];
    const float* asrc1    = (const float*)d_in[5];
    const float* adst1    = (const float*)d_in[6];
    const float* b1       = (const float*)d_in[7];
    const float* res1W    = (const float*)d_in[8];
    const float* res1b    = (const float*)d_in[9];
    const float* bn1g     = (const float*)d_in[10];
    const float* bn1b     = (const float*)d_in[11];
    const float* W2       = (const float*)d_in[12];
    const float* asrc2    = (const float*)d_in[13];
    const float* adst2    = (const float*)d_in[14];
    const float* b2       = (const float*)d_in[15];
    const float* res2W    = (const float*)d_in[16];
    const float* res2b    = (const float*)d_in[17];
    const float* bn2g     = (const float*)d_in[18];
    const float* bn2b     = (const float*)d_in[19];
    const float* fc1W     = (const float*)d_in[20];
    const float* fc1b     = (const float*)d_in[21];
    const float* fc2W     = (const float*)d_in[22];
    const float* fc2b     = (const float*)d_in[23];
    float* out = (float*)d_out;

    uint32_t* f16 = (uint32_t*)symp(g_f16);
    float* res   = (float*)symp(g_res);
    float* act   = (float*)symp(g_act);
    float* es    = (float*)symp(g_es);
    float* ed    = (float*)symp(g_ed);
    int*   rowp  = (int*)  symp(g_rowptr);
    int*   curs  = (int*)  symp(g_cursor);
    int*   bsum  = (int*)  symp(g_blocksums);
    int*   boff  = (int*)  symp(g_blockoff);
    float* bnacc = (float*)symp(g_bnacc);
    uint32_t* x16  = (uint32_t*)symp(g_x16);
    uint32_t* a216 = (uint32_t*)symp(g_a216);
    uint32_t* w116 = (uint32_t*)symp(g_w116), *r116 = (uint32_t*)symp(g_r116);
    uint32_t* w216 = (uint32_t*)symp(g_w216), *r216 = (uint32_t*)symp(g_r216);

    const int NB = (NN + 255) / 256;
    const int EB = (EE + 255) / 256;
    const int NODEWARP_BLKS = (NN * 32 + 255) / 256;   // 6250
    dim3 gemm_grid(HC / 64, (NN + 127) / 128, 2);
    const int W1W = HC * DIN / 2, W2W = HC * HC / 2;

    // ---- prep (gemm L1 lands at launch idx 3 for the ncu capture) ----
    cvt16_f4_kernel<<<(NN * DIN / 4 + 255) / 256, 256>>>(x, x16, NN * DIN / 4);        // 0
    wcvt2_kernel<<<dim3((W1W + 255) / 256, 2), 256>>>(W1, res1W, w116, r116, DIN);     // 1
    zero_int_kernel<<<NB, 256>>>(curs, NN);                                            // 2

    gemm16_kernel<<<gemm_grid, 256>>>(x16, w116, r116, res1b,
                                      asrc1, adst1, f16, res, es, ed,
                                      NN, DIN);                                        // 3 <- profiled

    // ---- CSR build ----
    count_deg_kernel<<<EB, 256>>>(edge_idx);
    scan_block_kernel<<<NB, 256>>>(curs, rowp, bsum, NN);
    scan_block_kernel<<<1, 256>>>(bsum, boff, nullptr, NB);
    scan_add_kernel<<<NB, 256>>>(rowp, boff, NN);
    copy_int_kernel<<<NB, 256>>>(curs, rowp, NN);
    fill_csr_kernel<<<EB, 256>>>(edge_idx);

    // ---- layer 1 rest ----
    agg_kernel<<<NODEWARP_BLKS, 256>>>(f16, es, ed, b1, res, act);
    zero_float_kernel<<<2, 256>>>(bnacc, 2 * HC);
    bn_stats_kernel<<<(NN + 63) / 64, 256>>>(act);
    bn_finalize_kernel<<<1, HC>>>(bn1g, bn1b);
    bn_apply_cvt_kernel<<<(NN * HC / 4 + 255) / 256, 256>>>(act, a216);

    // ---- layer 2 ----
    wcvt2_kernel<<<dim3((W2W + 255) / 256, 2), 256>>>(W2, res2W, w216, r216, HC);
    gemm16_kernel<<<gemm_grid, 256>>>(a216, w216, r216, res2b,
                                      asrc2, adst2, f16, res, es, ed,
                                      NN, HC);
    agg_kernel<<<NODEWARP_BLKS, 256>>>(f16, es, ed, b2, res, act);
    zero_float_kernel<<<2, 256>>>(bnacc, 2 * HC);
    bn_stats_kernel<<<(NN + 63) / 64, 256>>>(act);
    bn_finalize_kernel<<<1, HC>>>(bn2g, bn2b);
    bn_apply_kernel<<<(NN * HC / 4 + 255) / 256, 256>>>(act);

    // ---- pooling + MLP ----
    pool_kernel<<<NG, 256>>>(act, batch);
    mlp_kernel<<<NG, 128>>>(fc1W, fc1b, fc2W, fc2b, out);
}

// round 11
// speedup vs baseline: 1.9291x; 1.0713x over previous
#include <cuda_runtime.h>
#include <cuda_fp16.h>
#include <cstdint>

#define NN 50000
#define EE 800000
#define DIN 128
#define NH 4
#define CH 64
#define HC 256
#define NG 512
#define EPSBN 1e-5f
#define SLOPE 0.2f

// ---------------- scratch ----------------
__device__ uint32_t g_f16[(size_t)NN * HC / 2];   // feat fp16x2 (gather source)
__device__ uint32_t g_res16[(size_t)NN * HC / 2]; // residual fp16x2
__device__ float g_act [(size_t)NN * HC];
__device__ float g_es[NN * NH];
__device__ float g_ed[NN * NH];
__device__ int   g_rowptr[NN + 1];
__device__ int   g_cursor[NN];
__device__ int   g_srcsorted[EE];
__device__ int   g_blocksums[256];
__device__ int   g_blockoff[256];
__device__ float g_bnacc[2 * HC];
__device__ float g_bnA[HC];
__device__ float g_bnB[HC];
__device__ float g_pooled[NG * HC];
// fp16 GEMM operand buffers
__device__ uint32_t g_x16[(size_t)NN * DIN / 2];
__device__ uint32_t g_a216[(size_t)NN * HC / 2];
__device__ uint32_t g_w116[HC * DIN / 2], g_r116[HC * DIN / 2];
__device__ uint32_t g_w216[HC * HC / 2],  g_r216[HC * HC / 2];

__device__ __forceinline__ uint32_t f2h2(float2 v) {
    uint32_t r;
    asm("cvt.rn.f16x2.f32 %0, %1, %2;" : "=r"(r) : "f"(v.y), "f"(v.x));
    return r;
}

// ---------------- tiny utility kernels ----------------
__global__ void zero_float_kernel(float* p, int n) {
    int i = blockIdx.x * blockDim.x + threadIdx.x;
    if (i < n) p[i] = 0.0f;
}
__global__ void zero_int_kernel(int* p, int n) {
    int i = blockIdx.x * blockDim.x + threadIdx.x;
    if (i < n) p[i] = 0;
}
__global__ void copy_int_kernel(int* dst, const int* src, int n) {
    int i = blockIdx.x * blockDim.x + threadIdx.x;
    if (i < n) dst[i] = src[i];
}

// ---------------- prep: fp32 -> fp16 conversions ----------------
__global__ void cvt16_f4_kernel(const float* __restrict__ src,
                                uint32_t* __restrict__ dst, int n4) {
    int i = blockIdx.x * blockDim.x + threadIdx.x;
    if (i >= n4) return;
    float4 v = ((const float4*)src)[i];
    dst[2 * i]     = f2h2(make_float2(v.x, v.y));
    dst[2 * i + 1] = f2h2(make_float2(v.z, v.w));
}

__global__ void wcvt2_kernel(const float* __restrict__ W0, const float* __restrict__ W1,
                             uint32_t* __restrict__ t0, uint32_t* __restrict__ t1,
                             int Kd) {
    const float* W = blockIdx.y ? W1 : W0;
    uint32_t* th = blockIdx.y ? t1 : t0;
    int idx = blockIdx.x * blockDim.x + threadIdx.x;
    int kw = Kd >> 1;
    if (idx >= HC * kw) return;
    int n = idx / kw, kp = idx % kw;
    float a = W[(size_t)(2 * kp) * HC + n];
    float b = W[(size_t)(2 * kp + 1) * HC + n];
    th[idx] = f2h2(make_float2(a, b));
}

__global__ __launch_bounds__(256) void bn_apply_cvt_kernel(const float* __restrict__ x,
                                                           uint32_t* __restrict__ dh) {
    int i = blockIdx.x * blockDim.x + threadIdx.x;
    if (i >= NN * HC / 4) return;
    float4 v = ((const float4*)x)[i];
    int c = (i * 4) & 255;
    v.x = fmaxf(v.x * g_bnA[c + 0] + g_bnB[c + 0], 0.f);
    v.y = fmaxf(v.y * g_bnA[c + 1] + g_bnB[c + 1], 0.f);
    v.z = fmaxf(v.z * g_bnA[c + 2] + g_bnB[c + 2], 0.f);
    v.w = fmaxf(v.w * g_bnA[c + 3] + g_bnB[c + 3], 0.f);
    dh[2 * i]     = f2h2(make_float2(v.x, v.y));
    dh[2 * i + 1] = f2h2(make_float2(v.z, v.w));
}

// ---------------- CSR build ----------------
__global__ void count_deg_kernel(const int* __restrict__ ei) {
    int e = blockIdx.x * blockDim.x + threadIdx.x;
    if (e >= EE) return;
    atomicAdd(&g_cursor[ei[EE + e]], 1);
}

__global__ void scan_block_kernel(const int* __restrict__ in, int* __restrict__ out,
                                  int* __restrict__ blocksums, int n) {
    __shared__ int sh[256];
    int tid = threadIdx.x;
    int i = blockIdx.x * 256 + tid;
    int v = (i < n) ? in[i] : 0;
    sh[tid] = v;
    __syncthreads();
    for (int off = 1; off < 256; off <<= 1) {
        int t = (tid >= off) ? sh[tid - off] : 0;
        __syncthreads();
        sh[tid] += t;
        __syncthreads();
    }
    if (i < n) out[i] = sh[tid] - v;
    if (tid == 255 && blocksums) blocksums[blockIdx.x] = sh[255];
}

__global__ void scan_add_kernel(int* __restrict__ rowptr, const int* __restrict__ blockoff, int n) {
    int i = blockIdx.x * 256 + threadIdx.x;
    if (i < n) rowptr[i] += blockoff[blockIdx.x];
    if (blockIdx.x == 0 && threadIdx.x == 0) rowptr[n] = EE;
}

__global__ void fill_csr_kernel(const int* __restrict__ ei) {
    int e = blockIdx.x * blockDim.x + threadIdx.x;
    if (e >= EE) return;
    int s = ei[e];
    int d = ei[EE + e];
    int pos = atomicAdd(&g_cursor[d], 1);
    g_srcsorted[pos] = s;
}

// ============================================================================
// Merged-branch fp16 GEMM: one block computes BOTH the W-product (feat, fp16
// out + fused dots) and the residual product (fp16 out + bias) for its
// 128x64 tile, reusing A fragments in registers. grid (4, 391).
// ============================================================================
#define AST 12

__device__ __forceinline__ void mma_f16(float* d, const uint32_t* a,
                                        uint32_t b0, uint32_t b1) {
    asm volatile(
        "mma.sync.aligned.m16n8k16.row.col.f32.f16.f16.f32 "
        "{%0,%1,%2,%3}, {%4,%5,%6,%7}, {%8,%9}, {%0,%1,%2,%3};\n"
        : "+f"(d[0]), "+f"(d[1]), "+f"(d[2]), "+f"(d[3])
        : "r"(a[0]), "r"(a[1]), "r"(a[2]), "r"(a[3]), "r"(b0), "r"(b1));
}

__device__ __forceinline__ void ldsm_x4(uint32_t& r0, uint32_t& r1,
                                        uint32_t& r2, uint32_t& r3, uint32_t saddr) {
    asm volatile("ldmatrix.sync.aligned.m8n8.x4.shared.b16 {%0,%1,%2,%3}, [%4];"
                 : "=r"(r0), "=r"(r1), "=r"(r2), "=r"(r3) : "r"(saddr));
}

__device__ __forceinline__ void cp_async16u(uint32_t* smem_ptr, const uint32_t* gptr, bool pred) {
    uint32_t sa = (uint32_t)__cvta_generic_to_shared(smem_ptr);
    int bytes = pred ? 16 : 0;
    asm volatile("cp.async.ca.shared.global [%0], [%1], 16, %2;\n"
                 :: "r"(sa), "l"(gptr), "r"(bytes));
}

__global__ __launch_bounds__(256, 2) void gemm16_kernel(
    const uint32_t* __restrict__ A16,
    const uint32_t* __restrict__ B16W, const uint32_t* __restrict__ B16R,
    const float* __restrict__ biasR,
    const float* __restrict__ asrc, const float* __restrict__ adst,
    uint32_t* __restrict__ Cf16, uint32_t* __restrict__ Cr16,
    float* __restrict__ es, float* __restrict__ ed,
    int Nr, int K)
{
    __shared__ uint32_t sA[2][128 * AST];
    __shared__ uint32_t sBW[2][64 * AST];
    __shared__ uint32_t sBR[2][64 * AST];
    __shared__ float sEs[128], sEd[128];

    const int Kw = K >> 1;
    const int tid  = threadIdx.x;
    const int lane = tid & 31;
    const int wid  = tid >> 5;
    const int warp_m = wid & 3;
    const int warp_n = wid >> 2;
    const int row0 = blockIdx.y * 128;
    const int col0 = blockIdx.x * 64;

    const int grp = lane >> 2;
    const int tig = lane & 3;

    if (tid < 128) { sEs[tid] = 0.f; sEd[tid] = 0.f; }

    float accW[2][4][4], accR[2][4][4];
#pragma unroll
    for (int mt = 0; mt < 2; mt++)
#pragma unroll
        for (int nt = 0; nt < 4; nt++)
#pragma unroll
            for (int i = 0; i < 4; i++) { accW[mt][nt][i] = 0.f; accR[mt][nt][i] = 0.f; }

    const int a_row = tid >> 1;
    const int a_wof = (tid & 1) * 4;
    const int b_row = (tid & 127) >> 1;
    const int b_wof = (tid & 1) * 4;
    const bool loadW = tid < 128;

    const int T = K / 16;

    const uint32_t sA_a  = (uint32_t)__cvta_generic_to_shared(&sA[0][0]);
    const uint32_t sBW_a = (uint32_t)__cvta_generic_to_shared(&sBW[0][0]);
    const uint32_t sBR_a = (uint32_t)__cvta_generic_to_shared(&sBR[0][0]);
    const uint32_t aoff = ((warp_m * 32 + (lane & 15)) * AST + (lane >> 4) * 4) * 4;
    const uint32_t boff = ((warp_n * 32 + (lane & 7) + ((lane >> 4) << 3)) * AST
                          + ((lane >> 3) & 1) * 4) * 4;
    const uint32_t ABUF = 128 * AST * 4;
    const uint32_t BBUF = 64 * AST * 4;
    const uint32_t MTSTEP = 16 * AST * 4;

    auto load_tile = [&](int it, int buf) {
        int gr = row0 + a_row;
        cp_async16u(&sA[buf][a_row * AST + a_wof],
                    &A16[(size_t)gr * Kw + it * 8 + a_wof], gr < Nr);
        if (loadW)
            cp_async16u(&sBW[buf][b_row * AST + b_wof],
                        &B16W[(size_t)(col0 + b_row) * Kw + it * 8 + b_wof], true);
        else
            cp_async16u(&sBR[buf][b_row * AST + b_wof],
                        &B16R[(size_t)(col0 + b_row) * Kw + it * 8 + b_wof], true);
        asm volatile("cp.async.commit_group;\n");
    };

    load_tile(0, 0);
    load_tile(1, 1);

    for (int it = 0; it < T; it++) {
        if (it < T - 1) asm volatile("cp.async.wait_group 1;\n");
        else            asm volatile("cp.async.wait_group 0;\n");
        __syncthreads();
        const uint32_t bufo = (it & 1) ? 1u : 0u;
        const uint32_t ab  = sA_a  + bufo * ABUF + aoff;
        const uint32_t bbw = sBW_a + bufo * BBUF + boff;
        const uint32_t bbr = sBR_a + bufo * BBUF + boff;

        uint32_t ah[2][4], bh[4][2];
        ldsm_x4(ah[0][0], ah[0][1], ah[0][2], ah[0][3], ab);
        ldsm_x4(ah[1][0], ah[1][1], ah[1][2], ah[1][3], ab + MTSTEP);

        // W branch
        ldsm_x4(bh[0][0], bh[0][1], bh[1][0], bh[1][1], bbw);
        ldsm_x4(bh[2][0], bh[2][1], bh[3][0], bh[3][1], bbw + MTSTEP);
#pragma unroll
        for (int nt = 0; nt < 4; nt++)
#pragma unroll
            for (int mt = 0; mt < 2; mt++)
                mma_f16(accW[mt][nt], ah[mt], bh[nt][0], bh[nt][1]);

        // residual branch (reuse A fragments)
        ldsm_x4(bh[0][0], bh[0][1], bh[1][0], bh[1][1], bbr);
        ldsm_x4(bh[2][0], bh[2][1], bh[3][0], bh[3][1], bbr + MTSTEP);
#pragma unroll
        for (int nt = 0; nt < 4; nt++)
#pragma unroll
            for (int mt = 0; mt < 2; mt++)
                mma_f16(accR[mt][nt], ah[mt], bh[nt][0], bh[nt][1]);

        __syncthreads();
        if (it + 2 < T) load_tile(it + 2, it & 1);
    }

    // ---- C writes (both fp16) ----
#pragma unroll
    for (int mt = 0; mt < 2; mt++) {
        int r = row0 + warp_m * 32 + mt * 16 + grp;
#pragma unroll
        for (int nt = 0; nt < 4; nt++) {
            int c = col0 + warp_n * 32 + nt * 8 + 2 * tig;
            float bx = biasR[c], by = biasR[c + 1];
            if (r < Nr) {
                Cf16[(size_t)r * (HC / 2) + (c >> 1)] =
                    f2h2(make_float2(accW[mt][nt][0], accW[mt][nt][1]));
                Cr16[(size_t)r * (HC / 2) + (c >> 1)] =
                    f2h2(make_float2(accR[mt][nt][0] + bx, accR[mt][nt][1] + by));
            }
            if (r + 8 < Nr) {
                Cf16[(size_t)(r + 8) * (HC / 2) + (c >> 1)] =
                    f2h2(make_float2(accW[mt][nt][2], accW[mt][nt][3]));
                Cr16[(size_t)(r + 8) * (HC / 2) + (c >> 1)] =
                    f2h2(make_float2(accR[mt][nt][2] + bx, accR[mt][nt][3] + by));
            }
        }
    }

    // ---- fused attention dots (from accW) ----
    {
        const int head = blockIdx.x;
        float pes[2][2] = {{0.f, 0.f}, {0.f, 0.f}};
        float ped[2][2] = {{0.f, 0.f}, {0.f, 0.f}};
#pragma unroll
        for (int mt = 0; mt < 2; mt++)
#pragma unroll
            for (int nt = 0; nt < 4; nt++) {
                int cl = warp_n * 32 + nt * 8 + 2 * tig;
                float a0 = asrc[head * CH + cl], a1 = asrc[head * CH + cl + 1];
                float d0 = adst[head * CH + cl], d1 = adst[head * CH + cl + 1];
                pes[mt][0] += accW[mt][nt][0] * a0 + accW[mt][nt][1] * a1;
                pes[mt][1] += accW[mt][nt][2] * a0 + accW[mt][nt][3] * a1;
                ped[mt][0] += accW[mt][nt][0] * d0 + accW[mt][nt][1] * d1;
                ped[mt][1] += accW[mt][nt][2] * d0 + accW[mt][nt][3] * d1;
            }
#pragma unroll
        for (int o = 1; o <= 2; o <<= 1) {
#pragma unroll
            for (int mt = 0; mt < 2; mt++)
#pragma unroll
                for (int hh = 0; hh < 2; hh++) {
                    pes[mt][hh] += __shfl_xor_sync(0xffffffffu, pes[mt][hh], o);
                    ped[mt][hh] += __shfl_xor_sync(0xffffffffu, ped[mt][hh], o);
                }
        }
        if (tig == 0) {
#pragma unroll
            for (int mt = 0; mt < 2; mt++)
#pragma unroll
                for (int hh = 0; hh < 2; hh++) {
                    int lr = warp_m * 32 + mt * 16 + hh * 8 + grp;
                    atomicAdd(&sEs[lr], pes[mt][hh]);
                    atomicAdd(&sEd[lr], ped[mt][hh]);
                }
        }
        __syncthreads();
        if (tid < 128) {
            int node = row0 + tid;
            if (node < Nr) {
                es[node * NH + head] = sEs[tid];
                ed[node * NH + head] = sEd[tid];
            }
        }
    }
}

// ============================================================================
// GAT softmax + aggregate: one warp per node, all 4 heads.
// Lane l: channels 8l..8l+7 (head = l>>3). res in fp16.
// ============================================================================
__global__ __launch_bounds__(256) void agg_kernel(
    const uint32_t* __restrict__ f16, const float* __restrict__ es,
    const float* __restrict__ ed,
    const uint32_t* __restrict__ res16, float* __restrict__ out)
{
    int node = (blockIdx.x * blockDim.x + threadIdx.x) >> 5;
    int lane = threadIdx.x & 31;
    if (node >= NN) return;
    int head = lane >> 3;
    int j    = lane & 7;
    int s0 = g_rowptr[node], s1 = g_rowptr[node + 1];

    float acc[8];
#pragma unroll
    for (int i = 0; i < 8; i++) acc[i] = 0.f;

    if (s1 > s0) {
        float edv = ed[node * NH + head];
        float m = -INFINITY, den = 0.f;
        for (int k = s0 + j; k < s1; k += 8) {
            int s = g_srcsorted[k];
            float e = es[s * NH + head] + edv;
            e = (e >= 0.f) ? e : SLOPE * e;
            if (e > m) { den = den * __expf(m - e) + 1.f; m = e; }
            else den += __expf(e - m);
        }
#pragma unroll
        for (int o = 1; o <= 4; o <<= 1) {
            float mo  = __shfl_xor_sync(0xffffffffu, m, o);
            float dno = __shfl_xor_sync(0xffffffffu, den, o);
            float nm = fmaxf(m, mo);
            float f1 = (m == nm) ? 1.f : __expf(m - nm);
            float f2 = (mo == nm) ? 1.f : __expf(mo - nm);
            den = den * f1 + dno * f2;
            m = nm;
        }
        float inv = 1.f / (den + 1e-16f);

        int k = s0;
        for (; k + 2 <= s1; k += 2) {
            int sa = g_srcsorted[k];
            int sb = g_srcsorted[k + 1];
            uint4 va = *(const uint4*)&f16[(size_t)sa * (HC / 2) + 4 * lane];
            uint4 vb = *(const uint4*)&f16[(size_t)sb * (HC / 2) + 4 * lane];
            float ea = es[sa * NH + head] + edv;
            float eb = es[sb * NH + head] + edv;
            ea = (ea >= 0.f) ? ea : SLOPE * ea;
            eb = (eb >= 0.f) ? eb : SLOPE * eb;
            float wa = __expf(ea - m) * inv;
            float wb = __expf(eb - m) * inv;
            float2 p;
            p = __half22float2(*(const __half2*)&va.x); acc[0] += wa * p.x; acc[1] += wa * p.y;
            p = __half22float2(*(const __half2*)&va.y); acc[2] += wa * p.x; acc[3] += wa * p.y;
            p = __half22float2(*(const __half2*)&va.z); acc[4] += wa * p.x; acc[5] += wa * p.y;
            p = __half22float2(*(const __half2*)&va.w); acc[6] += wa * p.x; acc[7] += wa * p.y;
            p = __half22float2(*(const __half2*)&vb.x); acc[0] += wb * p.x; acc[1] += wb * p.y;
            p = __half22float2(*(const __half2*)&vb.y); acc[2] += wb * p.x; acc[3] += wb * p.y;
            p = __half22float2(*(const __half2*)&vb.z); acc[4] += wb * p.x; acc[5] += wb * p.y;
            p = __half22float2(*(const __half2*)&vb.w); acc[6] += wb * p.x; acc[7] += wb * p.y;
        }
        if (k < s1) {
            int sa = g_srcsorted[k];
            uint4 va = *(const uint4*)&f16[(size_t)sa * (HC / 2) + 4 * lane];
            float ea = es[sa * NH + head] + edv;
            ea = (ea >= 0.f) ? ea : SLOPE * ea;
            float wa = __expf(ea - m) * inv;
            float2 p;
            p = __half22float2(*(const __half2*)&va.x); acc[0] += wa * p.x; acc[1] += wa * p.y;
            p = __half22float2(*(const __half2*)&va.y); acc[2] += wa * p.x; acc[3] += wa * p.y;
            p = __half22float2(*(const __half2*)&va.z); acc[4] += wa * p.x; acc[5] += wa * p.y;
            p = __half22float2(*(const __half2*)&va.w); acc[6] += wa * p.x; acc[7] += wa * p.y;
        }
    }

    int cb = 8 * lane;
    uint4 rv = *(const uint4*)&res16[(size_t)node * (HC / 2) + 4 * lane];
    float2 r0 = __half22float2(*(const __half2*)&rv.x);
    float2 r1 = __half22float2(*(const __half2*)&rv.y);
    float2 r2 = __half22float2(*(const __half2*)&rv.z);
    float2 r3 = __half22float2(*(const __half2*)&rv.w);
    float4 o0, o1;
    o0.x = acc[0] + r0.x; o0.y = acc[1] + r0.y;
    o0.z = acc[2] + r1.x; o0.w = acc[3] + r1.y;
    o1.x = acc[4] + r2.x; o1.y = acc[5] + r2.y;
    o1.z = acc[6] + r3.x; o1.w = acc[7] + r3.y;
    ((float4*)&out[(size_t)node * HC + cb])[0] = o0;
    ((float4*)&out[(size_t)node * HC + cb])[1] = o1;
}

// ---------------- BatchNorm ----------------
__global__ __launch_bounds__(256) void bn_stats_kernel(const float* __restrict__ x) {
    int chn = threadIdx.x;
    int r0 = blockIdx.x * 64;
    int r1 = min(r0 + 64, NN);
    float s = 0.f, q = 0.f;
    for (int r = r0; r < r1; r++) {
        float v = x[(size_t)r * HC + chn];
        s += v; q += v * v;
    }
    atomicAdd(&g_bnacc[chn], s);
    atomicAdd(&g_bnacc[chn + HC], q);
}

__global__ void bn_finalize_kernel(const float* __restrict__ gma, const float* __restrict__ beta) {
    int c = threadIdx.x;
    float mean = g_bnacc[c] / (float)NN;
    float var  = g_bnacc[c + HC] / (float)NN - mean * mean;
    float a = gma[c] * rsqrtf(var + EPSBN);
    g_bnA[c] = a;
    g_bnB[c] = beta[c] - mean * a;
}

__global__ __launch_bounds__(256) void bn_apply_kernel(float* __restrict__ x) {
    int i = blockIdx.x * blockDim.x + threadIdx.x;
    if (i >= NN * HC / 4) return;
    float4 v = ((const float4*)x)[i];
    int c = (i * 4) & 255;
    v.x = fmaxf(v.x * g_bnA[c + 0] + g_bnB[c + 0], 0.f);
    v.y = fmaxf(v.y * g_bnA[c + 1] + g_bnB[c + 1], 0.f);
    v.z = fmaxf(v.z * g_bnA[c + 2] + g_bnB[c + 2], 0.f);
    v.w = fmaxf(v.w * g_bnA[c + 3] + g_bnB[c + 3], 0.f);
    ((float4*)x)[i] = v;
}

// ---------------- pooling (atomic-free; batch is sorted) ----------------
__global__ __launch_bounds__(256) void pool_kernel(const float* __restrict__ act,
                                                   const int* __restrict__ batch) {
    __shared__ int s_lo, s_hi;
    int g = blockIdx.x;
    int t = threadIdx.x;
    if (t == 0) {
        int lo = 0, hi = NN;
        while (lo < hi) { int mid = (lo + hi) >> 1; if (batch[mid] < g) lo = mid + 1; else hi = mid; }
        s_lo = lo;
        int lo2 = lo; hi = NN;
        while (lo2 < hi) { int mid = (lo2 + hi) >> 1; if (batch[mid] < g + 1) lo2 = mid + 1; else hi = mid; }
        s_hi = lo2;
    }
    __syncthreads();
    int lo = s_lo, hi = s_hi;
    float s = 0.f;
    for (int r = lo; r < hi; r++) s += act[(size_t)r * HC + t];
    float inv = (hi > lo) ? 1.0f / (float)(hi - lo) : 0.0f;
    g_pooled[(size_t)g * HC + t] = s * inv;
}

// ---------------- graph-level MLP ----------------
__global__ __launch_bounds__(128) void mlp_kernel(
    const float* __restrict__ fc1W, const float* __restrict__ fc1b,
    const float* __restrict__ fc2W, const float* __restrict__ fc2b,
    float* __restrict__ out)
{
    __shared__ float row[HC];
    __shared__ float red[128];
    int g = blockIdx.x, t = threadIdx.x;
    row[t]       = g_pooled[(size_t)g * HC + t];
    row[t + 128] = g_pooled[(size_t)g * HC + t + 128];
    __syncthreads();
    float a = fc1b[t];
#pragma unroll 8
    for (int k = 0; k < HC; k++) a += row[k] * fc1W[k * 128 + t];
    a = fmaxf(a, 0.f);
    for (int j = 0; j < 2; j++) {
        red[t] = a * fc2W[t * 2 + j];
        __syncthreads();
        for (int off = 64; off; off >>= 1) {
            if (t < off) red[t] += red[t + off];
            __syncthreads();
        }
        if (t == 0) out[g * 2 + j] = red[0] + fc2b[j];
        __syncthreads();
    }
}

// ---------------- host side ----------------
static void* symp(const void* sym) {
    void* p = nullptr;
    cudaGetSymbolAddress(&p, sym);
    return p;
}

extern "C" void kernel_launch(void* const* d_in, const int* in_sizes, int n_in,
                              void* d_out, int out_size)
{
    const float* x        = (const float*)d_in[0];
    const int*   edge_idx = (const int*)  d_in[1];
    const int*   batch    = (const int*)  d_in[3];
    const float* W1       = (const float*)d_in[4];
    const float* asrc1    = (const float*)d_in[5];
    const float* adst1    = (const float*)d_in[6];
    const float* b1       = (const float*)d_in[7];
    const float* res1W    = (const float*)d_in[8];
    const float* res1b    = (const float*)d_in[9];
    const float* bn1g     = (const float*)d_in[10];
    const float* bn1b     = (const float*)d_in[11];
    const float* W2       = (const float*)d_in[12];
    const float* asrc2    = (const float*)d_in[13];
    const float* adst2    = (const float*)d_in[14];
    const float* b2       = (const float*)d_in[15];
    const float* res2W    = (const float*)d_in[16];
    const float* res2b    = (const float*)d_in[17];
    const float* bn2g     = (const float*)d_in[18];
    const float* bn2b     = (const float*)d_in[19];
    const float* fc1W     = (const float*)d_in[20];
    const float* fc1b     = (const float*)d_in[21];
    const float* fc2W     = (const float*)d_in[22];
    const float* fc2b     = (const float*)d_in[23];
    float* out = (float*)d_out;

    uint32_t* f16  = (uint32_t*)symp(g_f16);
    uint32_t* res16= (uint32_t*)symp(g_res16);
    float* act   = (float*)symp(g_act);
    float* es    = (float*)symp(g_es);
    float* ed    = (float*)symp(g_ed);
    int*   rowp  = (int*)  symp(g_rowptr);
    int*   curs  = (int*)  symp(g_cursor);
    int*   bsum  = (int*)  symp(g_blocksums);
    int*   boff  = (int*)  symp(g_blockoff);
    float* bnacc = (float*)symp(g_bnacc);
    uint32_t* x16  = (uint32_t*)symp(g_x16);
    uint32_t* a216 = (uint32_t*)symp(g_a216);
    uint32_t* w116 = (uint32_t*)symp(g_w116), *r116 = (uint32_t*)symp(g_r116);
    uint32_t* w216 = (uint32_t*)symp(g_w216), *r216 = (uint32_t*)symp(g_r216);

    const int NB = (NN + 255) / 256;
    const int EB = (EE + 255) / 256;
    const int NODEWARP_BLKS = (NN * 32 + 255) / 256;
    dim3 gemm_grid(HC / 64, (NN + 127) / 128);   // (4, 391), branches merged
    const int W1W = HC * DIN / 2, W2W = HC * HC / 2;

    // ---- prep (gemm L1 lands at launch idx 3 for the ncu capture) ----
    cvt16_f4_kernel<<<(NN * DIN / 4 + 255) / 256, 256>>>(x, x16, NN * DIN / 4);        // 0
    wcvt2_kernel<<<dim3((W1W + 255) / 256, 2), 256>>>(W1, res1W, w116, r116, DIN);     // 1
    zero_int_kernel<<<NB, 256>>>(curs, NN);                                            // 2

    gemm16_kernel<<<gemm_grid, 256>>>(x16, w116, r116, res1b,
                                      asrc1, adst1, f16, res16, es, ed,
                                      NN, DIN);                                        // 3 <- profiled

    // ---- CSR build ----
    count_deg_kernel<<<EB, 256>>>(edge_idx);
    scan_block_kernel<<<NB, 256>>>(curs, rowp, bsum, NN);
    scan_block_kernel<<<1, 256>>>(bsum, boff, nullptr, NB);
    scan_add_kernel<<<NB, 256>>>(rowp, boff, NN);
    copy_int_kernel<<<NB, 256>>>(curs, rowp, NN);
    fill_csr_kernel<<<EB, 256>>>(edge_idx);

    // ---- layer 1 rest ----
    agg_kernel<<<NODEWARP_BLKS, 256>>>(f16, es, ed, res16, act);
    zero_float_kernel<<<2, 256>>>(bnacc, 2 * HC);
    bn_stats_kernel<<<(NN + 63) / 64, 256>>>(act);
    bn_finalize_kernel<<<1, HC>>>(bn1g, bn1b);
    bn_apply_cvt_kernel<<<(NN * HC / 4 + 255) / 256, 256>>>(act, a216);

    // ---- layer 2 ----
    wcvt2_kernel<<<dim3((W2W + 255) / 256, 2), 256>>>(W2, res2W, w216, r216, HC);
    gemm16_kernel<<<gemm_grid, 256>>>(a216, w216, r216, res2b,
                                      asrc2, adst2, f16, res16, es, ed,
                                      NN, HC);
    agg_kernel<<<NODEWARP_BLKS, 256>>>(f16, es, ed, res16, act);
    zero_float_kernel<<<2, 256>>>(bnacc, 2 * HC);
    bn_stats_kernel<<<(NN + 63) / 64, 256>>>(act);
    bn_finalize_kernel<<<1, HC>>>(bn2g, bn2b);
    bn_apply_kernel<<<(NN * HC / 4 + 255) / 256, 256>>>(act);

    // ---- pooling + MLP ----
    pool_kernel<<<NG, 256>>>(act, batch);
    mlp_kernel<<<NG, 128>>>(fc1W, fc1b, fc2W, fc2b, out);
}

// round 12
// speedup vs baseline: 1.9492x; 1.0104x over previous
#include <cuda_runtime.h>
#include <cuda_fp16.h>
#include <cstdint>

#define NN 50000
#define EE 800000
#define DIN 128
#define NH 4
#define CH 64
#define HC 256
#define NG 512
#define EPSBN 1e-5f
#define SLOPE 0.2f

// ---------------- scratch ----------------
__device__ uint32_t g_f16[(size_t)NN * HC / 2];   // feat fp16x2 (gather source)
__device__ uint32_t g_res16[(size_t)NN * HC / 2]; // residual fp16x2
__device__ float g_act [(size_t)NN * HC];
__device__ float g_es[NN * NH];
__device__ float g_ed[NN * NH];
__device__ int   g_rowptr[NN + 1];
__device__ int   g_cursor[NN];
__device__ int   g_srcsorted[EE];
__device__ int   g_blocksums[256];
__device__ int   g_blockoff[256];
__device__ float g_bnacc[2 * HC];
__device__ float g_bnA[HC];
__device__ float g_bnB[HC];
__device__ float g_pooled[NG * HC];
// fp16 GEMM operand buffers
__device__ uint32_t g_x16[(size_t)NN * DIN / 2];
__device__ uint32_t g_a216[(size_t)NN * HC / 2];
__device__ uint32_t g_w116[HC * DIN / 2], g_r116[HC * DIN / 2];
__device__ uint32_t g_w216[HC * HC / 2],  g_r216[HC * HC / 2];

__device__ __forceinline__ uint32_t f2h2(float2 v) {
    uint32_t r;
    asm("cvt.rn.f16x2.f32 %0, %1, %2;" : "=r"(r) : "f"(v.y), "f"(v.x));
    return r;
}

// ---------------- tiny utility kernels ----------------
__global__ void zero_float_kernel(float* p, int n) {
    int i = blockIdx.x * blockDim.x + threadIdx.x;
    if (i < n) p[i] = 0.0f;
}
__global__ void zero_int_kernel(int* p, int n) {
    int i = blockIdx.x * blockDim.x + threadIdx.x;
    if (i < n) p[i] = 0;
}
__global__ void copy_int_kernel(int* dst, const int* src, int n) {
    int i = blockIdx.x * blockDim.x + threadIdx.x;
    if (i < n) dst[i] = src[i];
}

// ---------------- prep: fp32 -> fp16 conversions ----------------
__global__ void cvt16_f4_kernel(const float* __restrict__ src,
                                uint32_t* __restrict__ dst, int n4) {
    int i = blockIdx.x * blockDim.x + threadIdx.x;
    if (i >= n4) return;
    float4 v = ((const float4*)src)[i];
    dst[2 * i]     = f2h2(make_float2(v.x, v.y));
    dst[2 * i + 1] = f2h2(make_float2(v.z, v.w));
}

__global__ void wcvt2_kernel(const float* __restrict__ W0, const float* __restrict__ W1,
                             uint32_t* __restrict__ t0, uint32_t* __restrict__ t1,
                             int Kd) {
    const float* W = blockIdx.y ? W1 : W0;
    uint32_t* th = blockIdx.y ? t1 : t0;
    int idx = blockIdx.x * blockDim.x + threadIdx.x;
    int kw = Kd >> 1;
    if (idx >= HC * kw) return;
    int n = idx / kw, kp = idx % kw;
    float a = W[(size_t)(2 * kp) * HC + n];
    float b = W[(size_t)(2 * kp + 1) * HC + n];
    th[idx] = f2h2(make_float2(a, b));
}

__global__ __launch_bounds__(256) void bn_apply_cvt_kernel(const float* __restrict__ x,
                                                           uint32_t* __restrict__ dh) {
    int i = blockIdx.x * blockDim.x + threadIdx.x;
    if (i >= NN * HC / 4) return;
    float4 v = ((const float4*)x)[i];
    int c = (i * 4) & 255;
    v.x = fmaxf(v.x * g_bnA[c + 0] + g_bnB[c + 0], 0.f);
    v.y = fmaxf(v.y * g_bnA[c + 1] + g_bnB[c + 1], 0.f);
    v.z = fmaxf(v.z * g_bnA[c + 2] + g_bnB[c + 2], 0.f);
    v.w = fmaxf(v.w * g_bnA[c + 3] + g_bnB[c + 3], 0.f);
    dh[2 * i]     = f2h2(make_float2(v.x, v.y));
    dh[2 * i + 1] = f2h2(make_float2(v.z, v.w));
}

// ---------------- CSR build ----------------
__global__ void count_deg_kernel(const int* __restrict__ ei) {
    int e = blockIdx.x * blockDim.x + threadIdx.x;
    if (e >= EE) return;
    atomicAdd(&g_cursor[ei[EE + e]], 1);
}

__global__ void scan_block_kernel(const int* __restrict__ in, int* __restrict__ out,
                                  int* __restrict__ blocksums, int n) {
    __shared__ int sh[256];
    int tid = threadIdx.x;
    int i = blockIdx.x * 256 + tid;
    int v = (i < n) ? in[i] : 0;
    sh[tid] = v;
    __syncthreads();
    for (int off = 1; off < 256; off <<= 1) {
        int t = (tid >= off) ? sh[tid - off] : 0;
        __syncthreads();
        sh[tid] += t;
        __syncthreads();
    }
    if (i < n) out[i] = sh[tid] - v;
    if (tid == 255 && blocksums) blocksums[blockIdx.x] = sh[255];
}

__global__ void scan_add_kernel(int* __restrict__ rowptr, const int* __restrict__ blockoff, int n) {
    int i = blockIdx.x * 256 + threadIdx.x;
    if (i < n) rowptr[i] += blockoff[blockIdx.x];
    if (blockIdx.x == 0 && threadIdx.x == 0) rowptr[n] = EE;
}

__global__ void fill_csr_kernel(const int* __restrict__ ei) {
    int e = blockIdx.x * blockDim.x + threadIdx.x;
    if (e >= EE) return;
    int s = ei[e];
    int d = ei[EE + e];
    int pos = atomicAdd(&g_cursor[d], 1);
    g_srcsorted[pos] = s;
}

// ============================================================================
// Merged-branch fp16 GEMM (unchanged from R11 winner).
// ============================================================================
#define AST 12

__device__ __forceinline__ void mma_f16(float* d, const uint32_t* a,
                                        uint32_t b0, uint32_t b1) {
    asm volatile(
        "mma.sync.aligned.m16n8k16.row.col.f32.f16.f16.f32 "
        "{%0,%1,%2,%3}, {%4,%5,%6,%7}, {%8,%9}, {%0,%1,%2,%3};\n"
        : "+f"(d[0]), "+f"(d[1]), "+f"(d[2]), "+f"(d[3])
        : "r"(a[0]), "r"(a[1]), "r"(a[2]), "r"(a[3]), "r"(b0), "r"(b1));
}

__device__ __forceinline__ void ldsm_x4(uint32_t& r0, uint32_t& r1,
                                        uint32_t& r2, uint32_t& r3, uint32_t saddr) {
    asm volatile("ldmatrix.sync.aligned.m8n8.x4.shared.b16 {%0,%1,%2,%3}, [%4];"
                 : "=r"(r0), "=r"(r1), "=r"(r2), "=r"(r3) : "r"(saddr));
}

__device__ __forceinline__ void cp_async16u(uint32_t* smem_ptr, const uint32_t* gptr, bool pred) {
    uint32_t sa = (uint32_t)__cvta_generic_to_shared(smem_ptr);
    int bytes = pred ? 16 : 0;
    asm volatile("cp.async.ca.shared.global [%0], [%1], 16, %2;\n"
                 :: "r"(sa), "l"(gptr), "r"(bytes));
}

__global__ __launch_bounds__(256, 2) void gemm16_kernel(
    const uint32_t* __restrict__ A16,
    const uint32_t* __restrict__ B16W, const uint32_t* __restrict__ B16R,
    const float* __restrict__ biasR,
    const float* __restrict__ asrc, const float* __restrict__ adst,
    uint32_t* __restrict__ Cf16, uint32_t* __restrict__ Cr16,
    float* __restrict__ es, float* __restrict__ ed,
    int Nr, int K)
{
    __shared__ uint32_t sA[2][128 * AST];
    __shared__ uint32_t sBW[2][64 * AST];
    __shared__ uint32_t sBR[2][64 * AST];
    __shared__ float sEs[128], sEd[128];

    const int Kw = K >> 1;
    const int tid  = threadIdx.x;
    const int lane = tid & 31;
    const int wid  = tid >> 5;
    const int warp_m = wid & 3;
    const int warp_n = wid >> 2;
    const int row0 = blockIdx.y * 128;
    const int col0 = blockIdx.x * 64;

    const int grp = lane >> 2;
    const int tig = lane & 3;

    if (tid < 128) { sEs[tid] = 0.f; sEd[tid] = 0.f; }

    float accW[2][4][4], accR[2][4][4];
#pragma unroll
    for (int mt = 0; mt < 2; mt++)
#pragma unroll
        for (int nt = 0; nt < 4; nt++)
#pragma unroll
            for (int i = 0; i < 4; i++) { accW[mt][nt][i] = 0.f; accR[mt][nt][i] = 0.f; }

    const int a_row = tid >> 1;
    const int a_wof = (tid & 1) * 4;
    const int b_row = (tid & 127) >> 1;
    const int b_wof = (tid & 1) * 4;
    const bool loadW = tid < 128;

    const int T = K / 16;

    const uint32_t sA_a  = (uint32_t)__cvta_generic_to_shared(&sA[0][0]);
    const uint32_t sBW_a = (uint32_t)__cvta_generic_to_shared(&sBW[0][0]);
    const uint32_t sBR_a = (uint32_t)__cvta_generic_to_shared(&sBR[0][0]);
    const uint32_t aoff = ((warp_m * 32 + (lane & 15)) * AST + (lane >> 4) * 4) * 4;
    const uint32_t boff = ((warp_n * 32 + (lane & 7) + ((lane >> 4) << 3)) * AST
                          + ((lane >> 3) & 1) * 4) * 4;
    const uint32_t ABUF = 128 * AST * 4;
    const uint32_t BBUF = 64 * AST * 4;
    const uint32_t MTSTEP = 16 * AST * 4;

    auto load_tile = [&](int it, int buf) {
        int gr = row0 + a_row;
        cp_async16u(&sA[buf][a_row * AST + a_wof],
                    &A16[(size_t)gr * Kw + it * 8 + a_wof], gr < Nr);
        if (loadW)
            cp_async16u(&sBW[buf][b_row * AST + b_wof],
                        &B16W[(size_t)(col0 + b_row) * Kw + it * 8 + b_wof], true);
        else
            cp_async16u(&sBR[buf][b_row * AST + b_wof],
                        &B16R[(size_t)(col0 + b_row) * Kw + it * 8 + b_wof], true);
        asm volatile("cp.async.commit_group;\n");
    };

    load_tile(0, 0);
    load_tile(1, 1);

    for (int it = 0; it < T; it++) {
        if (it < T - 1) asm volatile("cp.async.wait_group 1;\n");
        else            asm volatile("cp.async.wait_group 0;\n");
        __syncthreads();
        const uint32_t bufo = (it & 1) ? 1u : 0u;
        const uint32_t ab  = sA_a  + bufo * ABUF + aoff;
        const uint32_t bbw = sBW_a + bufo * BBUF + boff;
        const uint32_t bbr = sBR_a + bufo * BBUF + boff;

        uint32_t ah[2][4], bh[4][2];
        ldsm_x4(ah[0][0], ah[0][1], ah[0][2], ah[0][3], ab);
        ldsm_x4(ah[1][0], ah[1][1], ah[1][2], ah[1][3], ab + MTSTEP);

        ldsm_x4(bh[0][0], bh[0][1], bh[1][0], bh[1][1], bbw);
        ldsm_x4(bh[2][0], bh[2][1], bh[3][0], bh[3][1], bbw + MTSTEP);
#pragma unroll
        for (int nt = 0; nt < 4; nt++)
#pragma unroll
            for (int mt = 0; mt < 2; mt++)
                mma_f16(accW[mt][nt], ah[mt], bh[nt][0], bh[nt][1]);

        ldsm_x4(bh[0][0], bh[0][1], bh[1][0], bh[1][1], bbr);
        ldsm_x4(bh[2][0], bh[2][1], bh[3][0], bh[3][1], bbr + MTSTEP);
#pragma unroll
        for (int nt = 0; nt < 4; nt++)
#pragma unroll
            for (int mt = 0; mt < 2; mt++)
                mma_f16(accR[mt][nt], ah[mt], bh[nt][0], bh[nt][1]);

        __syncthreads();
        if (it + 2 < T) load_tile(it + 2, it & 1);
    }

    // ---- C writes (both fp16) ----
#pragma unroll
    for (int mt = 0; mt < 2; mt++) {
        int r = row0 + warp_m * 32 + mt * 16 + grp;
#pragma unroll
        for (int nt = 0; nt < 4; nt++) {
            int c = col0 + warp_n * 32 + nt * 8 + 2 * tig;
            float bx = biasR[c], by = biasR[c + 1];
            if (r < Nr) {
                Cf16[(size_t)r * (HC / 2) + (c >> 1)] =
                    f2h2(make_float2(accW[mt][nt][0], accW[mt][nt][1]));
                Cr16[(size_t)r * (HC / 2) + (c >> 1)] =
                    f2h2(make_float2(accR[mt][nt][0] + bx, accR[mt][nt][1] + by));
            }
            if (r + 8 < Nr) {
                Cf16[(size_t)(r + 8) * (HC / 2) + (c >> 1)] =
                    f2h2(make_float2(accW[mt][nt][2], accW[mt][nt][3]));
                Cr16[(size_t)(r + 8) * (HC / 2) + (c >> 1)] =
                    f2h2(make_float2(accR[mt][nt][2] + bx, accR[mt][nt][3] + by));
            }
        }
    }

    // ---- fused attention dots (from accW) ----
    {
        const int head = blockIdx.x;
        float pes[2][2] = {{0.f, 0.f}, {0.f, 0.f}};
        float ped[2][2] = {{0.f, 0.f}, {0.f, 0.f}};
#pragma unroll
        for (int mt = 0; mt < 2; mt++)
#pragma unroll
            for (int nt = 0; nt < 4; nt++) {
                int cl = warp_n * 32 + nt * 8 + 2 * tig;
                float a0 = asrc[head * CH + cl], a1 = asrc[head * CH + cl + 1];
                float d0 = adst[head * CH + cl], d1 = adst[head * CH + cl + 1];
                pes[mt][0] += accW[mt][nt][0] * a0 + accW[mt][nt][1] * a1;
                pes[mt][1] += accW[mt][nt][2] * a0 + accW[mt][nt][3] * a1;
                ped[mt][0] += accW[mt][nt][0] * d0 + accW[mt][nt][1] * d1;
                ped[mt][1] += accW[mt][nt][2] * d0 + accW[mt][nt][3] * d1;
            }
#pragma unroll
        for (int o = 1; o <= 2; o <<= 1) {
#pragma unroll
            for (int mt = 0; mt < 2; mt++)
#pragma unroll
                for (int hh = 0; hh < 2; hh++) {
                    pes[mt][hh] += __shfl_xor_sync(0xffffffffu, pes[mt][hh], o);
                    ped[mt][hh] += __shfl_xor_sync(0xffffffffu, ped[mt][hh], o);
                }
        }
        if (tig == 0) {
#pragma unroll
            for (int mt = 0; mt < 2; mt++)
#pragma unroll
                for (int hh = 0; hh < 2; hh++) {
                    int lr = warp_m * 32 + mt * 16 + hh * 8 + grp;
                    atomicAdd(&sEs[lr], pes[mt][hh]);
                    atomicAdd(&sEd[lr], ped[mt][hh]);
                }
        }
        __syncthreads();
        if (tid < 128) {
            int node = row0 + tid;
            if (node < Nr) {
                es[node * NH + head] = sEs[tid];
                ed[node * NH + head] = sEd[tid];
            }
        }
    }
}

// ============================================================================
// GAT softmax + aggregate + FUSED BN statistics.
// One warp per node, all 4 heads; lane l owns channels 8l..8l+7.
// Block-level smem accumulation of sum/sumsq -> 2 global atomics per channel.
// ============================================================================
__global__ __launch_bounds__(256) void agg_kernel(
    const uint32_t* __restrict__ f16, const float* __restrict__ es,
    const float* __restrict__ ed,
    const uint32_t* __restrict__ res16, float* __restrict__ out)
{
    __shared__ float ssum[8][HC];
    __shared__ float ssq [8][HC];

    int node = (blockIdx.x * blockDim.x + threadIdx.x) >> 5;
    int lane = threadIdx.x & 31;
    int wwid = threadIdx.x >> 5;
    int head = lane >> 3;
    int j    = lane & 7;
    bool valid = node < NN;

    float o[8];
#pragma unroll
    for (int i = 0; i < 8; i++) o[i] = 0.f;

    if (valid) {
        int s0 = g_rowptr[node], s1 = g_rowptr[node + 1];
        float acc[8];
#pragma unroll
        for (int i = 0; i < 8; i++) acc[i] = 0.f;

        if (s1 > s0) {
            float edv = ed[node * NH + head];
            float m = -INFINITY, den = 0.f;
            for (int k = s0 + j; k < s1; k += 8) {
                int s = g_srcsorted[k];
                float e = es[s * NH + head] + edv;
                e = (e >= 0.f) ? e : SLOPE * e;
                if (e > m) { den = den * __expf(m - e) + 1.f; m = e; }
                else den += __expf(e - m);
            }
#pragma unroll
            for (int oo = 1; oo <= 4; oo <<= 1) {
                float mo  = __shfl_xor_sync(0xffffffffu, m, oo);
                float dno = __shfl_xor_sync(0xffffffffu, den, oo);
                float nm = fmaxf(m, mo);
                float f1 = (m == nm) ? 1.f : __expf(m - nm);
                float f2 = (mo == nm) ? 1.f : __expf(mo - nm);
                den = den * f1 + dno * f2;
                m = nm;
            }
            float inv = 1.f / (den + 1e-16f);

            int k = s0;
            for (; k + 2 <= s1; k += 2) {
                int sa = g_srcsorted[k];
                int sb = g_srcsorted[k + 1];
                uint4 va = *(const uint4*)&f16[(size_t)sa * (HC / 2) + 4 * lane];
                uint4 vb = *(const uint4*)&f16[(size_t)sb * (HC / 2) + 4 * lane];
                float ea = es[sa * NH + head] + edv;
                float eb = es[sb * NH + head] + edv;
                ea = (ea >= 0.f) ? ea : SLOPE * ea;
                eb = (eb >= 0.f) ? eb : SLOPE * eb;
                float wa = __expf(ea - m) * inv;
                float wb = __expf(eb - m) * inv;
                float2 p;
                p = __half22float2(*(const __half2*)&va.x); acc[0] += wa * p.x; acc[1] += wa * p.y;
                p = __half22float2(*(const __half2*)&va.y); acc[2] += wa * p.x; acc[3] += wa * p.y;
                p = __half22float2(*(const __half2*)&va.z); acc[4] += wa * p.x; acc[5] += wa * p.y;
                p = __half22float2(*(const __half2*)&va.w); acc[6] += wa * p.x; acc[7] += wa * p.y;
                p = __half22float2(*(const __half2*)&vb.x); acc[0] += wb * p.x; acc[1] += wb * p.y;
                p = __half22float2(*(const __half2*)&vb.y); acc[2] += wb * p.x; acc[3] += wb * p.y;
                p = __half22float2(*(const __half2*)&vb.z); acc[4] += wb * p.x; acc[5] += wb * p.y;
                p = __half22float2(*(const __half2*)&vb.w); acc[6] += wb * p.x; acc[7] += wb * p.y;
            }
            if (k < s1) {
                int sa = g_srcsorted[k];
                uint4 va = *(const uint4*)&f16[(size_t)sa * (HC / 2) + 4 * lane];
                float ea = es[sa * NH + head] + edv;
                ea = (ea >= 0.f) ? ea : SLOPE * ea;
                float wa = __expf(ea - m) * inv;
                float2 p;
                p = __half22float2(*(const __half2*)&va.x); acc[0] += wa * p.x; acc[1] += wa * p.y;
                p = __half22float2(*(const __half2*)&va.y); acc[2] += wa * p.x; acc[3] += wa * p.y;
                p = __half22float2(*(const __half2*)&va.z); acc[4] += wa * p.x; acc[5] += wa * p.y;
                p = __half22float2(*(const __half2*)&va.w); acc[6] += wa * p.x; acc[7] += wa * p.y;
            }
        }

        uint4 rv = *(const uint4*)&res16[(size_t)node * (HC / 2) + 4 * lane];
        float2 r0 = __half22float2(*(const __half2*)&rv.x);
        float2 r1 = __half22float2(*(const __half2*)&rv.y);
        float2 r2 = __half22float2(*(const __half2*)&rv.z);
        float2 r3 = __half22float2(*(const __half2*)&rv.w);
        o[0] = acc[0] + r0.x; o[1] = acc[1] + r0.y;
        o[2] = acc[2] + r1.x; o[3] = acc[3] + r1.y;
        o[4] = acc[4] + r2.x; o[5] = acc[5] + r2.y;
        o[6] = acc[6] + r3.x; o[7] = acc[7] + r3.y;

        int cb = 8 * lane;
        ((float4*)&out[(size_t)node * HC + cb])[0] = make_float4(o[0], o[1], o[2], o[3]);
        ((float4*)&out[(size_t)node * HC + cb])[1] = make_float4(o[4], o[5], o[6], o[7]);
    }

    // ---- fused BN statistics ----
    {
        int cb = 8 * lane;
#pragma unroll
        for (int i = 0; i < 8; i++) {
            ssum[wwid][cb + i] = o[i];
            ssq [wwid][cb + i] = o[i] * o[i];
        }
        __syncthreads();
        int t = threadIdx.x;           // channel
        float S = 0.f, Q = 0.f;
#pragma unroll
        for (int w = 0; w < 8; w++) { S += ssum[w][t]; Q += ssq[w][t]; }
        atomicAdd(&g_bnacc[t], S);
        atomicAdd(&g_bnacc[t + HC], Q);
    }
}

// ---------------- BatchNorm finalize ----------------
__global__ void bn_finalize_kernel(const float* __restrict__ gma, const float* __restrict__ beta) {
    int c = threadIdx.x;
    float mean = g_bnacc[c] / (float)NN;
    float var  = g_bnacc[c + HC] / (float)NN - mean * mean;
    float a = gma[c] * rsqrtf(var + EPSBN);
    g_bnA[c] = a;
    g_bnB[c] = beta[c] - mean * a;
}

// ---------------- pooling with fused BN2-apply+ReLU (batch sorted) ----------------
__global__ __launch_bounds__(256) void pool_bn_kernel(const float* __restrict__ act,
                                                      const int* __restrict__ batch) {
    __shared__ int s_lo, s_hi;
    int g = blockIdx.x;
    int t = threadIdx.x;
    if (t == 0) {
        int lo = 0, hi = NN;
        while (lo < hi) { int mid = (lo + hi) >> 1; if (batch[mid] < g) lo = mid + 1; else hi = mid; }
        s_lo = lo;
        int lo2 = lo; hi = NN;
        while (lo2 < hi) { int mid = (lo2 + hi) >> 1; if (batch[mid] < g + 1) lo2 = mid + 1; else hi = mid; }
        s_hi = lo2;
    }
    __syncthreads();
    int lo = s_lo, hi = s_hi;
    float A = g_bnA[t], Bc = g_bnB[t];
    float s = 0.f;
    for (int r = lo; r < hi; r++)
        s += fmaxf(act[(size_t)r * HC + t] * A + Bc, 0.f);
    float inv = (hi > lo) ? 1.0f / (float)(hi - lo) : 0.0f;
    g_pooled[(size_t)g * HC + t] = s * inv;
}

// ---------------- graph-level MLP ----------------
__global__ __launch_bounds__(128) void mlp_kernel(
    const float* __restrict__ fc1W, const float* __restrict__ fc1b,
    const float* __restrict__ fc2W, const float* __restrict__ fc2b,
    float* __restrict__ out)
{
    __shared__ float row[HC];
    __shared__ float red[128];
    int g = blockIdx.x, t = threadIdx.x;
    row[t]       = g_pooled[(size_t)g * HC + t];
    row[t + 128] = g_pooled[(size_t)g * HC + t + 128];
    __syncthreads();
    float a = fc1b[t];
#pragma unroll 8
    for (int k = 0; k < HC; k++) a += row[k] * fc1W[k * 128 + t];
    a = fmaxf(a, 0.f);
    for (int j = 0; j < 2; j++) {
        red[t] = a * fc2W[t * 2 + j];
        __syncthreads();
        for (int off = 64; off; off >>= 1) {
            if (t < off) red[t] += red[t + off];
            __syncthreads();
        }
        if (t == 0) out[g * 2 + j] = red[0] + fc2b[j];
        __syncthreads();
    }
}

// ---------------- host side ----------------
static void* symp(const void* sym) {
    void* p = nullptr;
    cudaGetSymbolAddress(&p, sym);
    return p;
}

extern "C" void kernel_launch(void* const* d_in, const int* in_sizes, int n_in,
                              void* d_out, int out_size)
{
    const float* x        = (const float*)d_in[0];
    const int*   edge_idx = (const int*)  d_in[1];
    const int*   batch    = (const int*)  d_in[3];
    const float* W1       = (const float*)d_in[4];
    const float* asrc1    = (const float*)d_in[5];
    const float* adst1    = (const float*)d_in[6];
    const float* b1       = (const float*)d_in[7];
    const float* res1W    = (const float*)d_in[8];
    const float* res1b    = (const float*)d_in[9];
    const float* bn1g     = (const float*)d_in[10];
    const float* bn1b     = (const float*)d_in[11];
    const float* W2       = (const float*)d_in[12];
    const float* asrc2    = (const float*)d_in[13];
    const float* adst2    = (const float*)d_in[14];
    const float* b2       = (const float*)d_in[15];
    const float* res2W    = (const float*)d_in[16];
    const float* res2b    = (const float*)d_in[17];
    const float* bn2g     = (const float*)d_in[18];
    const float* bn2b     = (const float*)d_in[19];
    const float* fc1W     = (const float*)d_in[20];
    const float* fc1b     = (const float*)d_in[21];
    const float* fc2W     = (const float*)d_in[22];
    const float* fc2b     = (const float*)d_in[23];
    float* out = (float*)d_out;

    uint32_t* f16  = (uint32_t*)symp(g_f16);
    uint32_t* res16= (uint32_t*)symp(g_res16);
    float* act   = (float*)symp(g_act);
    float* es    = (float*)symp(g_es);
    float* ed    = (float*)symp(g_ed);
    int*   rowp  = (int*)  symp(g_rowptr);
    int*   curs  = (int*)  symp(g_cursor);
    int*   bsum  = (int*)  symp(g_blocksums);
    int*   boff  = (int*)  symp(g_blockoff);
    float* bnacc = (float*)symp(g_bnacc);
    uint32_t* x16  = (uint32_t*)symp(g_x16);
    uint32_t* a216 = (uint32_t*)symp(g_a216);
    uint32_t* w116 = (uint32_t*)symp(g_w116), *r116 = (uint32_t*)symp(g_r116);
    uint32_t* w216 = (uint32_t*)symp(g_w216), *r216 = (uint32_t*)symp(g_r216);

    const int NB = (NN + 255) / 256;
    const int EB = (EE + 255) / 256;
    const int NODEWARP_BLKS = (NN * 32 + 255) / 256;
    dim3 gemm_grid(HC / 64, (NN + 127) / 128);
    const int W1W = HC * DIN / 2, W2W = HC * HC / 2;

    // ---- prep (gemm L1 lands at launch idx 3 for the ncu capture) ----
    cvt16_f4_kernel<<<(NN * DIN / 4 + 255) / 256, 256>>>(x, x16, NN * DIN / 4);        // 0
    wcvt2_kernel<<<dim3((W1W + 255) / 256, 2), 256>>>(W1, res1W, w116, r116, DIN);     // 1
    zero_int_kernel<<<NB, 256>>>(curs, NN);                                            // 2

    gemm16_kernel<<<gemm_grid, 256>>>(x16, w116, r116, res1b,
                                      asrc1, adst1, f16, res16, es, ed,
                                      NN, DIN);                                        // 3 <- profiled

    // ---- CSR build ----
    count_deg_kernel<<<EB, 256>>>(edge_idx);
    scan_block_kernel<<<NB, 256>>>(curs, rowp, bsum, NN);
    scan_block_kernel<<<1, 256>>>(bsum, boff, nullptr, NB);
    scan_add_kernel<<<NB, 256>>>(rowp, boff, NN);
    copy_int_kernel<<<NB, 256>>>(curs, rowp, NN);
    fill_csr_kernel<<<EB, 256>>>(edge_idx);

    // ---- layer 1: agg (+stats) -> finalize -> apply+cvt ----
    zero_float_kernel<<<2, 256>>>(bnacc, 2 * HC);
    agg_kernel<<<NODEWARP_BLKS, 256>>>(f16, es, ed, res16, act);
    bn_finalize_kernel<<<1, HC>>>(bn1g, bn1b);
    bn_apply_cvt_kernel<<<(NN * HC / 4 + 255) / 256, 256>>>(act, a216);

    // ---- layer 2 ----
    wcvt2_kernel<<<dim3((W2W + 255) / 256, 2), 256>>>(W2, res2W, w216, r216, HC);
    gemm16_kernel<<<gemm_grid, 256>>>(a216, w216, r216, res2b,
                                      asrc2, adst2, f16, res16, es, ed,
                                      NN, HC);
    zero_float_kernel<<<2, 256>>>(bnacc, 2 * HC);
    agg_kernel<<<NODEWARP_BLKS, 256>>>(f16, es, ed, res16, act);
    bn_finalize_kernel<<<1, HC>>>(bn2g, bn2b);

    // ---- pooling (BN2-apply fused) + MLP ----
    pool_bn_kernel<<<NG, 256>>>(act, batch);
    mlp_kernel<<<NG, 128>>>(fc1W, fc1b, fc2W, fc2b, out);
}

// round 13
// speedup vs baseline: 1.9837x; 1.0177x over previous
#include <cuda_runtime.h>
#include <cuda_fp16.h>
#include <cstdint>

#define NN 50000
#define EE 800000
#define DIN 128
#define NH 4
#define CH 64
#define HC 256
#define NG 512
#define EPSBN 1e-5f
#define SLOPE 0.2f

// ---------------- scratch ----------------
__device__ uint32_t g_f16[(size_t)NN * HC / 2];   // feat fp16x2 (gather source)
__device__ uint32_t g_res16[(size_t)NN * HC / 2]; // residual fp16x2
__device__ float g_act [(size_t)NN * HC];
__device__ float g_es[NN * NH];
__device__ float g_ed[NN * NH];
__device__ int   g_rowptr[NN + 1];
__device__ int   g_cursor[NN];
__device__ int   g_srcsorted[EE];
__device__ int   g_blocksums[256];
__device__ int   g_blockoff[256];
__device__ float g_bnacc[2 * HC];
__device__ float g_bnA[HC];
__device__ float g_bnB[HC];
__device__ float g_pooled[NG * HC];
// fp16 GEMM operand buffers
__device__ uint32_t g_x16[(size_t)NN * DIN / 2];
__device__ uint32_t g_a216[(size_t)NN * HC / 2];
__device__ uint32_t g_w116[HC * DIN / 2], g_r116[HC * DIN / 2];
__device__ uint32_t g_w216[HC * HC / 2],  g_r216[HC * HC / 2];

__device__ __forceinline__ uint32_t f2h2(float2 v) {
    uint32_t r;
    asm("cvt.rn.f16x2.f32 %0, %1, %2;" : "=r"(r) : "f"(v.y), "f"(v.x));
    return r;
}

// ---------------- tiny utility kernels ----------------
__global__ void zero_float_kernel(float* p, int n) {
    int i = blockIdx.x * blockDim.x + threadIdx.x;
    if (i < n) p[i] = 0.0f;
}
__global__ void zero_int_kernel(int* p, int n) {
    int i = blockIdx.x * blockDim.x + threadIdx.x;
    if (i < n) p[i] = 0;
}

// ---------------- prep: fp32 -> fp16 conversions ----------------
__global__ void cvt16_f4_kernel(const float* __restrict__ src,
                                uint32_t* __restrict__ dst, int n4) {
    int i = blockIdx.x * blockDim.x + threadIdx.x;
    if (i >= n4) return;
    float4 v = ((const float4*)src)[i];
    dst[2 * i]     = f2h2(make_float2(v.x, v.y));
    dst[2 * i + 1] = f2h2(make_float2(v.z, v.w));
}

__global__ void wcvt2_kernel(const float* __restrict__ W0, const float* __restrict__ W1,
                             uint32_t* __restrict__ t0, uint32_t* __restrict__ t1,
                             int Kd) {
    const float* W = blockIdx.y ? W1 : W0;
    uint32_t* th = blockIdx.y ? t1 : t0;
    int idx = blockIdx.x * blockDim.x + threadIdx.x;
    int kw = Kd >> 1;
    if (idx >= HC * kw) return;
    int n = idx / kw, kp = idx % kw;
    float a = W[(size_t)(2 * kp) * HC + n];
    float b = W[(size_t)(2 * kp + 1) * HC + n];
    th[idx] = f2h2(make_float2(a, b));
}

__global__ __launch_bounds__(256) void bn_apply_cvt_kernel(const float* __restrict__ x,
                                                           uint32_t* __restrict__ dh) {
    int i = blockIdx.x * blockDim.x + threadIdx.x;
    if (i >= NN * HC / 4) return;
    float4 v = ((const float4*)x)[i];
    int c = (i * 4) & 255;
    v.x = fmaxf(v.x * g_bnA[c + 0] + g_bnB[c + 0], 0.f);
    v.y = fmaxf(v.y * g_bnA[c + 1] + g_bnB[c + 1], 0.f);
    v.z = fmaxf(v.z * g_bnA[c + 2] + g_bnB[c + 2], 0.f);
    v.w = fmaxf(v.w * g_bnA[c + 3] + g_bnB[c + 3], 0.f);
    dh[2 * i]     = f2h2(make_float2(v.x, v.y));
    dh[2 * i + 1] = f2h2(make_float2(v.z, v.w));
}

// ---------------- CSR build ----------------
__global__ void count_deg_kernel(const int* __restrict__ ei) {
    int e = blockIdx.x * blockDim.x + threadIdx.x;
    if (e >= EE) return;
    atomicAdd(&g_cursor[ei[EE + e]], 1);
}

__global__ void scan_block_kernel(const int* __restrict__ in, int* __restrict__ out,
                                  int* __restrict__ blocksums, int n) {
    __shared__ int sh[256];
    int tid = threadIdx.x;
    int i = blockIdx.x * 256 + tid;
    int v = (i < n) ? in[i] : 0;
    sh[tid] = v;
    __syncthreads();
    for (int off = 1; off < 256; off <<= 1) {
        int t = (tid >= off) ? sh[tid - off] : 0;
        __syncthreads();
        sh[tid] += t;
        __syncthreads();
    }
    if (i < n) out[i] = sh[tid] - v;
    if (tid == 255 && blocksums) blocksums[blockIdx.x] = sh[255];
}

// adds block offsets AND initializes cursor to the final rowptr (merged copy)
__global__ void scan_add_kernel(int* __restrict__ rowptr, int* __restrict__ cursor,
                                const int* __restrict__ blockoff, int n) {
    int i = blockIdx.x * 256 + threadIdx.x;
    if (i < n) {
        int v = rowptr[i] + blockoff[blockIdx.x];
        rowptr[i] = v;
        cursor[i] = v;
    }
    if (blockIdx.x == 0 && threadIdx.x == 0) rowptr[n] = EE;
}

__global__ void fill_csr_kernel(const int* __restrict__ ei) {
    int e = blockIdx.x * blockDim.x + threadIdx.x;
    if (e >= EE) return;
    int s = ei[e];
    int d = ei[EE + e];
    int pos = atomicAdd(&g_cursor[d], 1);
    g_srcsorted[pos] = s;
}

// ============================================================================
// Merged-branch fp16 GEMM, 3-stage cp.async pipeline, one sync per k-tile,
// loads issued before compute (overlap).
// ============================================================================
#define AST 12
#define NSTAGE 3

__device__ __forceinline__ void mma_f16(float* d, const uint32_t* a,
                                        uint32_t b0, uint32_t b1) {
    asm volatile(
        "mma.sync.aligned.m16n8k16.row.col.f32.f16.f16.f32 "
        "{%0,%1,%2,%3}, {%4,%5,%6,%7}, {%8,%9}, {%0,%1,%2,%3};\n"
        : "+f"(d[0]), "+f"(d[1]), "+f"(d[2]), "+f"(d[3])
        : "r"(a[0]), "r"(a[1]), "r"(a[2]), "r"(a[3]), "r"(b0), "r"(b1));
}

__device__ __forceinline__ void ldsm_x4(uint32_t& r0, uint32_t& r1,
                                        uint32_t& r2, uint32_t& r3, uint32_t saddr) {
    asm volatile("ldmatrix.sync.aligned.m8n8.x4.shared.b16 {%0,%1,%2,%3}, [%4];"
                 : "=r"(r0), "=r"(r1), "=r"(r2), "=r"(r3) : "r"(saddr));
}

__device__ __forceinline__ void cp_async16u(uint32_t* smem_ptr, const uint32_t* gptr, bool pred) {
    uint32_t sa = (uint32_t)__cvta_generic_to_shared(smem_ptr);
    int bytes = pred ? 16 : 0;
    asm volatile("cp.async.ca.shared.global [%0], [%1], 16, %2;\n"
                 :: "r"(sa), "l"(gptr), "r"(bytes));
}

__global__ __launch_bounds__(256, 2) void gemm16_kernel(
    const uint32_t* __restrict__ A16,
    const uint32_t* __restrict__ B16W, const uint32_t* __restrict__ B16R,
    const float* __restrict__ biasR,
    const float* __restrict__ asrc, const float* __restrict__ adst,
    uint32_t* __restrict__ Cf16, uint32_t* __restrict__ Cr16,
    float* __restrict__ es, float* __restrict__ ed,
    int Nr, int K)
{
    __shared__ uint32_t sA[NSTAGE][128 * AST];
    __shared__ uint32_t sBW[NSTAGE][64 * AST];
    __shared__ uint32_t sBR[NSTAGE][64 * AST];
    __shared__ float sEs[128], sEd[128];

    const int Kw = K >> 1;
    const int tid  = threadIdx.x;
    const int lane = tid & 31;
    const int wid  = tid >> 5;
    const int warp_m = wid & 3;
    const int warp_n = wid >> 2;
    const int row0 = blockIdx.y * 128;
    const int col0 = blockIdx.x * 64;

    const int grp = lane >> 2;
    const int tig = lane & 3;

    if (tid < 128) { sEs[tid] = 0.f; sEd[tid] = 0.f; }

    float accW[2][4][4], accR[2][4][4];
#pragma unroll
    for (int mt = 0; mt < 2; mt++)
#pragma unroll
        for (int nt = 0; nt < 4; nt++)
#pragma unroll
            for (int i = 0; i < 4; i++) { accW[mt][nt][i] = 0.f; accR[mt][nt][i] = 0.f; }

    const int a_row = tid >> 1;
    const int a_wof = (tid & 1) * 4;
    const int b_row = (tid & 127) >> 1;
    const int b_wof = (tid & 1) * 4;
    const bool loadW = tid < 128;

    const int T = K / 16;

    const uint32_t sA_a  = (uint32_t)__cvta_generic_to_shared(&sA[0][0]);
    const uint32_t sBW_a = (uint32_t)__cvta_generic_to_shared(&sBW[0][0]);
    const uint32_t sBR_a = (uint32_t)__cvta_generic_to_shared(&sBR[0][0]);
    const uint32_t aoff = ((warp_m * 32 + (lane & 15)) * AST + (lane >> 4) * 4) * 4;
    const uint32_t boff = ((warp_n * 32 + (lane & 7) + ((lane >> 4) << 3)) * AST
                          + ((lane >> 3) & 1) * 4) * 4;
    const uint32_t ABUF = 128 * AST * 4;
    const uint32_t BBUF = 64 * AST * 4;
    const uint32_t MTSTEP = 16 * AST * 4;

    auto load_tile = [&](int it, int buf) {
        int gr = row0 + a_row;
        cp_async16u(&sA[buf][a_row * AST + a_wof],
                    &A16[(size_t)gr * Kw + it * 8 + a_wof], gr < Nr);
        if (loadW)
            cp_async16u(&sBW[buf][b_row * AST + b_wof],
                        &B16W[(size_t)(col0 + b_row) * Kw + it * 8 + b_wof], true);
        else
            cp_async16u(&sBR[buf][b_row * AST + b_wof],
                        &B16R[(size_t)(col0 + b_row) * Kw + it * 8 + b_wof], true);
        asm volatile("cp.async.commit_group;\n");
    };

    load_tile(0, 0);
    if (T > 1) load_tile(1, 1);

    int buf = 0, nbuf = 2;   // buffer of tile `it`; next free buffer (tile it+2)
    for (int it = 0; it < T; it++) {
        if (it + 1 < T) asm volatile("cp.async.wait_group 1;\n");
        else            asm volatile("cp.async.wait_group 0;\n");
        __syncthreads();
        if (it + 2 < T) load_tile(it + 2, nbuf);

        const uint32_t ab  = sA_a  + (uint32_t)buf * ABUF + aoff;
        const uint32_t bbw = sBW_a + (uint32_t)buf * BBUF + boff;
        const uint32_t bbr = sBR_a + (uint32_t)buf * BBUF + boff;

        uint32_t ah[2][4], bh[4][2];
        ldsm_x4(ah[0][0], ah[0][1], ah[0][2], ah[0][3], ab);
        ldsm_x4(ah[1][0], ah[1][1], ah[1][2], ah[1][3], ab + MTSTEP);

        ldsm_x4(bh[0][0], bh[0][1], bh[1][0], bh[1][1], bbw);
        ldsm_x4(bh[2][0], bh[2][1], bh[3][0], bh[3][1], bbw + MTSTEP);
#pragma unroll
        for (int nt = 0; nt < 4; nt++)
#pragma unroll
            for (int mt = 0; mt < 2; mt++)
                mma_f16(accW[mt][nt], ah[mt], bh[nt][0], bh[nt][1]);

        ldsm_x4(bh[0][0], bh[0][1], bh[1][0], bh[1][1], bbr);
        ldsm_x4(bh[2][0], bh[2][1], bh[3][0], bh[3][1], bbr + MTSTEP);
#pragma unroll
        for (int nt = 0; nt < 4; nt++)
#pragma unroll
            for (int mt = 0; mt < 2; mt++)
                mma_f16(accR[mt][nt], ah[mt], bh[nt][0], bh[nt][1]);

        buf = (buf + 1 == NSTAGE) ? 0 : buf + 1;
        nbuf = (nbuf + 1 == NSTAGE) ? 0 : nbuf + 1;
    }

    // ---- C writes (both fp16) ----
#pragma unroll
    for (int mt = 0; mt < 2; mt++) {
        int r = row0 + warp_m * 32 + mt * 16 + grp;
#pragma unroll
        for (int nt = 0; nt < 4; nt++) {
            int c = col0 + warp_n * 32 + nt * 8 + 2 * tig;
            float bx = biasR[c], by = biasR[c + 1];
            if (r < Nr) {
                Cf16[(size_t)r * (HC / 2) + (c >> 1)] =
                    f2h2(make_float2(accW[mt][nt][0], accW[mt][nt][1]));
                Cr16[(size_t)r * (HC / 2) + (c >> 1)] =
                    f2h2(make_float2(accR[mt][nt][0] + bx, accR[mt][nt][1] + by));
            }
            if (r + 8 < Nr) {
                Cf16[(size_t)(r + 8) * (HC / 2) + (c >> 1)] =
                    f2h2(make_float2(accW[mt][nt][2], accW[mt][nt][3]));
                Cr16[(size_t)(r + 8) * (HC / 2) + (c >> 1)] =
                    f2h2(make_float2(accR[mt][nt][2] + bx, accR[mt][nt][3] + by));
            }
        }
    }

    // ---- fused attention dots (from accW) ----
    {
        const int head = blockIdx.x;
        float pes[2][2] = {{0.f, 0.f}, {0.f, 0.f}};
        float ped[2][2] = {{0.f, 0.f}, {0.f, 0.f}};
#pragma unroll
        for (int mt = 0; mt < 2; mt++)
#pragma unroll
            for (int nt = 0; nt < 4; nt++) {
                int cl = warp_n * 32 + nt * 8 + 2 * tig;
                float a0 = asrc[head * CH + cl], a1 = asrc[head * CH + cl + 1];
                float d0 = adst[head * CH + cl], d1 = adst[head * CH + cl + 1];
                pes[mt][0] += accW[mt][nt][0] * a0 + accW[mt][nt][1] * a1;
                pes[mt][1] += accW[mt][nt][2] * a0 + accW[mt][nt][3] * a1;
                ped[mt][0] += accW[mt][nt][0] * d0 + accW[mt][nt][1] * d1;
                ped[mt][1] += accW[mt][nt][2] * d0 + accW[mt][nt][3] * d1;
            }
#pragma unroll
        for (int o = 1; o <= 2; o <<= 1) {
#pragma unroll
            for (int mt = 0; mt < 2; mt++)
#pragma unroll
                for (int hh = 0; hh < 2; hh++) {
                    pes[mt][hh] += __shfl_xor_sync(0xffffffffu, pes[mt][hh], o);
                    ped[mt][hh] += __shfl_xor_sync(0xffffffffu, ped[mt][hh], o);
                }
        }
        if (tig == 0) {
#pragma unroll
            for (int mt = 0; mt < 2; mt++)
#pragma unroll
                for (int hh = 0; hh < 2; hh++) {
                    int lr = warp_m * 32 + mt * 16 + hh * 8 + grp;
                    atomicAdd(&sEs[lr], pes[mt][hh]);
                    atomicAdd(&sEd[lr], ped[mt][hh]);
                }
        }
        __syncthreads();
        if (tid < 128) {
            int node = row0 + tid;
            if (node < Nr) {
                es[node * NH + head] = sEs[tid];
                ed[node * NH + head] = sEd[tid];
            }
        }
    }
}

// ============================================================================
// GAT softmax + aggregate + fused BN statistics (R12 winner, unchanged).
// ============================================================================
__global__ __launch_bounds__(256) void agg_kernel(
    const uint32_t* __restrict__ f16, const float* __restrict__ es,
    const float* __restrict__ ed,
    const uint32_t* __restrict__ res16, float* __restrict__ out)
{
    __shared__ float ssum[8][HC];
    __shared__ float ssq [8][HC];

    int node = (blockIdx.x * blockDim.x + threadIdx.x) >> 5;
    int lane = threadIdx.x & 31;
    int wwid = threadIdx.x >> 5;
    int head = lane >> 3;
    int j    = lane & 7;
    bool valid = node < NN;

    float o[8];
#pragma unroll
    for (int i = 0; i < 8; i++) o[i] = 0.f;

    if (valid) {
        int s0 = g_rowptr[node], s1 = g_rowptr[node + 1];
        float acc[8];
#pragma unroll
        for (int i = 0; i < 8; i++) acc[i] = 0.f;

        if (s1 > s0) {
            float edv = ed[node * NH + head];
            float m = -INFINITY, den = 0.f;
            for (int k = s0 + j; k < s1; k += 8) {
                int s = g_srcsorted[k];
                float e = es[s * NH + head] + edv;
                e = (e >= 0.f) ? e : SLOPE * e;
                if (e > m) { den = den * __expf(m - e) + 1.f; m = e; }
                else den += __expf(e - m);
            }
#pragma unroll
            for (int oo = 1; oo <= 4; oo <<= 1) {
                float mo  = __shfl_xor_sync(0xffffffffu, m, oo);
                float dno = __shfl_xor_sync(0xffffffffu, den, oo);
                float nm = fmaxf(m, mo);
                float f1 = (m == nm) ? 1.f : __expf(m - nm);
                float f2 = (mo == nm) ? 1.f : __expf(mo - nm);
                den = den * f1 + dno * f2;
                m = nm;
            }
            float inv = 1.f / (den + 1e-16f);

            int k = s0;
            for (; k + 2 <= s1; k += 2) {
                int sa = g_srcsorted[k];
                int sb = g_srcsorted[k + 1];
                uint4 va = *(const uint4*)&f16[(size_t)sa * (HC / 2) + 4 * lane];
                uint4 vb = *(const uint4*)&f16[(size_t)sb * (HC / 2) + 4 * lane];
                float ea = es[sa * NH + head] + edv;
                float eb = es[sb * NH + head] + edv;
                ea = (ea >= 0.f) ? ea : SLOPE * ea;
                eb = (eb >= 0.f) ? eb : SLOPE * eb;
                float wa = __expf(ea - m) * inv;
                float wb = __expf(eb - m) * inv;
                float2 p;
                p = __half22float2(*(const __half2*)&va.x); acc[0] += wa * p.x; acc[1] += wa * p.y;
                p = __half22float2(*(const __half2*)&va.y); acc[2] += wa * p.x; acc[3] += wa * p.y;
                p = __half22float2(*(const __half2*)&va.z); acc[4] += wa * p.x; acc[5] += wa * p.y;
                p = __half22float2(*(const __half2*)&va.w); acc[6] += wa * p.x; acc[7] += wa * p.y;
                p = __half22float2(*(const __half2*)&vb.x); acc[0] += wb * p.x; acc[1] += wb * p.y;
                p = __half22float2(*(const __half2*)&vb.y); acc[2] += wb * p.x; acc[3] += wb * p.y;
                p = __half22float2(*(const __half2*)&vb.z); acc[4] += wb * p.x; acc[5] += wb * p.y;
                p = __half22float2(*(const __half2*)&vb.w); acc[6] += wb * p.x; acc[7] += wb * p.y;
            }
            if (k < s1) {
                int sa = g_srcsorted[k];
                uint4 va = *(const uint4*)&f16[(size_t)sa * (HC / 2) + 4 * lane];
                float ea = es[sa * NH + head] + edv;
                ea = (ea >= 0.f) ? ea : SLOPE * ea;
                float wa = __expf(ea - m) * inv;
                float2 p;
                p = __half22float2(*(const __half2*)&va.x); acc[0] += wa * p.x; acc[1] += wa * p.y;
                p = __half22float2(*(const __half2*)&va.y); acc[2] += wa * p.x; acc[3] += wa * p.y;
                p = __half22float2(*(const __half2*)&va.z); acc[4] += wa * p.x; acc[5] += wa * p.y;
                p = __half22float2(*(const __half2*)&va.w); acc[6] += wa * p.x; acc[7] += wa * p.y;
            }
        }

        uint4 rv = *(const uint4*)&res16[(size_t)node * (HC / 2) + 4 * lane];
        float2 r0 = __half22float2(*(const __half2*)&rv.x);
        float2 r1 = __half22float2(*(const __half2*)&rv.y);
        float2 r2 = __half22float2(*(const __half2*)&rv.z);
        float2 r3 = __half22float2(*(const __half2*)&rv.w);
        o[0] = acc[0] + r0.x; o[1] = acc[1] + r0.y;
        o[2] = acc[2] + r1.x; o[3] = acc[3] + r1.y;
        o[4] = acc[4] + r2.x; o[5] = acc[5] + r2.y;
        o[6] = acc[6] + r3.x; o[7] = acc[7] + r3.y;

        int cb = 8 * lane;
        ((float4*)&out[(size_t)node * HC + cb])[0] = make_float4(o[0], o[1], o[2], o[3]);
        ((float4*)&out[(size_t)node * HC + cb])[1] = make_float4(o[4], o[5], o[6], o[7]);
    }

    // ---- fused BN statistics ----
    {
        int cb = 8 * lane;
#pragma unroll
        for (int i = 0; i < 8; i++) {
            ssum[wwid][cb + i] = o[i];
            ssq [wwid][cb + i] = o[i] * o[i];
        }
        __syncthreads();
        int t = threadIdx.x;
        float S = 0.f, Q = 0.f;
#pragma unroll
        for (int w = 0; w < 8; w++) { S += ssum[w][t]; Q += ssq[w][t]; }
        atomicAdd(&g_bnacc[t], S);
        atomicAdd(&g_bnacc[t + HC], Q);
    }
}

// ---------------- BatchNorm finalize ----------------
__global__ void bn_finalize_kernel(const float* __restrict__ gma, const float* __restrict__ beta) {
    int c = threadIdx.x;
    float mean = g_bnacc[c] / (float)NN;
    float var  = g_bnacc[c + HC] / (float)NN - mean * mean;
    float a = gma[c] * rsqrtf(var + EPSBN);
    g_bnA[c] = a;
    g_bnB[c] = beta[c] - mean * a;
}

// ---------------- pooling with fused BN2-apply+ReLU ----------------
__global__ __launch_bounds__(256) void pool_bn_kernel(const float* __restrict__ act,
                                                      const int* __restrict__ batch) {
    __shared__ int s_lo, s_hi;
    int g = blockIdx.x;
    int t = threadIdx.x;
    if (t == 0) {
        int lo = 0, hi = NN;
        while (lo < hi) { int mid = (lo + hi) >> 1; if (batch[mid] < g) lo = mid + 1; else hi = mid; }
        s_lo = lo;
        int lo2 = lo; hi = NN;
        while (lo2 < hi) { int mid = (lo2 + hi) >> 1; if (batch[mid] < g + 1) lo2 = mid + 1; else hi = mid; }
        s_hi = lo2;
    }
    __syncthreads();
    int lo = s_lo, hi = s_hi;
    float A = g_bnA[t], Bc = g_bnB[t];
    float s = 0.f;
    for (int r = lo; r < hi; r++)
        s += fmaxf(act[(size_t)r * HC + t] * A + Bc, 0.f);
    float inv = (hi > lo) ? 1.0f / (float)(hi - lo) : 0.0f;
    g_pooled[(size_t)g * HC + t] = s * inv;
}

// ---------------- graph-level MLP ----------------
__global__ __launch_bounds__(128) void mlp_kernel(
    const float* __restrict__ fc1W, const float* __restrict__ fc1b,
    const float* __restrict__ fc2W, const float* __restrict__ fc2b,
    float* __restrict__ out)
{
    __shared__ float row[HC];
    __shared__ float red[128];
    int g = blockIdx.x, t = threadIdx.x;
    row[t]       = g_pooled[(size_t)g * HC + t];
    row[t + 128] = g_pooled[(size_t)g * HC + t + 128];
    __syncthreads();
    float a = fc1b[t];
#pragma unroll 8
    for (int k = 0; k < HC; k++) a += row[k] * fc1W[k * 128 + t];
    a = fmaxf(a, 0.f);
    for (int j = 0; j < 2; j++) {
        red[t] = a * fc2W[t * 2 + j];
        __syncthreads();
        for (int off = 64; off; off >>= 1) {
            if (t < off) red[t] += red[t + off];
            __syncthreads();
        }
        if (t == 0) out[g * 2 + j] = red[0] + fc2b[j];
        __syncthreads();
    }
}

// ---------------- host side ----------------
static void* symp(const void* sym) {
    void* p = nullptr;
    cudaGetSymbolAddress(&p, sym);
    return p;
}

extern "C" void kernel_launch(void* const* d_in, const int* in_sizes, int n_in,
                              void* d_out, int out_size)
{
    const float* x        = (const float*)d_in[0];
    const int*   edge_idx = (const int*)  d_in[1];
    const int*   batch    = (const int*)  d_in[3];
    const float* W1       = (const float*)d_in[4];
    const float* asrc1    = (const float*)d_in[5];
    const float* adst1    = (const float*)d_in[6];
    const float* b1       = (const float*)d_in[7];
    const float* res1W    = (const float*)d_in[8];
    const float* res1b    = (const float*)d_in[9];
    const float* bn1g     = (const float*)d_in[10];
    const float* bn1b     = (const float*)d_in[11];
    const float* W2       = (const float*)d_in[12];
    const float* asrc2    = (const float*)d_in[13];
    const float* adst2    = (const float*)d_in[14];
    const float* b2       = (const float*)d_in[15];
    const float* res2W    = (const float*)d_in[16];
    const float* res2b    = (const float*)d_in[17];
    const float* bn2g     = (const float*)d_in[18];
    const float* bn2b     = (const float*)d_in[19];
    const float* fc1W     = (const float*)d_in[20];
    const float* fc1b     = (const float*)d_in[21];
    const float* fc2W     = (const float*)d_in[22];
    const float* fc2b     = (const float*)d_in[23];
    float* out = (float*)d_out;

    uint32_t* f16  = (uint32_t*)symp(g_f16);
    uint32_t* res16= (uint32_t*)symp(g_res16);
    float* act   = (float*)symp(g_act);
    float* es    = (float*)symp(g_es);
    float* ed    = (float*)symp(g_ed);
    int*   rowp  = (int*)  symp(g_rowptr);
    int*   curs  = (int*)  symp(g_cursor);
    int*   bsum  = (int*)  symp(g_blocksums);
    int*   boff  = (int*)  symp(g_blockoff);
    float* bnacc = (float*)symp(g_bnacc);
    uint32_t* x16  = (uint32_t*)symp(g_x16);
    uint32_t* a216 = (uint32_t*)symp(g_a216);
    uint32_t* w116 = (uint32_t*)symp(g_w116), *r116 = (uint32_t*)symp(g_r116);
    uint32_t* w216 = (uint32_t*)symp(g_w216), *r216 = (uint32_t*)symp(g_r216);

    const int NB = (NN + 255) / 256;
    const int EB = (EE + 255) / 256;
    const int NODEWARP_BLKS = (NN * 32 + 255) / 256;
    dim3 gemm_grid(HC / 64, (NN + 127) / 128);
    const int W1W = HC * DIN / 2, W2W = HC * HC / 2;

    // ---- prep (gemm L1 lands at launch idx 3 for the ncu capture) ----
    cvt16_f4_kernel<<<(NN * DIN / 4 + 255) / 256, 256>>>(x, x16, NN * DIN / 4);        // 0
    wcvt2_kernel<<<dim3((W1W + 255) / 256, 2), 256>>>(W1, res1W, w116, r116, DIN);     // 1
    zero_int_kernel<<<NB, 256>>>(curs, NN);                                            // 2

    gemm16_kernel<<<gemm_grid, 256>>>(x16, w116, r116, res1b,
                                      asrc1, adst1, f16, res16, es, ed,
                                      NN, DIN);                                        // 3 <- profiled

    // ---- CSR build ----
    count_deg_kernel<<<EB, 256>>>(edge_idx);
    scan_block_kernel<<<NB, 256>>>(curs, rowp, bsum, NN);
    scan_block_kernel<<<1, 256>>>(bsum, boff, nullptr, NB);
    scan_add_kernel<<<NB, 256>>>(rowp, curs, boff, NN);
    fill_csr_kernel<<<EB, 256>>>(edge_idx);

    // ---- layer 1: agg (+stats) -> finalize -> apply+cvt ----
    zero_float_kernel<<<2, 256>>>(bnacc, 2 * HC);
    agg_kernel<<<NODEWARP_BLKS, 256>>>(f16, es, ed, res16, act);
    bn_finalize_kernel<<<1, HC>>>(bn1g, bn1b);
    bn_apply_cvt_kernel<<<(NN * HC / 4 + 255) / 256, 256>>>(act, a216);

    // ---- layer 2 ----
    wcvt2_kernel<<<dim3((W2W + 255) / 256, 2), 256>>>(W2, res2W, w216, r216, HC);
    gemm16_kernel<<<gemm_grid, 256>>>(a216, w216, r216, res2b,
                                      asrc2, adst2, f16, res16, es, ed,
                                      NN, HC);
    zero_float_kernel<<<2, 256>>>(bnacc, 2 * HC);
    agg_kernel<<<NODEWARP_BLKS, 256>>>(f16, es, ed, res16, act);
    bn_finalize_kernel<<<1, HC>>>(bn2g, bn2b);

    // ---- pooling (BN2-apply fused) + MLP ----
    pool_bn_kernel<<<NG, 256>>>(act, batch);
    mlp_kernel<<<NG, 128>>>(fc1W, fc1b, fc2W, fc2b, out);
}

// round 14
// speedup vs baseline: 2.0649x; 1.0410x over previous
#include <cuda_runtime.h>
#include <cuda_fp16.h>
#include <cstdint>

#define NN 50000
#define EE 800000
#define DIN 128
#define NH 4
#define CH 64
#define HC 256
#define NG 512
#define EPSBN 1e-5f
#define SLOPE 0.2f

// ---------------- scratch ----------------
__device__ uint32_t g_f16[(size_t)NN * HC / 2];   // feat fp16x2 (gather source)
__device__ uint32_t g_res16[(size_t)NN * HC / 2]; // residual fp16x2
__device__ float g_act [(size_t)NN * HC];
__device__ float g_es[NN * NH];
__device__ float g_ed[NN * NH];
__device__ int   g_rowptr[NN + 1];
__device__ int   g_cursor[NN];
__device__ int   g_srcsorted[EE];
__device__ int   g_blocksums[256];
__device__ int   g_blockoff[256];
__device__ float g_bnacc[2 * HC];
__device__ float g_bnA[HC];
__device__ float g_bnB[HC];
__device__ float g_pooled[NG * HC];
// fp16 GEMM operand buffers
__device__ uint32_t g_x16[(size_t)NN * DIN / 2];
__device__ uint32_t g_a216[(size_t)NN * HC / 2];
__device__ uint32_t g_w116[HC * DIN / 2], g_r116[HC * DIN / 2];
__device__ uint32_t g_w216[HC * HC / 2],  g_r216[HC * HC / 2];

__device__ __forceinline__ uint32_t f2h2(float2 v) {
    uint32_t r;
    asm("cvt.rn.f16x2.f32 %0, %1, %2;" : "=r"(r) : "f"(v.y), "f"(v.x));
    return r;
}

// ---------------- tiny utility kernels ----------------
__global__ void zero_float_kernel(float* p, int n) {
    int i = blockIdx.x * blockDim.x + threadIdx.x;
    if (i < n) p[i] = 0.0f;
}
__global__ void zero_int_kernel(int* p, int n) {
    int i = blockIdx.x * blockDim.x + threadIdx.x;
    if (i < n) p[i] = 0;
}

// ---------------- prep: fp32 -> fp16 conversions ----------------
__global__ void cvt16_f4_kernel(const float* __restrict__ src,
                                uint32_t* __restrict__ dst, int n4) {
    int i = blockIdx.x * blockDim.x + threadIdx.x;
    if (i >= n4) return;
    float4 v = ((const float4*)src)[i];
    dst[2 * i]     = f2h2(make_float2(v.x, v.y));
    dst[2 * i + 1] = f2h2(make_float2(v.z, v.w));
}

__global__ void wcvt2_kernel(const float* __restrict__ W0, const float* __restrict__ W1,
                             uint32_t* __restrict__ t0, uint32_t* __restrict__ t1,
                             int Kd) {
    const float* W = blockIdx.y ? W1 : W0;
    uint32_t* th = blockIdx.y ? t1 : t0;
    int idx = blockIdx.x * blockDim.x + threadIdx.x;
    int kw = Kd >> 1;
    if (idx >= HC * kw) return;
    int n = idx / kw, kp = idx % kw;
    float a = W[(size_t)(2 * kp) * HC + n];
    float b = W[(size_t)(2 * kp + 1) * HC + n];
    th[idx] = f2h2(make_float2(a, b));
}

__global__ __launch_bounds__(256) void bn_apply_cvt_kernel(const float* __restrict__ x,
                                                           uint32_t* __restrict__ dh) {
    int i = blockIdx.x * blockDim.x + threadIdx.x;
    if (i >= NN * HC / 4) return;
    float4 v = ((const float4*)x)[i];
    int c = (i * 4) & 255;
    v.x = fmaxf(v.x * g_bnA[c + 0] + g_bnB[c + 0], 0.f);
    v.y = fmaxf(v.y * g_bnA[c + 1] + g_bnB[c + 1], 0.f);
    v.z = fmaxf(v.z * g_bnA[c + 2] + g_bnB[c + 2], 0.f);
    v.w = fmaxf(v.w * g_bnA[c + 3] + g_bnB[c + 3], 0.f);
    dh[2 * i]     = f2h2(make_float2(v.x, v.y));
    dh[2 * i + 1] = f2h2(make_float2(v.z, v.w));
}

// ---------------- CSR build ----------------
__global__ void count_deg_kernel(const int* __restrict__ ei) {
    int e = blockIdx.x * blockDim.x + threadIdx.x;
    if (e >= EE) return;
    atomicAdd(&g_cursor[ei[EE + e]], 1);
}

__global__ void scan_block_kernel(const int* __restrict__ in, int* __restrict__ out,
                                  int* __restrict__ blocksums, int n) {
    __shared__ int sh[256];
    int tid = threadIdx.x;
    int i = blockIdx.x * 256 + tid;
    int v = (i < n) ? in[i] : 0;
    sh[tid] = v;
    __syncthreads();
    for (int off = 1; off < 256; off <<= 1) {
        int t = (tid >= off) ? sh[tid - off] : 0;
        __syncthreads();
        sh[tid] += t;
        __syncthreads();
    }
    if (i < n) out[i] = sh[tid] - v;
    if (tid == 255 && blocksums) blocksums[blockIdx.x] = sh[255];
}

// adds block offsets AND initializes cursor to the final rowptr (merged copy)
__global__ void scan_add_kernel(int* __restrict__ rowptr, int* __restrict__ cursor,
                                const int* __restrict__ blockoff, int n) {
    int i = blockIdx.x * 256 + threadIdx.x;
    if (i < n) {
        int v = rowptr[i] + blockoff[blockIdx.x];
        rowptr[i] = v;
        cursor[i] = v;
    }
    if (blockIdx.x == 0 && threadIdx.x == 0) rowptr[n] = EE;
}

__global__ void fill_csr_kernel(const int* __restrict__ ei) {
    int e = blockIdx.x * blockDim.x + threadIdx.x;
    if (e >= EE) return;
    int s = ei[e];
    int d = ei[EE + e];
    int pos = atomicAdd(&g_cursor[d], 1);
    g_srcsorted[pos] = s;
}

// ============================================================================
// Merged-branch fp16 GEMM, 3-stage cp.async pipeline (R13 winner, unchanged).
// ============================================================================
#define AST 12
#define NSTAGE 3

__device__ __forceinline__ void mma_f16(float* d, const uint32_t* a,
                                        uint32_t b0, uint32_t b1) {
    asm volatile(
        "mma.sync.aligned.m16n8k16.row.col.f32.f16.f16.f32 "
        "{%0,%1,%2,%3}, {%4,%5,%6,%7}, {%8,%9}, {%0,%1,%2,%3};\n"
        : "+f"(d[0]), "+f"(d[1]), "+f"(d[2]), "+f"(d[3])
        : "r"(a[0]), "r"(a[1]), "r"(a[2]), "r"(a[3]), "r"(b0), "r"(b1));
}

__device__ __forceinline__ void ldsm_x4(uint32_t& r0, uint32_t& r1,
                                        uint32_t& r2, uint32_t& r3, uint32_t saddr) {
    asm volatile("ldmatrix.sync.aligned.m8n8.x4.shared.b16 {%0,%1,%2,%3}, [%4];"
                 : "=r"(r0), "=r"(r1), "=r"(r2), "=r"(r3) : "r"(saddr));
}

__device__ __forceinline__ void cp_async16u(uint32_t* smem_ptr, const uint32_t* gptr, bool pred) {
    uint32_t sa = (uint32_t)__cvta_generic_to_shared(smem_ptr);
    int bytes = pred ? 16 : 0;
    asm volatile("cp.async.ca.shared.global [%0], [%1], 16, %2;\n"
                 :: "r"(sa), "l"(gptr), "r"(bytes));
}

__global__ __launch_bounds__(256, 2) void gemm16_kernel(
    const uint32_t* __restrict__ A16,
    const uint32_t* __restrict__ B16W, const uint32_t* __restrict__ B16R,
    const float* __restrict__ biasR,
    const float* __restrict__ asrc, const float* __restrict__ adst,
    uint32_t* __restrict__ Cf16, uint32_t* __restrict__ Cr16,
    float* __restrict__ es, float* __restrict__ ed,
    int Nr, int K)
{
    __shared__ uint32_t sA[NSTAGE][128 * AST];
    __shared__ uint32_t sBW[NSTAGE][64 * AST];
    __shared__ uint32_t sBR[NSTAGE][64 * AST];
    __shared__ float sEs[128], sEd[128];

    const int Kw = K >> 1;
    const int tid  = threadIdx.x;
    const int lane = tid & 31;
    const int wid  = tid >> 5;
    const int warp_m = wid & 3;
    const int warp_n = wid >> 2;
    const int row0 = blockIdx.y * 128;
    const int col0 = blockIdx.x * 64;

    const int grp = lane >> 2;
    const int tig = lane & 3;

    if (tid < 128) { sEs[tid] = 0.f; sEd[tid] = 0.f; }

    float accW[2][4][4], accR[2][4][4];
#pragma unroll
    for (int mt = 0; mt < 2; mt++)
#pragma unroll
        for (int nt = 0; nt < 4; nt++)
#pragma unroll
            for (int i = 0; i < 4; i++) { accW[mt][nt][i] = 0.f; accR[mt][nt][i] = 0.f; }

    const int a_row = tid >> 1;
    const int a_wof = (tid & 1) * 4;
    const int b_row = (tid & 127) >> 1;
    const int b_wof = (tid & 1) * 4;
    const bool loadW = tid < 128;

    const int T = K / 16;

    const uint32_t sA_a  = (uint32_t)__cvta_generic_to_shared(&sA[0][0]);
    const uint32_t sBW_a = (uint32_t)__cvta_generic_to_shared(&sBW[0][0]);
    const uint32_t sBR_a = (uint32_t)__cvta_generic_to_shared(&sBR[0][0]);
    const uint32_t aoff = ((warp_m * 32 + (lane & 15)) * AST + (lane >> 4) * 4) * 4;
    const uint32_t boff = ((warp_n * 32 + (lane & 7) + ((lane >> 4) << 3)) * AST
                          + ((lane >> 3) & 1) * 4) * 4;
    const uint32_t ABUF = 128 * AST * 4;
    const uint32_t BBUF = 64 * AST * 4;
    const uint32_t MTSTEP = 16 * AST * 4;

    auto load_tile = [&](int it, int buf) {
        int gr = row0 + a_row;
        cp_async16u(&sA[buf][a_row * AST + a_wof],
                    &A16[(size_t)gr * Kw + it * 8 + a_wof], gr < Nr);
        if (loadW)
            cp_async16u(&sBW[buf][b_row * AST + b_wof],
                        &B16W[(size_t)(col0 + b_row) * Kw + it * 8 + b_wof], true);
        else
            cp_async16u(&sBR[buf][b_row * AST + b_wof],
                        &B16R[(size_t)(col0 + b_row) * Kw + it * 8 + b_wof], true);
        asm volatile("cp.async.commit_group;\n");
    };

    load_tile(0, 0);
    if (T > 1) load_tile(1, 1);

    int buf = 0, nbuf = 2;
    for (int it = 0; it < T; it++) {
        if (it + 1 < T) asm volatile("cp.async.wait_group 1;\n");
        else            asm volatile("cp.async.wait_group 0;\n");
        __syncthreads();
        if (it + 2 < T) load_tile(it + 2, nbuf);

        const uint32_t ab  = sA_a  + (uint32_t)buf * ABUF + aoff;
        const uint32_t bbw = sBW_a + (uint32_t)buf * BBUF + boff;
        const uint32_t bbr = sBR_a + (uint32_t)buf * BBUF + boff;

        uint32_t ah[2][4], bh[4][2];
        ldsm_x4(ah[0][0], ah[0][1], ah[0][2], ah[0][3], ab);
        ldsm_x4(ah[1][0], ah[1][1], ah[1][2], ah[1][3], ab + MTSTEP);

        ldsm_x4(bh[0][0], bh[0][1], bh[1][0], bh[1][1], bbw);
        ldsm_x4(bh[2][0], bh[2][1], bh[3][0], bh[3][1], bbw + MTSTEP);
#pragma unroll
        for (int nt = 0; nt < 4; nt++)
#pragma unroll
            for (int mt = 0; mt < 2; mt++)
                mma_f16(accW[mt][nt], ah[mt], bh[nt][0], bh[nt][1]);

        ldsm_x4(bh[0][0], bh[0][1], bh[1][0], bh[1][1], bbr);
        ldsm_x4(bh[2][0], bh[2][1], bh[3][0], bh[3][1], bbr + MTSTEP);
#pragma unroll
        for (int nt = 0; nt < 4; nt++)
#pragma unroll
            for (int mt = 0; mt < 2; mt++)
                mma_f16(accR[mt][nt], ah[mt], bh[nt][0], bh[nt][1]);

        buf = (buf + 1 == NSTAGE) ? 0 : buf + 1;
        nbuf = (nbuf + 1 == NSTAGE) ? 0 : nbuf + 1;
    }

    // ---- C writes (both fp16) ----
#pragma unroll
    for (int mt = 0; mt < 2; mt++) {
        int r = row0 + warp_m * 32 + mt * 16 + grp;
#pragma unroll
        for (int nt = 0; nt < 4; nt++) {
            int c = col0 + warp_n * 32 + nt * 8 + 2 * tig;
            float bx = biasR[c], by = biasR[c + 1];
            if (r < Nr) {
                Cf16[(size_t)r * (HC / 2) + (c >> 1)] =
                    f2h2(make_float2(accW[mt][nt][0], accW[mt][nt][1]));
                Cr16[(size_t)r * (HC / 2) + (c >> 1)] =
                    f2h2(make_float2(accR[mt][nt][0] + bx, accR[mt][nt][1] + by));
            }
            if (r + 8 < Nr) {
                Cf16[(size_t)(r + 8) * (HC / 2) + (c >> 1)] =
                    f2h2(make_float2(accW[mt][nt][2], accW[mt][nt][3]));
                Cr16[(size_t)(r + 8) * (HC / 2) + (c >> 1)] =
                    f2h2(make_float2(accR[mt][nt][2] + bx, accR[mt][nt][3] + by));
            }
        }
    }

    // ---- fused attention dots (from accW) ----
    {
        const int head = blockIdx.x;
        float pes[2][2] = {{0.f, 0.f}, {0.f, 0.f}};
        float ped[2][2] = {{0.f, 0.f}, {0.f, 0.f}};
#pragma unroll
        for (int mt = 0; mt < 2; mt++)
#pragma unroll
            for (int nt = 0; nt < 4; nt++) {
                int cl = warp_n * 32 + nt * 8 + 2 * tig;
                float a0 = asrc[head * CH + cl], a1 = asrc[head * CH + cl + 1];
                float d0 = adst[head * CH + cl], d1 = adst[head * CH + cl + 1];
                pes[mt][0] += accW[mt][nt][0] * a0 + accW[mt][nt][1] * a1;
                pes[mt][1] += accW[mt][nt][2] * a0 + accW[mt][nt][3] * a1;
                ped[mt][0] += accW[mt][nt][0] * d0 + accW[mt][nt][1] * d1;
                ped[mt][1] += accW[mt][nt][2] * d0 + accW[mt][nt][3] * d1;
            }
#pragma unroll
        for (int o = 1; o <= 2; o <<= 1) {
#pragma unroll
            for (int mt = 0; mt < 2; mt++)
#pragma unroll
                for (int hh = 0; hh < 2; hh++) {
                    pes[mt][hh] += __shfl_xor_sync(0xffffffffu, pes[mt][hh], o);
                    ped[mt][hh] += __shfl_xor_sync(0xffffffffu, ped[mt][hh], o);
                }
        }
        if (tig == 0) {
#pragma unroll
            for (int mt = 0; mt < 2; mt++)
#pragma unroll
                for (int hh = 0; hh < 2; hh++) {
                    int lr = warp_m * 32 + mt * 16 + hh * 8 + grp;
                    atomicAdd(&sEs[lr], pes[mt][hh]);
                    atomicAdd(&sEd[lr], ped[mt][hh]);
                }
        }
        __syncthreads();
        if (tid < 128) {
            int node = row0 + tid;
            if (node < Nr) {
                es[node * NH + head] = sEs[tid];
                ed[node * NH + head] = sEd[tid];
            }
        }
    }
}

// ============================================================================
// GAT softmax + aggregate + fused BN statistics (unchanged).
// ============================================================================
__global__ __launch_bounds__(256) void agg_kernel(
    const uint32_t* __restrict__ f16, const float* __restrict__ es,
    const float* __restrict__ ed,
    const uint32_t* __restrict__ res16, float* __restrict__ out)
{
    __shared__ float ssum[8][HC];
    __shared__ float ssq [8][HC];

    int node = (blockIdx.x * blockDim.x + threadIdx.x) >> 5;
    int lane = threadIdx.x & 31;
    int wwid = threadIdx.x >> 5;
    int head = lane >> 3;
    int j    = lane & 7;
    bool valid = node < NN;

    float o[8];
#pragma unroll
    for (int i = 0; i < 8; i++) o[i] = 0.f;

    if (valid) {
        int s0 = g_rowptr[node], s1 = g_rowptr[node + 1];
        float acc[8];
#pragma unroll
        for (int i = 0; i < 8; i++) acc[i] = 0.f;

        if (s1 > s0) {
            float edv = ed[node * NH + head];
            float m = -INFINITY, den = 0.f;
            for (int k = s0 + j; k < s1; k += 8) {
                int s = g_srcsorted[k];
                float e = es[s * NH + head] + edv;
                e = (e >= 0.f) ? e : SLOPE * e;
                if (e > m) { den = den * __expf(m - e) + 1.f; m = e; }
                else den += __expf(e - m);
            }
#pragma unroll
            for (int oo = 1; oo <= 4; oo <<= 1) {
                float mo  = __shfl_xor_sync(0xffffffffu, m, oo);
                float dno = __shfl_xor_sync(0xffffffffu, den, oo);
                float nm = fmaxf(m, mo);
                float f1 = (m == nm) ? 1.f : __expf(m - nm);
                float f2 = (mo == nm) ? 1.f : __expf(mo - nm);
                den = den * f1 + dno * f2;
                m = nm;
            }
            float inv = 1.f / (den + 1e-16f);

            int k = s0;
            for (; k + 2 <= s1; k += 2) {
                int sa = g_srcsorted[k];
                int sb = g_srcsorted[k + 1];
                uint4 va = *(const uint4*)&f16[(size_t)sa * (HC / 2) + 4 * lane];
                uint4 vb = *(const uint4*)&f16[(size_t)sb * (HC / 2) + 4 * lane];
                float ea = es[sa * NH + head] + edv;
                float eb = es[sb * NH + head] + edv;
                ea = (ea >= 0.f) ? ea : SLOPE * ea;
                eb = (eb >= 0.f) ? eb : SLOPE * eb;
                float wa = __expf(ea - m) * inv;
                float wb = __expf(eb - m) * inv;
                float2 p;
                p = __half22float2(*(const __half2*)&va.x); acc[0] += wa * p.x; acc[1] += wa * p.y;
                p = __half22float2(*(const __half2*)&va.y); acc[2] += wa * p.x; acc[3] += wa * p.y;
                p = __half22float2(*(const __half2*)&va.z); acc[4] += wa * p.x; acc[5] += wa * p.y;
                p = __half22float2(*(const __half2*)&va.w); acc[6] += wa * p.x; acc[7] += wa * p.y;
                p = __half22float2(*(const __half2*)&vb.x); acc[0] += wb * p.x; acc[1] += wb * p.y;
                p = __half22float2(*(const __half2*)&vb.y); acc[2] += wb * p.x; acc[3] += wb * p.y;
                p = __half22float2(*(const __half2*)&vb.z); acc[4] += wb * p.x; acc[5] += wb * p.y;
                p = __half22float2(*(const __half2*)&vb.w); acc[6] += wb * p.x; acc[7] += wb * p.y;
            }
            if (k < s1) {
                int sa = g_srcsorted[k];
                uint4 va = *(const uint4*)&f16[(size_t)sa * (HC / 2) + 4 * lane];
                float ea = es[sa * NH + head] + edv;
                ea = (ea >= 0.f) ? ea : SLOPE * ea;
                float wa = __expf(ea - m) * inv;
                float2 p;
                p = __half22float2(*(const __half2*)&va.x); acc[0] += wa * p.x; acc[1] += wa * p.y;
                p = __half22float2(*(const __half2*)&va.y); acc[2] += wa * p.x; acc[3] += wa * p.y;
                p = __half22float2(*(const __half2*)&va.z); acc[4] += wa * p.x; acc[5] += wa * p.y;
                p = __half22float2(*(const __half2*)&va.w); acc[6] += wa * p.x; acc[7] += wa * p.y;
            }
        }

        uint4 rv = *(const uint4*)&res16[(size_t)node * (HC / 2) + 4 * lane];
        float2 r0 = __half22float2(*(const __half2*)&rv.x);
        float2 r1 = __half22float2(*(const __half2*)&rv.y);
        float2 r2 = __half22float2(*(const __half2*)&rv.z);
        float2 r3 = __half22float2(*(const __half2*)&rv.w);
        o[0] = acc[0] + r0.x; o[1] = acc[1] + r0.y;
        o[2] = acc[2] + r1.x; o[3] = acc[3] + r1.y;
        o[4] = acc[4] + r2.x; o[5] = acc[5] + r2.y;
        o[6] = acc[6] + r3.x; o[7] = acc[7] + r3.y;

        int cb = 8 * lane;
        ((float4*)&out[(size_t)node * HC + cb])[0] = make_float4(o[0], o[1], o[2], o[3]);
        ((float4*)&out[(size_t)node * HC + cb])[1] = make_float4(o[4], o[5], o[6], o[7]);
    }

    // ---- fused BN statistics ----
    {
        int cb = 8 * lane;
#pragma unroll
        for (int i = 0; i < 8; i++) {
            ssum[wwid][cb + i] = o[i];
            ssq [wwid][cb + i] = o[i] * o[i];
        }
        __syncthreads();
        int t = threadIdx.x;
        float S = 0.f, Q = 0.f;
#pragma unroll
        for (int w = 0; w < 8; w++) { S += ssum[w][t]; Q += ssq[w][t]; }
        atomicAdd(&g_bnacc[t], S);
        atomicAdd(&g_bnacc[t + HC], Q);
    }
}

// ---------------- BatchNorm finalize ----------------
__global__ void bn_finalize_kernel(const float* __restrict__ gma, const float* __restrict__ beta) {
    int c = threadIdx.x;
    float mean = g_bnacc[c] / (float)NN;
    float var  = g_bnacc[c + HC] / (float)NN - mean * mean;
    float a = gma[c] * rsqrtf(var + EPSBN);
    g_bnA[c] = a;
    g_bnB[c] = beta[c] - mean * a;
}

// ---------------- pooling with fused BN2-apply+ReLU ----------------
__global__ __launch_bounds__(256) void pool_bn_kernel(const float* __restrict__ act,
                                                      const int* __restrict__ batch) {
    __shared__ int s_lo, s_hi;
    int g = blockIdx.x;
    int t = threadIdx.x;
    if (t == 0) {
        int lo = 0, hi = NN;
        while (lo < hi) { int mid = (lo + hi) >> 1; if (batch[mid] < g) lo = mid + 1; else hi = mid; }
        s_lo = lo;
        int lo2 = lo; hi = NN;
        while (lo2 < hi) { int mid = (lo2 + hi) >> 1; if (batch[mid] < g + 1) lo2 = mid + 1; else hi = mid; }
        s_hi = lo2;
    }
    __syncthreads();
    int lo = s_lo, hi = s_hi;
    float A = g_bnA[t], Bc = g_bnB[t];
    float s = 0.f;
    for (int r = lo; r < hi; r++)
        s += fmaxf(act[(size_t)r * HC + t] * A + Bc, 0.f);
    float inv = (hi > lo) ? 1.0f / (float)(hi - lo) : 0.0f;
    g_pooled[(size_t)g * HC + t] = s * inv;
}

// ---------------- graph-level MLP ----------------
__global__ __launch_bounds__(128) void mlp_kernel(
    const float* __restrict__ fc1W, const float* __restrict__ fc1b,
    const float* __restrict__ fc2W, const float* __restrict__ fc2b,
    float* __restrict__ out)
{
    __shared__ float row[HC];
    __shared__ float red[128];
    int g = blockIdx.x, t = threadIdx.x;
    row[t]       = g_pooled[(size_t)g * HC + t];
    row[t + 128] = g_pooled[(size_t)g * HC + t + 128];
    __syncthreads();
    float a = fc1b[t];
#pragma unroll 8
    for (int k = 0; k < HC; k++) a += row[k] * fc1W[k * 128 + t];
    a = fmaxf(a, 0.f);
    for (int j = 0; j < 2; j++) {
        red[t] = a * fc2W[t * 2 + j];
        __syncthreads();
        for (int off = 64; off; off >>= 1) {
            if (t < off) red[t] += red[t + off];
            __syncthreads();
        }
        if (t == 0) out[g * 2 + j] = red[0] + fc2b[j];
        __syncthreads();
    }
}

// ---------------- host side ----------------
static void* symp(const void* sym) {
    void* p = nullptr;
    cudaGetSymbolAddress(&p, sym);
    return p;
}

extern "C" void kernel_launch(void* const* d_in, const int* in_sizes, int n_in,
                              void* d_out, int out_size)
{
    const float* x        = (const float*)d_in[0];
    const int*   edge_idx = (const int*)  d_in[1];
    const int*   batch    = (const int*)  d_in[3];
    const float* W1       = (const float*)d_in[4];
    const float* asrc1    = (const float*)d_in[5];
    const float* adst1    = (const float*)d_in[6];
    const float* b1       = (const float*)d_in[7];
    const float* res1W    = (const float*)d_in[8];
    const float* res1b    = (const float*)d_in[9];
    const float* bn1g     = (const float*)d_in[10];
    const float* bn1b     = (const float*)d_in[11];
    const float* W2       = (const float*)d_in[12];
    const float* asrc2    = (const float*)d_in[13];
    const float* adst2    = (const float*)d_in[14];
    const float* b2       = (const float*)d_in[15];
    const float* res2W    = (const float*)d_in[16];
    const float* res2b    = (const float*)d_in[17];
    const float* bn2g     = (const float*)d_in[18];
    const float* bn2b     = (const float*)d_in[19];
    const float* fc1W     = (const float*)d_in[20];
    const float* fc1b     = (const float*)d_in[21];
    const float* fc2W     = (const float*)d_in[22];
    const float* fc2b     = (const float*)d_in[23];
    float* out = (float*)d_out;

    uint32_t* f16  = (uint32_t*)symp(g_f16);
    uint32_t* res16= (uint32_t*)symp(g_res16);
    float* act   = (float*)symp(g_act);
    float* es    = (float*)symp(g_es);
    float* ed    = (float*)symp(g_ed);
    int*   rowp  = (int*)  symp(g_rowptr);
    int*   curs  = (int*)  symp(g_cursor);
    int*   bsum  = (int*)  symp(g_blocksums);
    int*   boff  = (int*)  symp(g_blockoff);
    float* bnacc = (float*)symp(g_bnacc);
    uint32_t* x16  = (uint32_t*)symp(g_x16);
    uint32_t* a216 = (uint32_t*)symp(g_a216);
    uint32_t* w116 = (uint32_t*)symp(g_w116), *r116 = (uint32_t*)symp(g_r116);
    uint32_t* w216 = (uint32_t*)symp(g_w216), *r216 = (uint32_t*)symp(g_r216);

    const int NB = (NN + 255) / 256;
    const int EB = (EE + 255) / 256;
    const int NODEWARP_BLKS = (NN * 32 + 255) / 256;
    dim3 gemm_grid(HC / 64, (NN + 127) / 128);
    const int W1W = HC * DIN / 2, W2W = HC * HC / 2;

    // side stream + fork/join events (host objects; created once, reused —
    // no device memory involved, launches stay identical every call)
    static cudaStream_t s2 = nullptr;
    static cudaEvent_t evFork = nullptr, evJoin = nullptr;
    if (s2 == nullptr) {
        cudaStreamCreateWithFlags(&s2, cudaStreamNonBlocking);
        cudaEventCreateWithFlags(&evFork, cudaEventDisableTiming);
        cudaEventCreateWithFlags(&evJoin, cudaEventDisableTiming);
    }

    // ---- fork: CSR build + L2 weight cvt + bnacc zero on side stream ----
    cudaEventRecord(evFork, 0);
    cudaStreamWaitEvent(s2, evFork, 0);
    zero_int_kernel<<<NB, 256, 0, s2>>>(curs, NN);
    count_deg_kernel<<<EB, 256, 0, s2>>>(edge_idx);
    scan_block_kernel<<<NB, 256, 0, s2>>>(curs, rowp, bsum, NN);
    scan_block_kernel<<<1, 256, 0, s2>>>(bsum, boff, nullptr, NB);
    scan_add_kernel<<<NB, 256, 0, s2>>>(rowp, curs, boff, NN);
    fill_csr_kernel<<<EB, 256, 0, s2>>>(edge_idx);
    zero_float_kernel<<<2, 256, 0, s2>>>(bnacc, 2 * HC);
    wcvt2_kernel<<<dim3((W2W + 255) / 256, 2), 256, 0, s2>>>(W2, res2W, w216, r216, HC);
    cudaEventRecord(evJoin, s2);

    // ---- main stream: prep + GEMM L1 ----
    cvt16_f4_kernel<<<(NN * DIN / 4 + 255) / 256, 256>>>(x, x16, NN * DIN / 4);
    wcvt2_kernel<<<dim3((W1W + 255) / 256, 2), 256>>>(W1, res1W, w116, r116, DIN);
    gemm16_kernel<<<gemm_grid, 256>>>(x16, w116, r116, res1b,
                                      asrc1, adst1, f16, res16, es, ed,
                                      NN, DIN);

    // ---- join: agg needs CSR + bnacc ----
    cudaStreamWaitEvent(0, evJoin, 0);

    // ---- layer 1: agg (+stats) -> finalize -> apply+cvt ----
    agg_kernel<<<NODEWARP_BLKS, 256>>>(f16, es, ed, res16, act);
    bn_finalize_kernel<<<1, HC>>>(bn1g, bn1b);
    zero_float_kernel<<<2, 256>>>(bnacc, 2 * HC);   // reset for layer 2 (after finalize read)
    bn_apply_cvt_kernel<<<(NN * HC / 4 + 255) / 256, 256>>>(act, a216);

    // ---- layer 2 ----
    gemm16_kernel<<<gemm_grid, 256>>>(a216, w216, r216, res2b,
                                      asrc2, adst2, f16, res16, es, ed,
                                      NN, HC);
    agg_kernel<<<NODEWARP_BLKS, 256>>>(f16, es, ed, res16, act);
    bn_finalize_kernel<<<1, HC>>>(bn2g, bn2b);

    // ---- pooling (BN2-apply fused) + MLP ----
    pool_bn_kernel<<<NG, 256>>>(act, batch);
    mlp_kernel<<<NG, 128>>>(fc1W, fc1b, fc2W, fc2b, out);
}

// round 15
// speedup vs baseline: 2.1481x; 1.0403x over previous
#include <cuda_runtime.h>
#include <cuda_fp16.h>
#include <cstdint>

#define NN 50000
#define EE 800000
#define DIN 128
#define NH 4
#define CH 64
#define HC 256
#define NG 512
#define EPSBN 1e-5f
#define SLOPE 0.2f

// ---------------- scratch ----------------
__device__ uint32_t g_f16[(size_t)NN * HC / 2];   // feat fp16x2 (gather source)
__device__ uint32_t g_res16[(size_t)NN * HC / 2]; // residual fp16x2
__device__ uint32_t g_act16[(size_t)NN * HC / 2]; // layer output fp16x2
__device__ float g_es[NN * NH];
__device__ float g_ed[NN * NH];
__device__ int   g_rowptr[NN + 1];
__device__ int   g_cursor[NN];
__device__ int   g_srcsorted[EE];
__device__ int   g_blocksums[256];
__device__ int   g_blockoff[256];
__device__ float g_bnacc[2 * HC];
__device__ float g_bnA[HC];
__device__ float g_bnB[HC];
// fp16 GEMM operand buffers
__device__ uint32_t g_x16[(size_t)NN * DIN / 2];
__device__ uint32_t g_a216[(size_t)NN * HC / 2];
__device__ uint32_t g_w116[HC * DIN / 2], g_r116[HC * DIN / 2];
__device__ uint32_t g_w216[HC * HC / 2],  g_r216[HC * HC / 2];

__device__ __forceinline__ uint32_t f2h2(float2 v) {
    uint32_t r;
    asm("cvt.rn.f16x2.f32 %0, %1, %2;" : "=r"(r) : "f"(v.y), "f"(v.x));
    return r;
}

// ---------------- tiny utility kernels ----------------
__global__ void zero_float_kernel(float* p, int n) {
    int i = blockIdx.x * blockDim.x + threadIdx.x;
    if (i < n) p[i] = 0.0f;
}
__global__ void zero_int_kernel(int* p, int n) {
    int i = blockIdx.x * blockDim.x + threadIdx.x;
    if (i < n) p[i] = 0;
}

// ---------------- prep: fp32 -> fp16 conversions ----------------
__global__ void cvt16_f4_kernel(const float* __restrict__ src,
                                uint32_t* __restrict__ dst, int n4) {
    int i = blockIdx.x * blockDim.x + threadIdx.x;
    if (i >= n4) return;
    float4 v = ((const float4*)src)[i];
    dst[2 * i]     = f2h2(make_float2(v.x, v.y));
    dst[2 * i + 1] = f2h2(make_float2(v.z, v.w));
}

__global__ void wcvt2_kernel(const float* __restrict__ W0, const float* __restrict__ W1,
                             uint32_t* __restrict__ t0, uint32_t* __restrict__ t1,
                             int Kd) {
    const float* W = blockIdx.y ? W1 : W0;
    uint32_t* th = blockIdx.y ? t1 : t0;
    int idx = blockIdx.x * blockDim.x + threadIdx.x;
    int kw = Kd >> 1;
    if (idx >= HC * kw) return;
    int n = idx / kw, kp = idx % kw;
    float a = W[(size_t)(2 * kp) * HC + n];
    float b = W[(size_t)(2 * kp + 1) * HC + n];
    th[idx] = f2h2(make_float2(a, b));
}

// BN+ReLU on fp16 act -> fp16 a216 (layer-2 GEMM input)
__global__ __launch_bounds__(256) void bn_apply_cvt_kernel(const uint32_t* __restrict__ a16,
                                                           uint32_t* __restrict__ dh) {
    int i = blockIdx.x * blockDim.x + threadIdx.x;
    if (i >= NN * HC / 4) return;            // i indexes uint2 (4 channels)
    uint2 w = ((const uint2*)a16)[i];
    int c = (i * 4) & 255;
    float2 p0 = __half22float2(*(const __half2*)&w.x);
    float2 p1 = __half22float2(*(const __half2*)&w.y);
    p0.x = fmaxf(p0.x * g_bnA[c + 0] + g_bnB[c + 0], 0.f);
    p0.y = fmaxf(p0.y * g_bnA[c + 1] + g_bnB[c + 1], 0.f);
    p1.x = fmaxf(p1.x * g_bnA[c + 2] + g_bnB[c + 2], 0.f);
    p1.y = fmaxf(p1.y * g_bnA[c + 3] + g_bnB[c + 3], 0.f);
    uint2 o;
    o.x = f2h2(p0);
    o.y = f2h2(p1);
    ((uint2*)dh)[i] = o;
}

// ---------------- CSR build ----------------
__global__ void count_deg_kernel(const int* __restrict__ ei) {
    int e = blockIdx.x * blockDim.x + threadIdx.x;
    if (e >= EE) return;
    atomicAdd(&g_cursor[ei[EE + e]], 1);
}

__global__ void scan_block_kernel(const int* __restrict__ in, int* __restrict__ out,
                                  int* __restrict__ blocksums, int n) {
    __shared__ int sh[256];
    int tid = threadIdx.x;
    int i = blockIdx.x * 256 + tid;
    int v = (i < n) ? in[i] : 0;
    sh[tid] = v;
    __syncthreads();
    for (int off = 1; off < 256; off <<= 1) {
        int t = (tid >= off) ? sh[tid - off] : 0;
        __syncthreads();
        sh[tid] += t;
        __syncthreads();
    }
    if (i < n) out[i] = sh[tid] - v;
    if (tid == 255 && blocksums) blocksums[blockIdx.x] = sh[255];
}

__global__ void scan_add_kernel(int* __restrict__ rowptr, int* __restrict__ cursor,
                                const int* __restrict__ blockoff, int n) {
    int i = blockIdx.x * 256 + threadIdx.x;
    if (i < n) {
        int v = rowptr[i] + blockoff[blockIdx.x];
        rowptr[i] = v;
        cursor[i] = v;
    }
    if (blockIdx.x == 0 && threadIdx.x == 0) rowptr[n] = EE;
}

__global__ void fill_csr_kernel(const int* __restrict__ ei) {
    int e = blockIdx.x * blockDim.x + threadIdx.x;
    if (e >= EE) return;
    int s = ei[e];
    int d = ei[EE + e];
    int pos = atomicAdd(&g_cursor[d], 1);
    g_srcsorted[pos] = s;
}

// ============================================================================
// Merged-branch fp16 GEMM, 3-stage cp.async pipeline (unchanged from R13/14).
// ============================================================================
#define AST 12
#define NSTAGE 3

__device__ __forceinline__ void mma_f16(float* d, const uint32_t* a,
                                        uint32_t b0, uint32_t b1) {
    asm volatile(
        "mma.sync.aligned.m16n8k16.row.col.f32.f16.f16.f32 "
        "{%0,%1,%2,%3}, {%4,%5,%6,%7}, {%8,%9}, {%0,%1,%2,%3};\n"
        : "+f"(d[0]), "+f"(d[1]), "+f"(d[2]), "+f"(d[3])
        : "r"(a[0]), "r"(a[1]), "r"(a[2]), "r"(a[3]), "r"(b0), "r"(b1));
}

__device__ __forceinline__ void ldsm_x4(uint32_t& r0, uint32_t& r1,
                                        uint32_t& r2, uint32_t& r3, uint32_t saddr) {
    asm volatile("ldmatrix.sync.aligned.m8n8.x4.shared.b16 {%0,%1,%2,%3}, [%4];"
                 : "=r"(r0), "=r"(r1), "=r"(r2), "=r"(r3) : "r"(saddr));
}

__device__ __forceinline__ void cp_async16u(uint32_t* smem_ptr, const uint32_t* gptr, bool pred) {
    uint32_t sa = (uint32_t)__cvta_generic_to_shared(smem_ptr);
    int bytes = pred ? 16 : 0;
    asm volatile("cp.async.ca.shared.global [%0], [%1], 16, %2;\n"
                 :: "r"(sa), "l"(gptr), "r"(bytes));
}

__global__ __launch_bounds__(256, 2) void gemm16_kernel(
    const uint32_t* __restrict__ A16,
    const uint32_t* __restrict__ B16W, const uint32_t* __restrict__ B16R,
    const float* __restrict__ biasR,
    const float* __restrict__ asrc, const float* __restrict__ adst,
    uint32_t* __restrict__ Cf16, uint32_t* __restrict__ Cr16,
    float* __restrict__ es, float* __restrict__ ed,
    int Nr, int K)
{
    __shared__ uint32_t sA[NSTAGE][128 * AST];
    __shared__ uint32_t sBW[NSTAGE][64 * AST];
    __shared__ uint32_t sBR[NSTAGE][64 * AST];
    __shared__ float sEs[128], sEd[128];

    const int Kw = K >> 1;
    const int tid  = threadIdx.x;
    const int lane = tid & 31;
    const int wid  = tid >> 5;
    const int warp_m = wid & 3;
    const int warp_n = wid >> 2;
    const int row0 = blockIdx.y * 128;
    const int col0 = blockIdx.x * 64;

    const int grp = lane >> 2;
    const int tig = lane & 3;

    if (tid < 128) { sEs[tid] = 0.f; sEd[tid] = 0.f; }

    float accW[2][4][4], accR[2][4][4];
#pragma unroll
    for (int mt = 0; mt < 2; mt++)
#pragma unroll
        for (int nt = 0; nt < 4; nt++)
#pragma unroll
            for (int i = 0; i < 4; i++) { accW[mt][nt][i] = 0.f; accR[mt][nt][i] = 0.f; }

    const int a_row = tid >> 1;
    const int a_wof = (tid & 1) * 4;
    const int b_row = (tid & 127) >> 1;
    const int b_wof = (tid & 1) * 4;
    const bool loadW = tid < 128;

    const int T = K / 16;

    const uint32_t sA_a  = (uint32_t)__cvta_generic_to_shared(&sA[0][0]);
    const uint32_t sBW_a = (uint32_t)__cvta_generic_to_shared(&sBW[0][0]);
    const uint32_t sBR_a = (uint32_t)__cvta_generic_to_shared(&sBR[0][0]);
    const uint32_t aoff = ((warp_m * 32 + (lane & 15)) * AST + (lane >> 4) * 4) * 4;
    const uint32_t boff = ((warp_n * 32 + (lane & 7) + ((lane >> 4) << 3)) * AST
                          + ((lane >> 3) & 1) * 4) * 4;
    const uint32_t ABUF = 128 * AST * 4;
    const uint32_t BBUF = 64 * AST * 4;
    const uint32_t MTSTEP = 16 * AST * 4;

    auto load_tile = [&](int it, int buf) {
        int gr = row0 + a_row;
        cp_async16u(&sA[buf][a_row * AST + a_wof],
                    &A16[(size_t)gr * Kw + it * 8 + a_wof], gr < Nr);
        if (loadW)
            cp_async16u(&sBW[buf][b_row * AST + b_wof],
                        &B16W[(size_t)(col0 + b_row) * Kw + it * 8 + b_wof], true);
        else
            cp_async16u(&sBR[buf][b_row * AST + b_wof],
                        &B16R[(size_t)(col0 + b_row) * Kw + it * 8 + b_wof], true);
        asm volatile("cp.async.commit_group;\n");
    };

    load_tile(0, 0);
    if (T > 1) load_tile(1, 1);

    int buf = 0, nbuf = 2;
    for (int it = 0; it < T; it++) {
        if (it + 1 < T) asm volatile("cp.async.wait_group 1;\n");
        else            asm volatile("cp.async.wait_group 0;\n");
        __syncthreads();
        if (it + 2 < T) load_tile(it + 2, nbuf);

        const uint32_t ab  = sA_a  + (uint32_t)buf * ABUF + aoff;
        const uint32_t bbw = sBW_a + (uint32_t)buf * BBUF + boff;
        const uint32_t bbr = sBR_a + (uint32_t)buf * BBUF + boff;

        uint32_t ah[2][4], bh[4][2];
        ldsm_x4(ah[0][0], ah[0][1], ah[0][2], ah[0][3], ab);
        ldsm_x4(ah[1][0], ah[1][1], ah[1][2], ah[1][3], ab + MTSTEP);

        ldsm_x4(bh[0][0], bh[0][1], bh[1][0], bh[1][1], bbw);
        ldsm_x4(bh[2][0], bh[2][1], bh[3][0], bh[3][1], bbw + MTSTEP);
#pragma unroll
        for (int nt = 0; nt < 4; nt++)
#pragma unroll
            for (int mt = 0; mt < 2; mt++)
                mma_f16(accW[mt][nt], ah[mt], bh[nt][0], bh[nt][1]);

        ldsm_x4(bh[0][0], bh[0][1], bh[1][0], bh[1][1], bbr);
        ldsm_x4(bh[2][0], bh[2][1], bh[3][0], bh[3][1], bbr + MTSTEP);
#pragma unroll
        for (int nt = 0; nt < 4; nt++)
#pragma unroll
            for (int mt = 0; mt < 2; mt++)
                mma_f16(accR[mt][nt], ah[mt], bh[nt][0], bh[nt][1]);

        buf = (buf + 1 == NSTAGE) ? 0 : buf + 1;
        nbuf = (nbuf + 1 == NSTAGE) ? 0 : nbuf + 1;
    }

    // ---- C writes (both fp16) ----
#pragma unroll
    for (int mt = 0; mt < 2; mt++) {
        int r = row0 + warp_m * 32 + mt * 16 + grp;
#pragma unroll
        for (int nt = 0; nt < 4; nt++) {
            int c = col0 + warp_n * 32 + nt * 8 + 2 * tig;
            float bx = biasR[c], by = biasR[c + 1];
            if (r < Nr) {
                Cf16[(size_t)r * (HC / 2) + (c >> 1)] =
                    f2h2(make_float2(accW[mt][nt][0], accW[mt][nt][1]));
                Cr16[(size_t)r * (HC / 2) + (c >> 1)] =
                    f2h2(make_float2(accR[mt][nt][0] + bx, accR[mt][nt][1] + by));
            }
            if (r + 8 < Nr) {
                Cf16[(size_t)(r + 8) * (HC / 2) + (c >> 1)] =
                    f2h2(make_float2(accW[mt][nt][2], accW[mt][nt][3]));
                Cr16[(size_t)(r + 8) * (HC / 2) + (c >> 1)] =
                    f2h2(make_float2(accR[mt][nt][2] + bx, accR[mt][nt][3] + by));
            }
        }
    }

    // ---- fused attention dots (from accW) ----
    {
        const int head = blockIdx.x;
        float pes[2][2] = {{0.f, 0.f}, {0.f, 0.f}};
        float ped[2][2] = {{0.f, 0.f}, {0.f, 0.f}};
#pragma unroll
        for (int mt = 0; mt < 2; mt++)
#pragma unroll
            for (int nt = 0; nt < 4; nt++) {
                int cl = warp_n * 32 + nt * 8 + 2 * tig;
                float a0 = asrc[head * CH + cl], a1 = asrc[head * CH + cl + 1];
                float d0 = adst[head * CH + cl], d1 = adst[head * CH + cl + 1];
                pes[mt][0] += accW[mt][nt][0] * a0 + accW[mt][nt][1] * a1;
                pes[mt][1] += accW[mt][nt][2] * a0 + accW[mt][nt][3] * a1;
                ped[mt][0] += accW[mt][nt][0] * d0 + accW[mt][nt][1] * d1;
                ped[mt][1] += accW[mt][nt][2] * d0 + accW[mt][nt][3] * d1;
            }
#pragma unroll
        for (int o = 1; o <= 2; o <<= 1) {
#pragma unroll
            for (int mt = 0; mt < 2; mt++)
#pragma unroll
                for (int hh = 0; hh < 2; hh++) {
                    pes[mt][hh] += __shfl_xor_sync(0xffffffffu, pes[mt][hh], o);
                    ped[mt][hh] += __shfl_xor_sync(0xffffffffu, ped[mt][hh], o);
                }
        }
        if (tig == 0) {
#pragma unroll
            for (int mt = 0; mt < 2; mt++)
#pragma unroll
                for (int hh = 0; hh < 2; hh++) {
                    int lr = warp_m * 32 + mt * 16 + hh * 8 + grp;
                    atomicAdd(&sEs[lr], pes[mt][hh]);
                    atomicAdd(&sEd[lr], ped[mt][hh]);
                }
        }
        __syncthreads();
        if (tid < 128) {
            int node = row0 + tid;
            if (node < Nr) {
                es[node * NH + head] = sEs[tid];
                ed[node * NH + head] = sEd[tid];
            }
        }
    }
}

// ============================================================================
// GAT softmax + aggregate + fused BN statistics; fp16 act output; 4-wide gather.
// ============================================================================
__device__ __forceinline__ void acc_edge(float* acc, const uint4& v, float w) {
    float2 p;
    p = __half22float2(*(const __half2*)&v.x); acc[0] += w * p.x; acc[1] += w * p.y;
    p = __half22float2(*(const __half2*)&v.y); acc[2] += w * p.x; acc[3] += w * p.y;
    p = __half22float2(*(const __half2*)&v.z); acc[4] += w * p.x; acc[5] += w * p.y;
    p = __half22float2(*(const __half2*)&v.w); acc[6] += w * p.x; acc[7] += w * p.y;
}

__global__ __launch_bounds__(256) void agg_kernel(
    const uint32_t* __restrict__ f16, const float* __restrict__ es,
    const float* __restrict__ ed,
    const uint32_t* __restrict__ res16, uint32_t* __restrict__ out16)
{
    __shared__ float ssum[8][HC];
    __shared__ float ssq [8][HC];

    int node = (blockIdx.x * blockDim.x + threadIdx.x) >> 5;
    int lane = threadIdx.x & 31;
    int wwid = threadIdx.x >> 5;
    int head = lane >> 3;
    int j    = lane & 7;
    bool valid = node < NN;

    float o[8];
#pragma unroll
    for (int i = 0; i < 8; i++) o[i] = 0.f;

    if (valid) {
        int s0 = g_rowptr[node], s1 = g_rowptr[node + 1];
        float acc[8];
#pragma unroll
        for (int i = 0; i < 8; i++) acc[i] = 0.f;

        if (s1 > s0) {
            float edv = ed[node * NH + head];
            float m = -INFINITY, den = 0.f;
            for (int k = s0 + j; k < s1; k += 8) {
                int s = g_srcsorted[k];
                float e = es[s * NH + head] + edv;
                e = (e >= 0.f) ? e : SLOPE * e;
                if (e > m) { den = den * __expf(m - e) + 1.f; m = e; }
                else den += __expf(e - m);
            }
#pragma unroll
            for (int oo = 1; oo <= 4; oo <<= 1) {
                float mo  = __shfl_xor_sync(0xffffffffu, m, oo);
                float dno = __shfl_xor_sync(0xffffffffu, den, oo);
                float nm = fmaxf(m, mo);
                float f1 = (m == nm) ? 1.f : __expf(m - nm);
                float f2 = (mo == nm) ? 1.f : __expf(mo - nm);
                den = den * f1 + dno * f2;
                m = nm;
            }
            float inv = 1.f / (den + 1e-16f);

            int k = s0;
            for (; k + 4 <= s1; k += 4) {
                int sa = g_srcsorted[k];
                int sb = g_srcsorted[k + 1];
                int sc = g_srcsorted[k + 2];
                int sd = g_srcsorted[k + 3];
                uint4 va = *(const uint4*)&f16[(size_t)sa * (HC / 2) + 4 * lane];
                uint4 vb = *(const uint4*)&f16[(size_t)sb * (HC / 2) + 4 * lane];
                uint4 vc = *(const uint4*)&f16[(size_t)sc * (HC / 2) + 4 * lane];
                uint4 vd = *(const uint4*)&f16[(size_t)sd * (HC / 2) + 4 * lane];
                float ea = es[sa * NH + head] + edv;
                float eb = es[sb * NH + head] + edv;
                float ec = es[sc * NH + head] + edv;
                float eD = es[sd * NH + head] + edv;
                ea = (ea >= 0.f) ? ea : SLOPE * ea;
                eb = (eb >= 0.f) ? eb : SLOPE * eb;
                ec = (ec >= 0.f) ? ec : SLOPE * ec;
                eD = (eD >= 0.f) ? eD : SLOPE * eD;
                acc_edge(acc, va, __expf(ea - m) * inv);
                acc_edge(acc, vb, __expf(eb - m) * inv);
                acc_edge(acc, vc, __expf(ec - m) * inv);
                acc_edge(acc, vd, __expf(eD - m) * inv);
            }
            for (; k < s1; k++) {
                int sa = g_srcsorted[k];
                uint4 va = *(const uint4*)&f16[(size_t)sa * (HC / 2) + 4 * lane];
                float ea = es[sa * NH + head] + edv;
                ea = (ea >= 0.f) ? ea : SLOPE * ea;
                acc_edge(acc, va, __expf(ea - m) * inv);
            }
        }

        uint4 rv = *(const uint4*)&res16[(size_t)node * (HC / 2) + 4 * lane];
        float2 r0 = __half22float2(*(const __half2*)&rv.x);
        float2 r1 = __half22float2(*(const __half2*)&rv.y);
        float2 r2 = __half22float2(*(const __half2*)&rv.z);
        float2 r3 = __half22float2(*(const __half2*)&rv.w);
        o[0] = acc[0] + r0.x; o[1] = acc[1] + r0.y;
        o[2] = acc[2] + r1.x; o[3] = acc[3] + r1.y;
        o[4] = acc[4] + r2.x; o[5] = acc[5] + r2.y;
        o[6] = acc[6] + r3.x; o[7] = acc[7] + r3.y;

        uint4 ov;
        ov.x = f2h2(make_float2(o[0], o[1]));
        ov.y = f2h2(make_float2(o[2], o[3]));
        ov.z = f2h2(make_float2(o[4], o[5]));
        ov.w = f2h2(make_float2(o[6], o[7]));
        *(uint4*)&out16[(size_t)node * (HC / 2) + 4 * lane] = ov;
    }

    // ---- fused BN statistics ----
    {
        int cb = 8 * lane;
#pragma unroll
        for (int i = 0; i < 8; i++) {
            ssum[wwid][cb + i] = o[i];
            ssq [wwid][cb + i] = o[i] * o[i];
        }
        __syncthreads();
        int t = threadIdx.x;
        float S = 0.f, Q = 0.f;
#pragma unroll
        for (int w = 0; w < 8; w++) { S += ssum[w][t]; Q += ssq[w][t]; }
        atomicAdd(&g_bnacc[t], S);
        atomicAdd(&g_bnacc[t + HC], Q);
    }
}

// ---------------- BatchNorm finalize (+zeroes bnacc for next layer) ----------
__global__ void bn_finalize_kernel(const float* __restrict__ gma, const float* __restrict__ beta) {
    int c = threadIdx.x;
    float mean = g_bnacc[c] / (float)NN;
    float var  = g_bnacc[c + HC] / (float)NN - mean * mean;
    float a = gma[c] * rsqrtf(var + EPSBN);
    g_bnA[c] = a;
    g_bnB[c] = beta[c] - mean * a;
    g_bnacc[c] = 0.f;
    g_bnacc[c + HC] = 0.f;
}

// ---------------- fused pooling(BN2+ReLU) + MLP -------------------------------
// 512 blocks x 128 threads. Thread t owns channels 2t, 2t+1 for pooling,
// then computes fc1 output t, then fc2 reduction.
__global__ __launch_bounds__(128) void pool_mlp_kernel(
    const uint32_t* __restrict__ act16, const int* __restrict__ batch,
    const float* __restrict__ fc1W, const float* __restrict__ fc1b,
    const float* __restrict__ fc2W, const float* __restrict__ fc2b,
    float* __restrict__ out)
{
    __shared__ float row[HC];
    __shared__ float red[128];
    __shared__ int s_lo, s_hi;
    int g = blockIdx.x, t = threadIdx.x;
    if (t == 0) {
        int lo = 0, hi = NN;
        while (lo < hi) { int mid = (lo + hi) >> 1; if (batch[mid] < g) lo = mid + 1; else hi = mid; }
        s_lo = lo;
        int lo2 = lo; hi = NN;
        while (lo2 < hi) { int mid = (lo2 + hi) >> 1; if (batch[mid] < g + 1) lo2 = mid + 1; else hi = mid; }
        s_hi = lo2;
    }
    __syncthreads();
    int lo = s_lo, hi = s_hi;
    float A0 = g_bnA[2 * t],     B0 = g_bnB[2 * t];
    float A1 = g_bnA[2 * t + 1], B1 = g_bnB[2 * t + 1];
    float sx = 0.f, sy = 0.f;
    for (int r = lo; r < hi; r++) {
        uint32_t w = act16[(size_t)r * (HC / 2) + t];
        float2 p = __half22float2(*(const __half2*)&w);
        sx += fmaxf(p.x * A0 + B0, 0.f);
        sy += fmaxf(p.y * A1 + B1, 0.f);
    }
    float inv = (hi > lo) ? 1.0f / (float)(hi - lo) : 0.0f;
    row[2 * t]     = sx * inv;
    row[2 * t + 1] = sy * inv;
    __syncthreads();

    float a = fc1b[t];
#pragma unroll 8
    for (int k = 0; k < HC; k++) a += row[k] * fc1W[k * 128 + t];
    a = fmaxf(a, 0.f);
    for (int jj = 0; jj < 2; jj++) {
        red[t] = a * fc2W[t * 2 + jj];
        __syncthreads();
        for (int off = 64; off; off >>= 1) {
            if (t < off) red[t] += red[t + off];
            __syncthreads();
        }
        if (t == 0) out[g * 2 + jj] = red[0] + fc2b[jj];
        __syncthreads();
    }
}

// ---------------- host side ----------------
static void* symp(const void* sym) {
    void* p = nullptr;
    cudaGetSymbolAddress(&p, sym);
    return p;
}

extern "C" void kernel_launch(void* const* d_in, const int* in_sizes, int n_in,
                              void* d_out, int out_size)
{
    const float* x        = (const float*)d_in[0];
    const int*   edge_idx = (const int*)  d_in[1];
    const int*   batch    = (const int*)  d_in[3];
    const float* W1       = (const float*)d_in[4];
    const float* asrc1    = (const float*)d_in[5];
    const float* adst1    = (const float*)d_in[6];
    const float* b1       = (const float*)d_in[7];
    const float* res1W    = (const float*)d_in[8];
    const float* res1b    = (const float*)d_in[9];
    const float* bn1g     = (const float*)d_in[10];
    const float* bn1b     = (const float*)d_in[11];
    const float* W2       = (const float*)d_in[12];
    const float* asrc2    = (const float*)d_in[13];
    const float* adst2    = (const float*)d_in[14];
    const float* b2       = (const float*)d_in[15];
    const float* res2W    = (const float*)d_in[16];
    const float* res2b    = (const float*)d_in[17];
    const float* bn2g     = (const float*)d_in[18];
    const float* bn2b     = (const float*)d_in[19];
    const float* fc1W     = (const float*)d_in[20];
    const float* fc1b     = (const float*)d_in[21];
    const float* fc2W     = (const float*)d_in[22];
    const float* fc2b     = (const float*)d_in[23];
    float* out = (float*)d_out;

    uint32_t* f16  = (uint32_t*)symp(g_f16);
    uint32_t* res16= (uint32_t*)symp(g_res16);
    uint32_t* act16= (uint32_t*)symp(g_act16);
    float* es    = (float*)symp(g_es);
    float* ed    = (float*)symp(g_ed);
    int*   rowp  = (int*)  symp(g_rowptr);
    int*   curs  = (int*)  symp(g_cursor);
    int*   bsum  = (int*)  symp(g_blocksums);
    int*   boff  = (int*)  symp(g_blockoff);
    float* bnacc = (float*)symp(g_bnacc);
    uint32_t* x16  = (uint32_t*)symp(g_x16);
    uint32_t* a216 = (uint32_t*)symp(g_a216);
    uint32_t* w116 = (uint32_t*)symp(g_w116), *r116 = (uint32_t*)symp(g_r116);
    uint32_t* w216 = (uint32_t*)symp(g_w216), *r216 = (uint32_t*)symp(g_r216);

    const int NB = (NN + 255) / 256;
    const int EB = (EE + 255) / 256;
    const int NODEWARP_BLKS = (NN * 32 + 255) / 256;
    dim3 gemm_grid(HC / 64, (NN + 127) / 128);
    const int W1W = HC * DIN / 2, W2W = HC * HC / 2;

    static cudaStream_t s2 = nullptr;
    static cudaEvent_t evFork = nullptr, evJoin = nullptr;
    if (s2 == nullptr) {
        cudaStreamCreateWithFlags(&s2, cudaStreamNonBlocking);
        cudaEventCreateWithFlags(&evFork, cudaEventDisableTiming);
        cudaEventCreateWithFlags(&evJoin, cudaEventDisableTiming);
    }

    // ---- fork: CSR build + L2 weight cvt + bnacc zero on side stream ----
    cudaEventRecord(evFork, 0);
    cudaStreamWaitEvent(s2, evFork, 0);
    zero_int_kernel<<<NB, 256, 0, s2>>>(curs, NN);
    count_deg_kernel<<<EB, 256, 0, s2>>>(edge_idx);
    scan_block_kernel<<<NB, 256, 0, s2>>>(curs, rowp, bsum, NN);
    scan_block_kernel<<<1, 256, 0, s2>>>(bsum, boff, nullptr, NB);
    scan_add_kernel<<<NB, 256, 0, s2>>>(rowp, curs, boff, NN);
    fill_csr_kernel<<<EB, 256, 0, s2>>>(edge_idx);
    zero_float_kernel<<<2, 256, 0, s2>>>(bnacc, 2 * HC);
    wcvt2_kernel<<<dim3((W2W + 255) / 256, 2), 256, 0, s2>>>(W2, res2W, w216, r216, HC);
    cudaEventRecord(evJoin, s2);

    // ---- main stream: prep + GEMM L1 ----
    cvt16_f4_kernel<<<(NN * DIN / 4 + 255) / 256, 256>>>(x, x16, NN * DIN / 4);
    wcvt2_kernel<<<dim3((W1W + 255) / 256, 2), 256>>>(W1, res1W, w116, r116, DIN);
    gemm16_kernel<<<gemm_grid, 256>>>(x16, w116, r116, res1b,
                                      asrc1, adst1, f16, res16, es, ed,
                                      NN, DIN);

    // ---- join: agg needs CSR + bnacc ----
    cudaStreamWaitEvent(0, evJoin, 0);

    // ---- layer 1: agg (+stats, fp16 out) -> finalize(+zero) -> apply+cvt ----
    agg_kernel<<<NODEWARP_BLKS, 256>>>(f16, es, ed, res16, act16);
    bn_finalize_kernel<<<1, HC>>>(bn1g, bn1b);
    bn_apply_cvt_kernel<<<(NN * HC / 4 + 255) / 256, 256>>>(act16, a216);

    // ---- layer 2 ----
    gemm16_kernel<<<gemm_grid, 256>>>(a216, w216, r216, res2b,
                                      asrc2, adst2, f16, res16, es, ed,
                                      NN, HC);
    agg_kernel<<<NODEWARP_BLKS, 256>>>(f16, es, ed, res16, act16);
    bn_finalize_kernel<<<1, HC>>>(bn2g, bn2b);

    // ---- fused pooling(BN2) + MLP ----
    pool_mlp_kernel<<<NG, 128>>>(act16, batch, fc1W, fc1b, fc2W, fc2b, out);
}

// round 16
// speedup vs baseline: 2.2035x; 1.0258x over previous
#include <cuda_runtime.h>
#include <cuda_fp16.h>
#include <cstdint>

#define NN 50000
#define EE 800000
#define DIN 128
#define NH 4
#define CH 64
#define HC 256
#define NG 512
#define EPSBN 1e-5f
#define SLOPE 0.2f

// ---------------- scratch ----------------
__device__ uint32_t g_f16[(size_t)NN * HC / 2];   // feat fp16x2 (gather source)
__device__ uint32_t g_res16[(size_t)NN * HC / 2]; // residual fp16x2
__device__ uint32_t g_act16[(size_t)NN * HC / 2]; // layer output fp16x2
__device__ float g_es[NN * NH];
__device__ float g_ed[NN * NH];
__device__ int   g_rowptr[NN + 1];
__device__ int   g_cursor[NN];
__device__ int   g_srcsorted[EE];
__device__ int   g_blocksums[256];
__device__ int   g_blockoff[256];
__device__ float g_bnacc[4 * HC];                 // [layer][sum|sq][HC]
// fp16 GEMM operand buffers
__device__ uint32_t g_x16[(size_t)NN * DIN / 2];
__device__ uint32_t g_a216[(size_t)NN * HC / 2];
__device__ uint32_t g_w116[HC * DIN / 2], g_r116[HC * DIN / 2];
__device__ uint32_t g_w216[HC * HC / 2],  g_r216[HC * HC / 2];

__device__ __forceinline__ uint32_t f2h2(float2 v) {
    uint32_t r;
    asm("cvt.rn.f16x2.f32 %0, %1, %2;" : "=r"(r) : "f"(v.y), "f"(v.x));
    return r;
}

// ---------------- tiny utility kernels ----------------
__global__ void zero_float_kernel(float* p, int n) {
    int i = blockIdx.x * blockDim.x + threadIdx.x;
    if (i < n) p[i] = 0.0f;
}
__global__ void zero_int_kernel(int* p, int n) {
    int i = blockIdx.x * blockDim.x + threadIdx.x;
    if (i < n) p[i] = 0;
}

// ---------------- merged prep: x fp32->fp16 AND W1/res1W convert ----------------
#define NXCHUNK (NN * DIN / 4)
__global__ void prep1_kernel(const float* __restrict__ x, uint32_t* __restrict__ x16,
                             const float* __restrict__ W0, const float* __restrict__ W1,
                             uint32_t* __restrict__ t0, uint32_t* __restrict__ t1) {
    int idx = blockIdx.x * blockDim.x + threadIdx.x;
    if (idx < NXCHUNK) {
        float4 v = ((const float4*)x)[idx];
        x16[2 * idx]     = f2h2(make_float2(v.x, v.y));
        x16[2 * idx + 1] = f2h2(make_float2(v.z, v.w));
        return;
    }
    int j = idx - NXCHUNK;
    const int W1W = HC * DIN / 2;       // 16384 words per weight
    if (j >= 2 * W1W) return;
    const float* W = (j >= W1W) ? W1 : W0;
    uint32_t* th = (j >= W1W) ? t1 : t0;
    int widx = (j >= W1W) ? j - W1W : j;
    const int kw = DIN / 2;
    int n = widx / kw, kp = widx % kw;
    float a = W[(size_t)(2 * kp) * HC + n];
    float b = W[(size_t)(2 * kp + 1) * HC + n];
    th[widx] = f2h2(make_float2(a, b));
}

// layer-2 weights (side stream)
__global__ void wcvt2_kernel(const float* __restrict__ W0, const float* __restrict__ W1,
                             uint32_t* __restrict__ t0, uint32_t* __restrict__ t1,
                             int Kd) {
    const float* W = blockIdx.y ? W1 : W0;
    uint32_t* th = blockIdx.y ? t1 : t0;
    int idx = blockIdx.x * blockDim.x + threadIdx.x;
    int kw = Kd >> 1;
    if (idx >= HC * kw) return;
    int n = idx / kw, kp = idx % kw;
    float a = W[(size_t)(2 * kp) * HC + n];
    float b = W[(size_t)(2 * kp + 1) * HC + n];
    th[idx] = f2h2(make_float2(a, b));
}

// BN(inline finalize)+ReLU on fp16 act -> fp16 a216
__global__ __launch_bounds__(256) void bn_apply_cvt_kernel(
    const uint32_t* __restrict__ a16, uint32_t* __restrict__ dh,
    const float* __restrict__ gma, const float* __restrict__ beta,
    const float* __restrict__ bnacc)
{
    __shared__ float sA[HC], sB[HC];
    int t = threadIdx.x;
    {
        float mean = bnacc[t] * (1.0f / NN);
        float var  = bnacc[t + HC] * (1.0f / NN) - mean * mean;
        float a = gma[t] * rsqrtf(var + EPSBN);
        sA[t] = a;
        sB[t] = beta[t] - mean * a;
    }
    __syncthreads();
    int i = blockIdx.x * 256 + t;
    if (i >= NN * HC / 4) return;
    uint2 w = ((const uint2*)a16)[i];
    int c = (i * 4) & 255;
    float2 p0 = __half22float2(*(const __half2*)&w.x);
    float2 p1 = __half22float2(*(const __half2*)&w.y);
    p0.x = fmaxf(p0.x * sA[c + 0] + sB[c + 0], 0.f);
    p0.y = fmaxf(p0.y * sA[c + 1] + sB[c + 1], 0.f);
    p1.x = fmaxf(p1.x * sA[c + 2] + sB[c + 2], 0.f);
    p1.y = fmaxf(p1.y * sA[c + 3] + sB[c + 3], 0.f);
    uint2 o;
    o.x = f2h2(p0);
    o.y = f2h2(p1);
    ((uint2*)dh)[i] = o;
}

// ---------------- CSR build ----------------
__global__ void count_deg_kernel(const int* __restrict__ ei) {
    int e = blockIdx.x * blockDim.x + threadIdx.x;
    if (e >= EE) return;
    atomicAdd(&g_cursor[ei[EE + e]], 1);
}

__global__ void scan_block_kernel(const int* __restrict__ in, int* __restrict__ out,
                                  int* __restrict__ blocksums, int n) {
    __shared__ int sh[256];
    int tid = threadIdx.x;
    int i = blockIdx.x * 256 + tid;
    int v = (i < n) ? in[i] : 0;
    sh[tid] = v;
    __syncthreads();
    for (int off = 1; off < 256; off <<= 1) {
        int t = (tid >= off) ? sh[tid - off] : 0;
        __syncthreads();
        sh[tid] += t;
        __syncthreads();
    }
    if (i < n) out[i] = sh[tid] - v;
    if (tid == 255 && blocksums) blocksums[blockIdx.x] = sh[255];
}

__global__ void scan_add_kernel(int* __restrict__ rowptr, int* __restrict__ cursor,
                                const int* __restrict__ blockoff, int n) {
    int i = blockIdx.x * 256 + threadIdx.x;
    if (i < n) {
        int v = rowptr[i] + blockoff[blockIdx.x];
        rowptr[i] = v;
        cursor[i] = v;
    }
    if (blockIdx.x == 0 && threadIdx.x == 0) rowptr[n] = EE;
}

__global__ void fill_csr_kernel(const int* __restrict__ ei) {
    int e = blockIdx.x * blockDim.x + threadIdx.x;
    if (e >= EE) return;
    int s = ei[e];
    int d = ei[EE + e];
    int pos = atomicAdd(&g_cursor[d], 1);
    g_srcsorted[pos] = s;
}

// ============================================================================
// Merged-branch fp16 GEMM, 3-stage cp.async pipeline (unchanged).
// ============================================================================
#define AST 12
#define NSTAGE 3

__device__ __forceinline__ void mma_f16(float* d, const uint32_t* a,
                                        uint32_t b0, uint32_t b1) {
    asm volatile(
        "mma.sync.aligned.m16n8k16.row.col.f32.f16.f16.f32 "
        "{%0,%1,%2,%3}, {%4,%5,%6,%7}, {%8,%9}, {%0,%1,%2,%3};\n"
        : "+f"(d[0]), "+f"(d[1]), "+f"(d[2]), "+f"(d[3])
        : "r"(a[0]), "r"(a[1]), "r"(a[2]), "r"(a[3]), "r"(b0), "r"(b1));
}

__device__ __forceinline__ void ldsm_x4(uint32_t& r0, uint32_t& r1,
                                        uint32_t& r2, uint32_t& r3, uint32_t saddr) {
    asm volatile("ldmatrix.sync.aligned.m8n8.x4.shared.b16 {%0,%1,%2,%3}, [%4];"
                 : "=r"(r0), "=r"(r1), "=r"(r2), "=r"(r3) : "r"(saddr));
}

__device__ __forceinline__ void cp_async16u(uint32_t* smem_ptr, const uint32_t* gptr, bool pred) {
    uint32_t sa = (uint32_t)__cvta_generic_to_shared(smem_ptr);
    int bytes = pred ? 16 : 0;
    asm volatile("cp.async.ca.shared.global [%0], [%1], 16, %2;\n"
                 :: "r"(sa), "l"(gptr), "r"(bytes));
}

__global__ __launch_bounds__(256, 2) void gemm16_kernel(
    const uint32_t* __restrict__ A16,
    const uint32_t* __restrict__ B16W, const uint32_t* __restrict__ B16R,
    const float* __restrict__ biasR,
    const float* __restrict__ asrc, const float* __restrict__ adst,
    uint32_t* __restrict__ Cf16, uint32_t* __restrict__ Cr16,
    float* __restrict__ es, float* __restrict__ ed,
    int Nr, int K)
{
    __shared__ uint32_t sA[NSTAGE][128 * AST];
    __shared__ uint32_t sBW[NSTAGE][64 * AST];
    __shared__ uint32_t sBR[NSTAGE][64 * AST];
    __shared__ float sEs[128], sEd[128];

    const int Kw = K >> 1;
    const int tid  = threadIdx.x;
    const int lane = tid & 31;
    const int wid  = tid >> 5;
    const int warp_m = wid & 3;
    const int warp_n = wid >> 2;
    const int row0 = blockIdx.y * 128;
    const int col0 = blockIdx.x * 64;

    const int grp = lane >> 2;
    const int tig = lane & 3;

    if (tid < 128) { sEs[tid] = 0.f; sEd[tid] = 0.f; }

    float accW[2][4][4], accR[2][4][4];
#pragma unroll
    for (int mt = 0; mt < 2; mt++)
#pragma unroll
        for (int nt = 0; nt < 4; nt++)
#pragma unroll
            for (int i = 0; i < 4; i++) { accW[mt][nt][i] = 0.f; accR[mt][nt][i] = 0.f; }

    const int a_row = tid >> 1;
    const int a_wof = (tid & 1) * 4;
    const int b_row = (tid & 127) >> 1;
    const int b_wof = (tid & 1) * 4;
    const bool loadW = tid < 128;

    const int T = K / 16;

    const uint32_t sA_a  = (uint32_t)__cvta_generic_to_shared(&sA[0][0]);
    const uint32_t sBW_a = (uint32_t)__cvta_generic_to_shared(&sBW[0][0]);
    const uint32_t sBR_a = (uint32_t)__cvta_generic_to_shared(&sBR[0][0]);
    const uint32_t aoff = ((warp_m * 32 + (lane & 15)) * AST + (lane >> 4) * 4) * 4;
    const uint32_t boff = ((warp_n * 32 + (lane & 7) + ((lane >> 4) << 3)) * AST
                          + ((lane >> 3) & 1) * 4) * 4;
    const uint32_t ABUF = 128 * AST * 4;
    const uint32_t BBUF = 64 * AST * 4;
    const uint32_t MTSTEP = 16 * AST * 4;

    auto load_tile = [&](int it, int buf) {
        int gr = row0 + a_row;
        cp_async16u(&sA[buf][a_row * AST + a_wof],
                    &A16[(size_t)gr * Kw + it * 8 + a_wof], gr < Nr);
        if (loadW)
            cp_async16u(&sBW[buf][b_row * AST + b_wof],
                        &B16W[(size_t)(col0 + b_row) * Kw + it * 8 + b_wof], true);
        else
            cp_async16u(&sBR[buf][b_row * AST + b_wof],
                        &B16R[(size_t)(col0 + b_row) * Kw + it * 8 + b_wof], true);
        asm volatile("cp.async.commit_group;\n");
    };

    load_tile(0, 0);
    if (T > 1) load_tile(1, 1);

    int buf = 0, nbuf = 2;
    for (int it = 0; it < T; it++) {
        if (it + 1 < T) asm volatile("cp.async.wait_group 1;\n");
        else            asm volatile("cp.async.wait_group 0;\n");
        __syncthreads();
        if (it + 2 < T) load_tile(it + 2, nbuf);

        const uint32_t ab  = sA_a  + (uint32_t)buf * ABUF + aoff;
        const uint32_t bbw = sBW_a + (uint32_t)buf * BBUF + boff;
        const uint32_t bbr = sBR_a + (uint32_t)buf * BBUF + boff;

        uint32_t ah[2][4], bh[4][2];
        ldsm_x4(ah[0][0], ah[0][1], ah[0][2], ah[0][3], ab);
        ldsm_x4(ah[1][0], ah[1][1], ah[1][2], ah[1][3], ab + MTSTEP);

        ldsm_x4(bh[0][0], bh[0][1], bh[1][0], bh[1][1], bbw);
        ldsm_x4(bh[2][0], bh[2][1], bh[3][0], bh[3][1], bbw + MTSTEP);
#pragma unroll
        for (int nt = 0; nt < 4; nt++)
#pragma unroll
            for (int mt = 0; mt < 2; mt++)
                mma_f16(accW[mt][nt], ah[mt], bh[nt][0], bh[nt][1]);

        ldsm_x4(bh[0][0], bh[0][1], bh[1][0], bh[1][1], bbr);
        ldsm_x4(bh[2][0], bh[2][1], bh[3][0], bh[3][1], bbr + MTSTEP);
#pragma unroll
        for (int nt = 0; nt < 4; nt++)
#pragma unroll
            for (int mt = 0; mt < 2; mt++)
                mma_f16(accR[mt][nt], ah[mt], bh[nt][0], bh[nt][1]);

        buf = (buf + 1 == NSTAGE) ? 0 : buf + 1;
        nbuf = (nbuf + 1 == NSTAGE) ? 0 : nbuf + 1;
    }

    // ---- C writes (both fp16) ----
#pragma unroll
    for (int mt = 0; mt < 2; mt++) {
        int r = row0 + warp_m * 32 + mt * 16 + grp;
#pragma unroll
        for (int nt = 0; nt < 4; nt++) {
            int c = col0 + warp_n * 32 + nt * 8 + 2 * tig;
            float bx = biasR[c], by = biasR[c + 1];
            if (r < Nr) {
                Cf16[(size_t)r * (HC / 2) + (c >> 1)] =
                    f2h2(make_float2(accW[mt][nt][0], accW[mt][nt][1]));
                Cr16[(size_t)r * (HC / 2) + (c >> 1)] =
                    f2h2(make_float2(accR[mt][nt][0] + bx, accR[mt][nt][1] + by));
            }
            if (r + 8 < Nr) {
                Cf16[(size_t)(r + 8) * (HC / 2) + (c >> 1)] =
                    f2h2(make_float2(accW[mt][nt][2], accW[mt][nt][3]));
                Cr16[(size_t)(r + 8) * (HC / 2) + (c >> 1)] =
                    f2h2(make_float2(accR[mt][nt][2] + bx, accR[mt][nt][3] + by));
            }
        }
    }

    // ---- fused attention dots (from accW) ----
    {
        const int head = blockIdx.x;
        float pes[2][2] = {{0.f, 0.f}, {0.f, 0.f}};
        float ped[2][2] = {{0.f, 0.f}, {0.f, 0.f}};
#pragma unroll
        for (int mt = 0; mt < 2; mt++)
#pragma unroll
            for (int nt = 0; nt < 4; nt++) {
                int cl = warp_n * 32 + nt * 8 + 2 * tig;
                float a0 = asrc[head * CH + cl], a1 = asrc[head * CH + cl + 1];
                float d0 = adst[head * CH + cl], d1 = adst[head * CH + cl + 1];
                pes[mt][0] += accW[mt][nt][0] * a0 + accW[mt][nt][1] * a1;
                pes[mt][1] += accW[mt][nt][2] * a0 + accW[mt][nt][3] * a1;
                ped[mt][0] += accW[mt][nt][0] * d0 + accW[mt][nt][1] * d1;
                ped[mt][1] += accW[mt][nt][2] * d0 + accW[mt][nt][3] * d1;
            }
#pragma unroll
        for (int o = 1; o <= 2; o <<= 1) {
#pragma unroll
            for (int mt = 0; mt < 2; mt++)
#pragma unroll
                for (int hh = 0; hh < 2; hh++) {
                    pes[mt][hh] += __shfl_xor_sync(0xffffffffu, pes[mt][hh], o);
                    ped[mt][hh] += __shfl_xor_sync(0xffffffffu, ped[mt][hh], o);
                }
        }
        if (tig == 0) {
#pragma unroll
            for (int mt = 0; mt < 2; mt++)
#pragma unroll
                for (int hh = 0; hh < 2; hh++) {
                    int lr = warp_m * 32 + mt * 16 + hh * 8 + grp;
                    atomicAdd(&sEs[lr], pes[mt][hh]);
                    atomicAdd(&sEd[lr], ped[mt][hh]);
                }
        }
        __syncthreads();
        if (tid < 128) {
            int node = row0 + tid;
            if (node < Nr) {
                es[node * NH + head] = sEs[tid];
                ed[node * NH + head] = sEd[tid];
            }
        }
    }
}

// ============================================================================
// GAT softmax + aggregate + fused BN statistics; fp16 act output; 4-wide gather.
// bnacc selects the layer's stats buffer.
// ============================================================================
__device__ __forceinline__ void acc_edge(float* acc, const uint4& v, float w) {
    float2 p;
    p = __half22float2(*(const __half2*)&v.x); acc[0] += w * p.x; acc[1] += w * p.y;
    p = __half22float2(*(const __half2*)&v.y); acc[2] += w * p.x; acc[3] += w * p.y;
    p = __half22float2(*(const __half2*)&v.z); acc[4] += w * p.x; acc[5] += w * p.y;
    p = __half22float2(*(const __half2*)&v.w); acc[6] += w * p.x; acc[7] += w * p.y;
}

__global__ __launch_bounds__(256) void agg_kernel(
    const uint32_t* __restrict__ f16, const float* __restrict__ es,
    const float* __restrict__ ed,
    const uint32_t* __restrict__ res16, uint32_t* __restrict__ out16,
    float* __restrict__ bnacc)
{
    __shared__ float ssum[8][HC];
    __shared__ float ssq [8][HC];

    int node = (blockIdx.x * blockDim.x + threadIdx.x) >> 5;
    int lane = threadIdx.x & 31;
    int wwid = threadIdx.x >> 5;
    int head = lane >> 3;
    int j    = lane & 7;
    bool valid = node < NN;

    float o[8];
#pragma unroll
    for (int i = 0; i < 8; i++) o[i] = 0.f;

    if (valid) {
        int s0 = g_rowptr[node], s1 = g_rowptr[node + 1];
        float acc[8];
#pragma unroll
        for (int i = 0; i < 8; i++) acc[i] = 0.f;

        if (s1 > s0) {
            float edv = ed[node * NH + head];
            float m = -INFINITY, den = 0.f;
            for (int k = s0 + j; k < s1; k += 8) {
                int s = g_srcsorted[k];
                float e = es[s * NH + head] + edv;
                e = (e >= 0.f) ? e : SLOPE * e;
                if (e > m) { den = den * __expf(m - e) + 1.f; m = e; }
                else den += __expf(e - m);
            }
#pragma unroll
            for (int oo = 1; oo <= 4; oo <<= 1) {
                float mo  = __shfl_xor_sync(0xffffffffu, m, oo);
                float dno = __shfl_xor_sync(0xffffffffu, den, oo);
                float nm = fmaxf(m, mo);
                float f1 = (m == nm) ? 1.f : __expf(m - nm);
                float f2 = (mo == nm) ? 1.f : __expf(mo - nm);
                den = den * f1 + dno * f2;
                m = nm;
            }
            float inv = 1.f / (den + 1e-16f);

            int k = s0;
            for (; k + 4 <= s1; k += 4) {
                int sa = g_srcsorted[k];
                int sb = g_srcsorted[k + 1];
                int sc = g_srcsorted[k + 2];
                int sd = g_srcsorted[k + 3];
                uint4 va = *(const uint4*)&f16[(size_t)sa * (HC / 2) + 4 * lane];
                uint4 vb = *(const uint4*)&f16[(size_t)sb * (HC / 2) + 4 * lane];
                uint4 vc = *(const uint4*)&f16[(size_t)sc * (HC / 2) + 4 * lane];
                uint4 vd = *(const uint4*)&f16[(size_t)sd * (HC / 2) + 4 * lane];
                float ea = es[sa * NH + head] + edv;
                float eb = es[sb * NH + head] + edv;
                float ec = es[sc * NH + head] + edv;
                float eD = es[sd * NH + head] + edv;
                ea = (ea >= 0.f) ? ea : SLOPE * ea;
                eb = (eb >= 0.f) ? eb : SLOPE * eb;
                ec = (ec >= 0.f) ? ec : SLOPE * ec;
                eD = (eD >= 0.f) ? eD : SLOPE * eD;
                acc_edge(acc, va, __expf(ea - m) * inv);
                acc_edge(acc, vb, __expf(eb - m) * inv);
                acc_edge(acc, vc, __expf(ec - m) * inv);
                acc_edge(acc, vd, __expf(eD - m) * inv);
            }
            for (; k < s1; k++) {
                int sa = g_srcsorted[k];
                uint4 va = *(const uint4*)&f16[(size_t)sa * (HC / 2) + 4 * lane];
                float ea = es[sa * NH + head] + edv;
                ea = (ea >= 0.f) ? ea : SLOPE * ea;
                acc_edge(acc, va, __expf(ea - m) * inv);
            }
        }

        uint4 rv = *(const uint4*)&res16[(size_t)node * (HC / 2) + 4 * lane];
        float2 r0 = __half22float2(*(const __half2*)&rv.x);
        float2 r1 = __half22float2(*(const __half2*)&rv.y);
        float2 r2 = __half22float2(*(const __half2*)&rv.z);
        float2 r3 = __half22float2(*(const __half2*)&rv.w);
        o[0] = acc[0] + r0.x; o[1] = acc[1] + r0.y;
        o[2] = acc[2] + r1.x; o[3] = acc[3] + r1.y;
        o[4] = acc[4] + r2.x; o[5] = acc[5] + r2.y;
        o[6] = acc[6] + r3.x; o[7] = acc[7] + r3.y;

        uint4 ov;
        ov.x = f2h2(make_float2(o[0], o[1]));
        ov.y = f2h2(make_float2(o[2], o[3]));
        ov.z = f2h2(make_float2(o[4], o[5]));
        ov.w = f2h2(make_float2(o[6], o[7]));
        *(uint4*)&out16[(size_t)node * (HC / 2) + 4 * lane] = ov;
    }

    // ---- fused BN statistics ----
    {
        int cb = 8 * lane;
#pragma unroll
        for (int i = 0; i < 8; i++) {
            ssum[wwid][cb + i] = o[i];
            ssq [wwid][cb + i] = o[i] * o[i];
        }
        __syncthreads();
        int t = threadIdx.x;
        float S = 0.f, Q = 0.f;
#pragma unroll
        for (int w = 0; w < 8; w++) { S += ssum[w][t]; Q += ssq[w][t]; }
        atomicAdd(&bnacc[t], S);
        atomicAdd(&bnacc[t + HC], Q);
    }
}

// ---------------- fused pooling(BN2-inline-finalize + ReLU) + MLP --------------
__global__ __launch_bounds__(128) void pool_mlp_kernel(
    const uint32_t* __restrict__ act16, const int* __restrict__ batch,
    const float* __restrict__ gma, const float* __restrict__ beta,
    const float* __restrict__ bnacc,
    const float* __restrict__ fc1W, const float* __restrict__ fc1b,
    const float* __restrict__ fc2W, const float* __restrict__ fc2b,
    float* __restrict__ out)
{
    __shared__ float row[HC];
    __shared__ float red[128];
    __shared__ int s_lo, s_hi;
    int g = blockIdx.x, t = threadIdx.x;
    if (t == 0) {
        int lo = 0, hi = NN;
        while (lo < hi) { int mid = (lo + hi) >> 1; if (batch[mid] < g) lo = mid + 1; else hi = mid; }
        s_lo = lo;
        int lo2 = lo; hi = NN;
        while (lo2 < hi) { int mid = (lo2 + hi) >> 1; if (batch[mid] < g + 1) lo2 = mid + 1; else hi = mid; }
        s_hi = lo2;
    }
    // inline BN finalize for channels 2t, 2t+1
    float m0 = bnacc[2 * t] * (1.0f / NN);
    float v0 = bnacc[2 * t + HC] * (1.0f / NN) - m0 * m0;
    float A0 = gma[2 * t] * rsqrtf(v0 + EPSBN);
    float B0 = beta[2 * t] - m0 * A0;
    float m1 = bnacc[2 * t + 1] * (1.0f / NN);
    float v1 = bnacc[2 * t + 1 + HC] * (1.0f / NN) - m1 * m1;
    float A1 = gma[2 * t + 1] * rsqrtf(v1 + EPSBN);
    float B1 = beta[2 * t + 1] - m1 * A1;
    __syncthreads();
    int lo = s_lo, hi = s_hi;
    float sx = 0.f, sy = 0.f;
    for (int r = lo; r < hi; r++) {
        uint32_t w = act16[(size_t)r * (HC / 2) + t];
        float2 p = __half22float2(*(const __half2*)&w);
        sx += fmaxf(p.x * A0 + B0, 0.f);
        sy += fmaxf(p.y * A1 + B1, 0.f);
    }
    float inv = (hi > lo) ? 1.0f / (float)(hi - lo) : 0.0f;
    row[2 * t]     = sx * inv;
    row[2 * t + 1] = sy * inv;
    __syncthreads();

    float a = fc1b[t];
#pragma unroll 8
    for (int k = 0; k < HC; k++) a += row[k] * fc1W[k * 128 + t];
    a = fmaxf(a, 0.f);
    for (int jj = 0; jj < 2; jj++) {
        red[t] = a * fc2W[t * 2 + jj];
        __syncthreads();
        for (int off = 64; off; off >>= 1) {
            if (t < off) red[t] += red[t + off];
            __syncthreads();
        }
        if (t == 0) out[g * 2 + jj] = red[0] + fc2b[jj];
        __syncthreads();
    }
}

// ---------------- host side ----------------
static void* symp(const void* sym) {
    void* p = nullptr;
    cudaGetSymbolAddress(&p, sym);
    return p;
}

extern "C" void kernel_launch(void* const* d_in, const int* in_sizes, int n_in,
                              void* d_out, int out_size)
{
    const float* x        = (const float*)d_in[0];
    const int*   edge_idx = (const int*)  d_in[1];
    const int*   batch    = (const int*)  d_in[3];
    const float* W1       = (const float*)d_in[4];
    const float* asrc1    = (const float*)d_in[5];
    const float* adst1    = (const float*)d_in[6];
    const float* b1       = (const float*)d_in[7];
    const float* res1W    = (const float*)d_in[8];
    const float* res1b    = (const float*)d_in[9];
    const float* bn1g     = (const float*)d_in[10];
    const float* bn1b     = (const float*)d_in[11];
    const float* W2       = (const float*)d_in[12];
    const float* asrc2    = (const float*)d_in[13];
    const float* adst2    = (const float*)d_in[14];
    const float* b2       = (const float*)d_in[15];
    const float* res2W    = (const float*)d_in[16];
    const float* res2b    = (const float*)d_in[17];
    const float* bn2g     = (const float*)d_in[18];
    const float* bn2b     = (const float*)d_in[19];
    const float* fc1W     = (const float*)d_in[20];
    const float* fc1b     = (const float*)d_in[21];
    const float* fc2W     = (const float*)d_in[22];
    const float* fc2b     = (const float*)d_in[23];
    float* out = (float*)d_out;

    uint32_t* f16  = (uint32_t*)symp(g_f16);
    uint32_t* res16= (uint32_t*)symp(g_res16);
    uint32_t* act16= (uint32_t*)symp(g_act16);
    float* es    = (float*)symp(g_es);
    float* ed    = (float*)symp(g_ed);
    int*   rowp  = (int*)  symp(g_rowptr);
    int*   curs  = (int*)  symp(g_cursor);
    int*   bsum  = (int*)  symp(g_blocksums);
    int*   boff  = (int*)  symp(g_blockoff);
    float* bnacc = (float*)symp(g_bnacc);     // [0:512) layer1, [512:1024) layer2
    uint32_t* x16  = (uint32_t*)symp(g_x16);
    uint32_t* a216 = (uint32_t*)symp(g_a216);
    uint32_t* w116 = (uint32_t*)symp(g_w116), *r116 = (uint32_t*)symp(g_r116);
    uint32_t* w216 = (uint32_t*)symp(g_w216), *r216 = (uint32_t*)symp(g_r216);

    const int NB = (NN + 255) / 256;
    const int EB = (EE + 255) / 256;
    const int NODEWARP_BLKS = (NN * 32 + 255) / 256;
    dim3 gemm_grid(HC / 64, (NN + 127) / 128);
    const int W1W = HC * DIN / 2, W2W = HC * HC / 2;
    const int PREP1_N = NXCHUNK + 2 * W1W;

    static cudaStream_t s2 = nullptr;
    static cudaEvent_t evFork = nullptr, evJoin = nullptr;
    if (s2 == nullptr) {
        cudaStreamCreateWithFlags(&s2, cudaStreamNonBlocking);
        cudaEventCreateWithFlags(&evFork, cudaEventDisableTiming);
        cudaEventCreateWithFlags(&evJoin, cudaEventDisableTiming);
    }

    // ---- fork: CSR build + L2 weight cvt + bnacc zero (both layers) ----
    cudaEventRecord(evFork, 0);
    cudaStreamWaitEvent(s2, evFork, 0);
    zero_int_kernel<<<NB, 256, 0, s2>>>(curs, NN);
    count_deg_kernel<<<EB, 256, 0, s2>>>(edge_idx);
    scan_block_kernel<<<NB, 256, 0, s2>>>(curs, rowp, bsum, NN);
    scan_block_kernel<<<1, 256, 0, s2>>>(bsum, boff, nullptr, NB);
    scan_add_kernel<<<NB, 256, 0, s2>>>(rowp, curs, boff, NN);
    fill_csr_kernel<<<EB, 256, 0, s2>>>(edge_idx);
    zero_float_kernel<<<4, 256, 0, s2>>>(bnacc, 4 * HC);
    wcvt2_kernel<<<dim3((W2W + 255) / 256, 2), 256, 0, s2>>>(W2, res2W, w216, r216, HC);
    cudaEventRecord(evJoin, s2);

    // ---- main stream: merged prep + GEMM L1 ----
    prep1_kernel<<<(PREP1_N + 255) / 256, 256>>>(x, x16, W1, res1W, w116, r116);
    gemm16_kernel<<<gemm_grid, 256>>>(x16, w116, r116, res1b,
                                      asrc1, adst1, f16, res16, es, ed,
                                      NN, DIN);

    // ---- join: agg needs CSR + bnacc ----
    cudaStreamWaitEvent(0, evJoin, 0);

    // ---- layer 1: agg (+stats -> bnacc[0]) -> apply(inline finalize)+cvt ----
    agg_kernel<<<NODEWARP_BLKS, 256>>>(f16, es, ed, res16, act16, bnacc);
    bn_apply_cvt_kernel<<<(NN * HC / 4 + 255) / 256, 256>>>(act16, a216, bn1g, bn1b, bnacc);

    // ---- layer 2 ----
    gemm16_kernel<<<gemm_grid, 256>>>(a216, w216, r216, res2b,
                                      asrc2, adst2, f16, res16, es, ed,
                                      NN, HC);
    agg_kernel<<<NODEWARP_BLKS, 256>>>(f16, es, ed, res16, act16, bnacc + 2 * HC);

    // ---- fused pooling(BN2 inline finalize) + MLP ----
    pool_mlp_kernel<<<NG, 128>>>(act16, batch, bn2g, bn2b, bnacc + 2 * HC,
                                 fc1W, fc1b, fc2W, fc2b, out);
}